// round 2
// baseline (speedup 1.0000x reference)
#include <cuda_runtime.h>
#include <cuda_bf16.h>
#include <math.h>

#define DIM 4096
#define NHEADS 32
#define NKV 8
#define HD 128
#define SEQ 2048
#define BSZ 2
#define TOK (BSZ*SEQ)
#define KVDIM (NKV*HD)

// Scratch (no cudaMalloc allowed)
__device__ float g_q[(size_t)TOK * DIM];
__device__ float g_k[(size_t)TOK * KVDIM];
__device__ float g_v[(size_t)TOK * KVDIM];
__device__ float g_attn[(size_t)TOK * DIM];

// ---------------------------------------------------------------------------
// SGEMM: C[M,N] = A[M,K] @ B[N,K]^T + bias[N]
// 128x128 tile, BK=8, 256 threads, 8x8 micro-tile per thread.
// ---------------------------------------------------------------------------
#define BM 128
#define BN 128
#define BK 8

__global__ __launch_bounds__(256, 2)
void sgemm_nt_bias(const float* __restrict__ A, const float* __restrict__ B,
                   const float* __restrict__ bias, float* __restrict__ C,
                   int M, int N, int K) {
    __shared__ float As[BK][BM];
    __shared__ float Bs[BK][BN];

    const int tid = threadIdx.x;
    const int bm = blockIdx.y * BM;
    const int bn = blockIdx.x * BN;

    const int lr = tid >> 1;          // 0..127
    const int lc = (tid & 1) * 4;     // 0 or 4

    const int ty = tid >> 4;          // 0..15
    const int tx = tid & 15;          // 0..15

    float acc[8][8];
#pragma unroll
    for (int i = 0; i < 8; i++)
#pragma unroll
        for (int j = 0; j < 8; j++) acc[i][j] = 0.f;

    for (int k0 = 0; k0 < K; k0 += BK) {
        float4 a4 = *(const float4*)&A[(size_t)(bm + lr) * K + k0 + lc];
        float4 b4 = *(const float4*)&B[(size_t)(bn + lr) * K + k0 + lc];
        As[lc + 0][lr] = a4.x; As[lc + 1][lr] = a4.y;
        As[lc + 2][lr] = a4.z; As[lc + 3][lr] = a4.w;
        Bs[lc + 0][lr] = b4.x; Bs[lc + 1][lr] = b4.y;
        Bs[lc + 2][lr] = b4.z; Bs[lc + 3][lr] = b4.w;
        __syncthreads();

#pragma unroll
        for (int k = 0; k < BK; k++) {
            float a[8], b[8];
            float4 alo = *(const float4*)&As[k][ty * 8];
            float4 ahi = *(const float4*)&As[k][ty * 8 + 4];
            float4 blo = *(const float4*)&Bs[k][tx * 8];
            float4 bhi = *(const float4*)&Bs[k][tx * 8 + 4];
            a[0]=alo.x;a[1]=alo.y;a[2]=alo.z;a[3]=alo.w;
            a[4]=ahi.x;a[5]=ahi.y;a[6]=ahi.z;a[7]=ahi.w;
            b[0]=blo.x;b[1]=blo.y;b[2]=blo.z;b[3]=blo.w;
            b[4]=bhi.x;b[5]=bhi.y;b[6]=bhi.z;b[7]=bhi.w;
#pragma unroll
            for (int i = 0; i < 8; i++)
#pragma unroll
                for (int j = 0; j < 8; j++)
                    acc[i][j] += a[i] * b[j];
        }
        __syncthreads();
    }

#pragma unroll
    for (int i = 0; i < 8; i++) {
        float* crow = &C[(size_t)(bm + ty * 8 + i) * N + bn + tx * 8];
#pragma unroll
        for (int j = 0; j < 8; j++)
            crow[j] = acc[i][j] + bias[bn + tx * 8 + j];
    }
}

// ---------------------------------------------------------------------------
// RoPE (interleaved pairs), in-place. nheads in {32, 8}, row stride nheads*128
// ---------------------------------------------------------------------------
__global__ void rope_kernel(float* __restrict__ t, const float* __restrict__ cs,
                            const float* __restrict__ sn, int nheads) {
    int idx = blockIdx.x * blockDim.x + threadIdx.x;
    int ppt = nheads * 64;                // pairs per token
    int total = TOK * ppt;
    if (idx >= total) return;
    int tok = idx / ppt;
    int rem = idx - tok * ppt;
    int h = rem >> 6;
    int i = rem & 63;
    int s = tok & (SEQ - 1);
    float c = cs[s * 64 + i];
    float si = sn[s * 64 + i];
    float* p = t + (size_t)tok * (nheads * HD) + h * HD + 2 * i;
    float a = p[0], b = p[1];
    p[0] = a * c - b * si;
    p[1] = a * si + b * c;
}

// ---------------------------------------------------------------------------
// Causal GQA flash attention, fp32.
// Q tile 64 rows, K tile 64, D=128, 256 threads.
// grid: (SEQ/64, BSZ*NHEADS)
// ---------------------------------------------------------------------------
#define QT 64
#define KT 64
#define QS_STR 132
#define SS_STR 68
#define FA_SMEM ((QT*QS_STR*2 + KT*HD + QT*SS_STR) * 4)

__global__ __launch_bounds__(256, 1)
void flash_kernel(const float* __restrict__ Q, const float* __restrict__ K,
                  const float* __restrict__ V, float* __restrict__ O) {
    extern __shared__ float sm[];
    float* Qs = sm;                    // 64 x 132
    float* Ks = Qs + QT * QS_STR;      // 64 x 132
    float* Vs = Ks + KT * QS_STR;      // 64 x 128
    float* Ss = Vs + KT * HD;          // 64 x 68

    const int tid = threadIdx.x;
    const int q0 = blockIdx.x * QT;
    const int bh = blockIdx.y;
    const int b = bh >> 5;
    const int h = bh & 31;
    const int g = h >> 2;

    const float* Qg = Q + (size_t)b * SEQ * DIM + h * HD;
    const float* Kg = K + (size_t)b * SEQ * KVDIM + g * HD;
    const float* Vg = V + (size_t)b * SEQ * KVDIM + g * HD;

    // load Q tile
    for (int i = tid; i < QT * 32; i += 256) {
        int r = i >> 5, c = (i & 31) * 4;
        *(float4*)&Qs[r * QS_STR + c] =
            *(const float4*)&Qg[(size_t)(q0 + r) * DIM + c];
    }

    float acc[32];
#pragma unroll
    for (int i = 0; i < 32; i++) acc[i] = 0.f;
    float m = -1e30f, l = 0.f;

    const int r_own = tid >> 2;        // row for softmax/PV/output
    const int cqb = (tid & 3) * 32;    // col base for PV/output
    const int rg = tid >> 4;           // score rows rg + 16*i
    const int cg = tid & 15;           // score cols cg + 16*j
    const float scale = 0.08838834764831845f;  // 1/sqrt(128)

    for (int k0 = 0; k0 <= q0; k0 += KT) {
        __syncthreads();
        for (int i = tid; i < KT * 32; i += 256) {
            int r = i >> 5, c = (i & 31) * 4;
            *(float4*)&Ks[r * QS_STR + c] =
                *(const float4*)&Kg[(size_t)(k0 + r) * KVDIM + c];
            *(float4*)&Vs[r * HD + c] =
                *(const float4*)&Vg[(size_t)(k0 + r) * KVDIM + c];
        }
        __syncthreads();

        // ---- scores: S = Q @ K^T, 4x4 micro-tile (strided) ----
        float s[4][4];
#pragma unroll
        for (int i = 0; i < 4; i++)
#pragma unroll
            for (int j = 0; j < 4; j++) s[i][j] = 0.f;

        for (int d = 0; d < HD; d += 4) {
            float4 q4[4], k4[4];
#pragma unroll
            for (int i = 0; i < 4; i++)
                q4[i] = *(const float4*)&Qs[(rg + 16 * i) * QS_STR + d];
#pragma unroll
            for (int j = 0; j < 4; j++)
                k4[j] = *(const float4*)&Ks[(cg + 16 * j) * QS_STR + d];
#pragma unroll
            for (int i = 0; i < 4; i++)
#pragma unroll
                for (int j = 0; j < 4; j++)
                    s[i][j] += q4[i].x * k4[j].x + q4[i].y * k4[j].y +
                               q4[i].z * k4[j].z + q4[i].w * k4[j].w;
        }

#pragma unroll
        for (int i = 0; i < 4; i++) {
            int rr = rg + 16 * i;
#pragma unroll
            for (int j = 0; j < 4; j++) {
                int cc = cg + 16 * j;
                float val = s[i][j] * scale;
                if (k0 + cc > q0 + rr) val = -1e30f;
                Ss[rr * SS_STR + cc] = val;
            }
        }
        __syncthreads();

        // ---- online softmax: 4 threads per row ----
        float rmax = -1e30f;
#pragma unroll
        for (int jj = 0; jj < 16; jj++)
            rmax = fmaxf(rmax, Ss[r_own * SS_STR + (tid & 3) + 4 * jj]);
        rmax = fmaxf(rmax, __shfl_xor_sync(0xffffffffu, rmax, 1));
        rmax = fmaxf(rmax, __shfl_xor_sync(0xffffffffu, rmax, 2));

        float newm = fmaxf(m, rmax);
        float alpha = __expf(m - newm);
        float lsum = 0.f;
#pragma unroll
        for (int jj = 0; jj < 16; jj++) {
            int c = (tid & 3) + 4 * jj;
            float p = __expf(Ss[r_own * SS_STR + c] - newm);
            Ss[r_own * SS_STR + c] = p;
            lsum += p;
        }
        lsum += __shfl_xor_sync(0xffffffffu, lsum, 1);
        lsum += __shfl_xor_sync(0xffffffffu, lsum, 2);
        l = l * alpha + lsum;
        m = newm;
#pragma unroll
        for (int i = 0; i < 32; i++) acc[i] *= alpha;
        __syncthreads();

        // ---- O += P @ V ----
        for (int kk = 0; kk < KT; kk++) {
            float p = Ss[r_own * SS_STR + kk];
            const float* vrow = &Vs[kk * HD + cqb];
#pragma unroll
            for (int c4 = 0; c4 < 8; c4++) {
                float4 vv = *(const float4*)&vrow[c4 * 4];
                acc[c4 * 4 + 0] += p * vv.x;
                acc[c4 * 4 + 1] += p * vv.y;
                acc[c4 * 4 + 2] += p * vv.z;
                acc[c4 * 4 + 3] += p * vv.w;
            }
        }
    }

    float inv = 1.f / l;
    float* Og = O + (size_t)(b * SEQ + q0 + r_own) * DIM + h * HD + cqb;
#pragma unroll
    for (int i = 0; i < 32; i++) Og[i] = acc[i] * inv;
}

// ---------------------------------------------------------------------------
extern "C" void kernel_launch(void* const* d_in, const int* in_sizes, int n_in,
                              void* d_out, int out_size) {
    const float* x   = (const float*)d_in[0];
    const float* fcs = (const float*)d_in[1];
    const float* fsn = (const float*)d_in[2];
    // d_in[3] = mask (causal applied analytically)
    const float* wq = (const float*)d_in[4];
    const float* bq = (const float*)d_in[5];
    const float* wk = (const float*)d_in[6];
    const float* bk = (const float*)d_in[7];
    const float* wv = (const float*)d_in[8];
    const float* bv = (const float*)d_in[9];
    const float* wo = (const float*)d_in[10];
    const float* bo = (const float*)d_in[11];
    float* out = (float*)d_out;

    float *q, *k, *v, *attn;
    cudaGetSymbolAddress((void**)&q, g_q);
    cudaGetSymbolAddress((void**)&k, g_k);
    cudaGetSymbolAddress((void**)&v, g_v);
    cudaGetSymbolAddress((void**)&attn, g_attn);

    cudaFuncSetAttribute(flash_kernel, cudaFuncAttributeMaxDynamicSharedMemorySize,
                         FA_SMEM);

    // QKV projections
    sgemm_nt_bias<<<dim3(DIM / BN, TOK / BM), 256>>>(x, wq, bq, q, TOK, DIM, DIM);
    sgemm_nt_bias<<<dim3(KVDIM / BN, TOK / BM), 256>>>(x, wk, bk, k, TOK, KVDIM, DIM);
    sgemm_nt_bias<<<dim3(KVDIM / BN, TOK / BM), 256>>>(x, wv, bv, v, TOK, KVDIM, DIM);

    // RoPE on Q and K
    {
        int total_q = TOK * NHEADS * 64;
        rope_kernel<<<(total_q + 255) / 256, 256>>>(q, fcs, fsn, NHEADS);
        int total_k = TOK * NKV * 64;
        rope_kernel<<<(total_k + 255) / 256, 256>>>(k, fcs, fsn, NKV);
    }

    // Flash attention
    flash_kernel<<<dim3(SEQ / QT, BSZ * NHEADS), 256, FA_SMEM>>>(q, k, v, attn);

    // Output projection
    sgemm_nt_bias<<<dim3(DIM / BN, TOK / BM), 256>>>(attn, wo, bo, out, TOK, DIM, DIM);
}

// round 3
// speedup vs baseline: 1.4194x; 1.4194x over previous
#include <cuda_runtime.h>
#include <cuda_bf16.h>
#include <math.h>
#include <stdint.h>

#define DIM 4096
#define NHEADS 32
#define NKV 8
#define HD 128
#define SEQ 2048
#define BSZ 2
#define TOK (BSZ*SEQ)
#define KVDIM (NKV*HD)

// Scratch (no cudaMalloc allowed)
__device__ float g_q[(size_t)TOK * DIM];
__device__ float g_k[(size_t)TOK * KVDIM];
__device__ float g_v[(size_t)TOK * KVDIM];
__device__ float g_attn[(size_t)TOK * DIM];

// ---------------------------------------------------------------------------
// TF32 tensor-core GEMM: C[M,N] = A[M,K] @ B[N,K]^T + bias[N]
// 128x128x32 tile, 256 threads (8 warps, 4x2), warp tile 32x64,
// mma.sync.m16n8k8.tf32, fragment-ordered smem, reg double buffering.
// ---------------------------------------------------------------------------
#define TBM 128
#define TBN 128
#define TBK 32
// smem (u32 units): As[2][4096], Bs[2][4096] = 64 KB
#define GEMM_SMEM 65536

__device__ __forceinline__ uint32_t f2tf32(float f) {
    uint32_t t;
    asm("cvt.rna.tf32.f32 %0, %1;" : "=r"(t) : "f"(f));
    return t;
}

__global__ __launch_bounds__(256, 2)
void tf32_gemm_nt_bias(const float* __restrict__ A, const float* __restrict__ B,
                       const float* __restrict__ bias, float* __restrict__ C,
                       int M, int N, int K) {
    extern __shared__ uint32_t sh[];
    uint32_t* As = sh;          // [2][4096]  frag layout: ((mt*4+kt)*32+lane)*4+slot
    uint32_t* Bs = sh + 8192;   // [2][4096]  frag layout: ((nt*4+kt)*32+lane)*2+slot

    const int tid = threadIdx.x;
    const int bm = blockIdx.y * TBM;
    const int bn = blockIdx.x * TBN;
    const int lane = tid & 31;
    const int wid = tid >> 5;
    const int warp_m = wid >> 1;   // 0..3 (32 rows each)
    const int warp_n = wid & 1;    // 0..1 (64 cols each)

    float4 pa[4], pb[4];

    float acc[2][8][4];
#pragma unroll
    for (int mi = 0; mi < 2; mi++)
#pragma unroll
        for (int ni = 0; ni < 8; ni++)
#pragma unroll
            for (int j = 0; j < 4; j++) acc[mi][ni][j] = 0.f;

    const int nit = K / TBK;

    // ---- global -> regs ----
    auto g2r = [&](int k0) {
#pragma unroll
        for (int i = 0; i < 4; i++) {
            int flat = tid + 256 * i;
            int r = flat >> 3;
            int c = (flat & 7) * 4;
            pa[i] = *(const float4*)&A[(size_t)(bm + r) * K + k0 + c];
            pb[i] = *(const float4*)&B[(size_t)(bn + r) * K + k0 + c];
        }
    };

    // ---- regs -> smem (cvt.rna + fragment arrangement) ----
    auto r2s = [&](int buf) {
#pragma unroll
        for (int i = 0; i < 4; i++) {
            int flat = tid + 256 * i;
            int r = flat >> 3;
            int c = (flat & 7) * 4;
            // A: mt = r>>4, rr = r&15, kt = c>>3, cc = c&7 (0 or 4)
            {
                int mt = r >> 4, rr = r & 15, kt = c >> 3, ccb = c & 7;
                int slot = ((rr >> 3) & 1) + ((ccb >= 4) ? 2 : 0);
                uint32_t* dst = &As[buf * 4096 +
                                    ((mt * 4 + kt) * 32 + ((rr & 7) << 2)) * 4 + slot];
                dst[0]  = f2tf32(pa[i].x);
                dst[4]  = f2tf32(pa[i].y);
                dst[8]  = f2tf32(pa[i].z);
                dst[12] = f2tf32(pa[i].w);
            }
            // B: nt = r>>3, nn = r&7, kt = c>>3, kk = c&7
            {
                int nt = r >> 3, nn = r & 7, kt = c >> 3, kkb = c & 7;
                int slot = (kkb >= 4) ? 1 : 0;
                uint32_t* dst = &Bs[buf * 4096 +
                                    ((nt * 4 + kt) * 32 + (nn << 2)) * 2 + slot];
                dst[0] = f2tf32(pb[i].x);
                dst[2] = f2tf32(pb[i].y);
                dst[4] = f2tf32(pb[i].z);
                dst[6] = f2tf32(pb[i].w);
            }
        }
    };

    g2r(0);
    r2s(0);
    __syncthreads();

    for (int it = 0; it < nit; it++) {
        int buf = it & 1;
        if (it + 1 < nit) g2r((it + 1) * TBK);

#pragma unroll
        for (int kt = 0; kt < 4; kt++) {
            uint4 af[2];
            uint2 bf[8];
#pragma unroll
            for (int mi = 0; mi < 2; mi++)
                af[mi] = *(const uint4*)&As[buf * 4096 +
                           (((warp_m * 2 + mi) * 4 + kt) * 32 + lane) * 4];
#pragma unroll
            for (int ni = 0; ni < 8; ni++)
                bf[ni] = *(const uint2*)&Bs[buf * 4096 +
                           (((warp_n * 8 + ni) * 4 + kt) * 32 + lane) * 2];
#pragma unroll
            for (int mi = 0; mi < 2; mi++)
#pragma unroll
                for (int ni = 0; ni < 8; ni++)
                    asm volatile(
                        "mma.sync.aligned.m16n8k8.row.col.f32.tf32.tf32.f32 "
                        "{%0,%1,%2,%3}, {%4,%5,%6,%7}, {%8,%9}, {%0,%1,%2,%3};"
                        : "+f"(acc[mi][ni][0]), "+f"(acc[mi][ni][1]),
                          "+f"(acc[mi][ni][2]), "+f"(acc[mi][ni][3])
                        : "r"(af[mi].x), "r"(af[mi].y), "r"(af[mi].z), "r"(af[mi].w),
                          "r"(bf[ni].x), "r"(bf[ni].y));
        }

        if (it + 1 < nit) r2s((it + 1) & 1);
        __syncthreads();
    }

    // ---- epilogue ----
#pragma unroll
    for (int mi = 0; mi < 2; mi++) {
        int r0 = bm + warp_m * 32 + mi * 16 + (lane >> 2);
#pragma unroll
        for (int ni = 0; ni < 8; ni++) {
            int c0 = bn + warp_n * 64 + ni * 8 + (lane & 3) * 2;
            float2 bb = *(const float2*)&bias[c0];
            float2 o0 = make_float2(acc[mi][ni][0] + bb.x, acc[mi][ni][1] + bb.y);
            float2 o1 = make_float2(acc[mi][ni][2] + bb.x, acc[mi][ni][3] + bb.y);
            *(float2*)&C[(size_t)r0 * N + c0] = o0;
            *(float2*)&C[(size_t)(r0 + 8) * N + c0] = o1;
        }
    }
}

// ---------------------------------------------------------------------------
// RoPE (interleaved pairs), in-place.
// ---------------------------------------------------------------------------
__global__ void rope_kernel(float* __restrict__ t, const float* __restrict__ cs,
                            const float* __restrict__ sn, int nheads) {
    int idx = blockIdx.x * blockDim.x + threadIdx.x;
    int ppt = nheads * 64;
    int total = TOK * ppt;
    if (idx >= total) return;
    int tok = idx / ppt;
    int rem = idx - tok * ppt;
    int h = rem >> 6;
    int i = rem & 63;
    int s = tok & (SEQ - 1);
    float c = cs[s * 64 + i];
    float si = sn[s * 64 + i];
    float* p = t + (size_t)tok * (nheads * HD) + h * HD + 2 * i;
    float a = p[0], b = p[1];
    p[0] = a * c - b * si;
    p[1] = a * si + b * c;
}

// ---------------------------------------------------------------------------
// Causal GQA flash attention, fp32 (unchanged from R1).
// ---------------------------------------------------------------------------
#define QT 64
#define KT 64
#define QS_STR 132
#define SS_STR 68
#define FA_SMEM ((QT*QS_STR*2 + KT*HD + QT*SS_STR) * 4)

__global__ __launch_bounds__(256, 1)
void flash_kernel(const float* __restrict__ Q, const float* __restrict__ K,
                  const float* __restrict__ V, float* __restrict__ O) {
    extern __shared__ float sm[];
    float* Qs = sm;
    float* Ks = Qs + QT * QS_STR;
    float* Vs = Ks + KT * QS_STR;
    float* Ss = Vs + KT * HD;

    const int tid = threadIdx.x;
    const int q0 = blockIdx.x * QT;
    const int bh = blockIdx.y;
    const int b = bh >> 5;
    const int h = bh & 31;
    const int g = h >> 2;

    const float* Qg = Q + (size_t)b * SEQ * DIM + h * HD;
    const float* Kg = K + (size_t)b * SEQ * KVDIM + g * HD;
    const float* Vg = V + (size_t)b * SEQ * KVDIM + g * HD;

    for (int i = tid; i < QT * 32; i += 256) {
        int r = i >> 5, c = (i & 31) * 4;
        *(float4*)&Qs[r * QS_STR + c] =
            *(const float4*)&Qg[(size_t)(q0 + r) * DIM + c];
    }

    float acc[32];
#pragma unroll
    for (int i = 0; i < 32; i++) acc[i] = 0.f;
    float m = -1e30f, l = 0.f;

    const int r_own = tid >> 2;
    const int cqb = (tid & 3) * 32;
    const int rg = tid >> 4;
    const int cg = tid & 15;
    const float scale = 0.08838834764831845f;

    for (int k0 = 0; k0 <= q0; k0 += KT) {
        __syncthreads();
        for (int i = tid; i < KT * 32; i += 256) {
            int r = i >> 5, c = (i & 31) * 4;
            *(float4*)&Ks[r * QS_STR + c] =
                *(const float4*)&Kg[(size_t)(k0 + r) * KVDIM + c];
            *(float4*)&Vs[r * HD + c] =
                *(const float4*)&Vg[(size_t)(k0 + r) * KVDIM + c];
        }
        __syncthreads();

        float s[4][4];
#pragma unroll
        for (int i = 0; i < 4; i++)
#pragma unroll
            for (int j = 0; j < 4; j++) s[i][j] = 0.f;

        for (int d = 0; d < HD; d += 4) {
            float4 q4[4], k4[4];
#pragma unroll
            for (int i = 0; i < 4; i++)
                q4[i] = *(const float4*)&Qs[(rg + 16 * i) * QS_STR + d];
#pragma unroll
            for (int j = 0; j < 4; j++)
                k4[j] = *(const float4*)&Ks[(cg + 16 * j) * QS_STR + d];
#pragma unroll
            for (int i = 0; i < 4; i++)
#pragma unroll
                for (int j = 0; j < 4; j++)
                    s[i][j] += q4[i].x * k4[j].x + q4[i].y * k4[j].y +
                               q4[i].z * k4[j].z + q4[i].w * k4[j].w;
        }

#pragma unroll
        for (int i = 0; i < 4; i++) {
            int rr = rg + 16 * i;
#pragma unroll
            for (int j = 0; j < 4; j++) {
                int cc = cg + 16 * j;
                float val = s[i][j] * scale;
                if (k0 + cc > q0 + rr) val = -1e30f;
                Ss[rr * SS_STR + cc] = val;
            }
        }
        __syncthreads();

        float rmax = -1e30f;
#pragma unroll
        for (int jj = 0; jj < 16; jj++)
            rmax = fmaxf(rmax, Ss[r_own * SS_STR + (tid & 3) + 4 * jj]);
        rmax = fmaxf(rmax, __shfl_xor_sync(0xffffffffu, rmax, 1));
        rmax = fmaxf(rmax, __shfl_xor_sync(0xffffffffu, rmax, 2));

        float newm = fmaxf(m, rmax);
        float alpha = __expf(m - newm);
        float lsum = 0.f;
#pragma unroll
        for (int jj = 0; jj < 16; jj++) {
            int c = (tid & 3) + 4 * jj;
            float p = __expf(Ss[r_own * SS_STR + c] - newm);
            Ss[r_own * SS_STR + c] = p;
            lsum += p;
        }
        lsum += __shfl_xor_sync(0xffffffffu, lsum, 1);
        lsum += __shfl_xor_sync(0xffffffffu, lsum, 2);
        l = l * alpha + lsum;
        m = newm;
#pragma unroll
        for (int i = 0; i < 32; i++) acc[i] *= alpha;
        __syncthreads();

        for (int kk = 0; kk < KT; kk++) {
            float p = Ss[r_own * SS_STR + kk];
            const float* vrow = &Vs[kk * HD + cqb];
#pragma unroll
            for (int c4 = 0; c4 < 8; c4++) {
                float4 vv = *(const float4*)&vrow[c4 * 4];
                acc[c4 * 4 + 0] += p * vv.x;
                acc[c4 * 4 + 1] += p * vv.y;
                acc[c4 * 4 + 2] += p * vv.z;
                acc[c4 * 4 + 3] += p * vv.w;
            }
        }
    }

    float inv = 1.f / l;
    float* Og = O + (size_t)(b * SEQ + q0 + r_own) * DIM + h * HD + cqb;
#pragma unroll
    for (int i = 0; i < 32; i++) Og[i] = acc[i] * inv;
}

// ---------------------------------------------------------------------------
extern "C" void kernel_launch(void* const* d_in, const int* in_sizes, int n_in,
                              void* d_out, int out_size) {
    const float* x   = (const float*)d_in[0];
    const float* fcs = (const float*)d_in[1];
    const float* fsn = (const float*)d_in[2];
    const float* wq = (const float*)d_in[4];
    const float* bq = (const float*)d_in[5];
    const float* wk = (const float*)d_in[6];
    const float* bk = (const float*)d_in[7];
    const float* wv = (const float*)d_in[8];
    const float* bv = (const float*)d_in[9];
    const float* wo = (const float*)d_in[10];
    const float* bo = (const float*)d_in[11];
    float* out = (float*)d_out;

    float *q, *k, *v, *attn;
    cudaGetSymbolAddress((void**)&q, g_q);
    cudaGetSymbolAddress((void**)&k, g_k);
    cudaGetSymbolAddress((void**)&v, g_v);
    cudaGetSymbolAddress((void**)&attn, g_attn);

    cudaFuncSetAttribute(tf32_gemm_nt_bias,
                         cudaFuncAttributeMaxDynamicSharedMemorySize, GEMM_SMEM);
    cudaFuncSetAttribute(flash_kernel,
                         cudaFuncAttributeMaxDynamicSharedMemorySize, FA_SMEM);

    // QKV projections (tf32 tensor cores)
    tf32_gemm_nt_bias<<<dim3(DIM / TBN, TOK / TBM), 256, GEMM_SMEM>>>(
        x, wq, bq, q, TOK, DIM, DIM);
    tf32_gemm_nt_bias<<<dim3(KVDIM / TBN, TOK / TBM), 256, GEMM_SMEM>>>(
        x, wk, bk, k, TOK, KVDIM, DIM);
    tf32_gemm_nt_bias<<<dim3(KVDIM / TBN, TOK / TBM), 256, GEMM_SMEM>>>(
        x, wv, bv, v, TOK, KVDIM, DIM);

    // RoPE on Q and K
    {
        int total_q = TOK * NHEADS * 64;
        rope_kernel<<<(total_q + 255) / 256, 256>>>(q, fcs, fsn, NHEADS);
        int total_k = TOK * NKV * 64;
        rope_kernel<<<(total_k + 255) / 256, 256>>>(k, fcs, fsn, NKV);
    }

    // Flash attention (fp32)
    flash_kernel<<<dim3(SEQ / QT, BSZ * NHEADS), 256, FA_SMEM>>>(q, k, v, attn);

    // Output projection
    tf32_gemm_nt_bias<<<dim3(DIM / TBN, TOK / TBM), 256, GEMM_SMEM>>>(
        attn, wo, bo, out, TOK, DIM, DIM);
}

// round 4
// speedup vs baseline: 7.9057x; 5.5700x over previous
#include <cuda_runtime.h>
#include <cuda_fp16.h>
#include <math.h>
#include <stdint.h>

#define DIM 4096
#define NHEADS 32
#define NKV 8
#define HD 128
#define SEQ 2048
#define BSZ 2
#define TOK (BSZ*SEQ)
#define KVDIM (NKV*HD)

// fp16 scratch (no cudaMalloc allowed)
__device__ __half g_xh[(size_t)TOK * DIM];
__device__ __half g_wqh[(size_t)DIM * DIM];
__device__ __half g_wkh[(size_t)KVDIM * DIM];
__device__ __half g_wvh[(size_t)KVDIM * DIM];
__device__ __half g_woh[(size_t)DIM * DIM];
__device__ __half g_qh[(size_t)TOK * DIM];
__device__ __half g_kh[(size_t)TOK * KVDIM];
__device__ __half g_vh[(size_t)TOK * KVDIM];
__device__ __half g_ah[(size_t)TOK * DIM];

// ---------------------------------------------------------------------------
// PTX helpers
// ---------------------------------------------------------------------------
__device__ __forceinline__ uint32_t smem_u32(const void* p) {
    return (uint32_t)__cvta_generic_to_shared(p);
}
__device__ __forceinline__ void cp16(uint32_t dst, const void* src) {
    asm volatile("cp.async.cg.shared.global [%0], [%1], 16;\n" ::"r"(dst), "l"(src));
}
#define CP_COMMIT asm volatile("cp.async.commit_group;\n" ::: "memory")
#define CP_WAIT0  asm volatile("cp.async.wait_group 0;\n" ::: "memory")

__device__ __forceinline__ void ldsm4(uint32_t& r0, uint32_t& r1, uint32_t& r2,
                                      uint32_t& r3, uint32_t addr) {
    asm volatile("ldmatrix.sync.aligned.m8n8.x4.shared.b16 {%0,%1,%2,%3}, [%4];\n"
                 : "=r"(r0), "=r"(r1), "=r"(r2), "=r"(r3) : "r"(addr));
}
__device__ __forceinline__ void ldsm4t(uint32_t& r0, uint32_t& r1, uint32_t& r2,
                                       uint32_t& r3, uint32_t addr) {
    asm volatile("ldmatrix.sync.aligned.m8n8.x4.trans.shared.b16 {%0,%1,%2,%3}, [%4];\n"
                 : "=r"(r0), "=r"(r1), "=r"(r2), "=r"(r3) : "r"(addr));
}
__device__ __forceinline__ void mma_f16(float* c, const uint32_t* a,
                                        uint32_t b0, uint32_t b1) {
    asm volatile(
        "mma.sync.aligned.m16n8k16.row.col.f32.f16.f16.f32 "
        "{%0,%1,%2,%3}, {%4,%5,%6,%7}, {%8,%9}, {%0,%1,%2,%3};\n"
        : "+f"(c[0]), "+f"(c[1]), "+f"(c[2]), "+f"(c[3])
        : "r"(a[0]), "r"(a[1]), "r"(a[2]), "r"(a[3]), "r"(b0), "r"(b1));
}
__device__ __forceinline__ uint32_t pack_h2(float x, float y) {
    __half2 h = __floats2half2_rn(x, y);
    return *(uint32_t*)&h;
}

// ---------------------------------------------------------------------------
// fp32 -> fp16 conversion (vectorized, n % 8 == 0)
// ---------------------------------------------------------------------------
__global__ void f2h_kernel(const float* __restrict__ in, __half* __restrict__ out,
                           int n) {
    int i = (blockIdx.x * blockDim.x + threadIdx.x) * 8;
    if (i >= n) return;
    float4 v0 = *(const float4*)(in + i);
    float4 v1 = *(const float4*)(in + i + 4);
    __half2 h0 = __floats2half2_rn(v0.x, v0.y);
    __half2 h1 = __floats2half2_rn(v0.z, v0.w);
    __half2 h2 = __floats2half2_rn(v1.x, v1.y);
    __half2 h3 = __floats2half2_rn(v1.z, v1.w);
    uint4 o;
    o.x = *(uint32_t*)&h0; o.y = *(uint32_t*)&h1;
    o.z = *(uint32_t*)&h2; o.w = *(uint32_t*)&h3;
    *(uint4*)(out + i) = o;
}

// ---------------------------------------------------------------------------
// fp16 tensor-core GEMM: C[M,N] = A[M,K] @ B[N,K]^T + bias[N]
// 128x128x32 tile, 256 threads (8 warps 4x2), warp tile 32x64, m16n8k16,
// cp.async double-buffered, stride-40 padded smem (conflict-free ldmatrix).
// ---------------------------------------------------------------------------
#define GSTR 40

template <int OUT_HALF>
__global__ __launch_bounds__(256, 2)
void h_gemm_nt_bias(const __half* __restrict__ A, const __half* __restrict__ B,
                    const float* __restrict__ bias, void* __restrict__ Cv,
                    int M, int N, int K) {
    __shared__ __half As[2][128 * GSTR];
    __shared__ __half Bs[2][128 * GSTR];

    const int tid = threadIdx.x;
    const int lane = tid & 31;
    const int wid = tid >> 5;
    const int wm = wid >> 1;
    const int wn = wid & 1;
    const int bm = blockIdx.y * 128;
    const int bn = blockIdx.x * 128;
    const int lr = lane & 7;
    const int gq = lane >> 3;

    float acc[2][8][4];
#pragma unroll
    for (int mi = 0; mi < 2; mi++)
#pragma unroll
        for (int ni = 0; ni < 8; ni++)
#pragma unroll
            for (int j = 0; j < 4; j++) acc[mi][ni][j] = 0.f;

    auto g2s = [&](int k0, int buf) {
#pragma unroll
        for (int p = 0; p < 2; p++) {
            int cid = tid + 256 * p;
            int row = cid & 127;
            int ch = cid >> 7;  // 0..3
            cp16(smem_u32(&As[buf][row * GSTR + ch * 8]),
                 A + (size_t)(bm + row) * K + k0 + ch * 8);
            cp16(smem_u32(&Bs[buf][row * GSTR + ch * 8]),
                 B + (size_t)(bn + row) * K + k0 + ch * 8);
        }
    };

    const int nit = K / 32;
    g2s(0, 0);
    CP_COMMIT;

    for (int it = 0; it < nit; it++) {
        int buf = it & 1;
        CP_WAIT0;
        __syncthreads();
        if (it + 1 < nit) { g2s((it + 1) * 32, buf ^ 1); CP_COMMIT; }

#pragma unroll
        for (int kk2 = 0; kk2 < 2; kk2++) {
            int kk = kk2 * 16;
            uint32_t a[2][4];
#pragma unroll
            for (int mi = 0; mi < 2; mi++)
                ldsm4(a[mi][0], a[mi][1], a[mi][2], a[mi][3],
                      smem_u32(&As[buf][(wm * 32 + mi * 16 + lr + (gq & 1) * 8) * GSTR +
                                        kk + (gq >> 1) * 8]));
#pragma unroll
            for (int np = 0; np < 4; np++) {
                uint32_t b0, b1, b2, b3;
                ldsm4(b0, b1, b2, b3,
                      smem_u32(&Bs[buf][(wn * 64 + np * 16 + lr + (gq & 1) * 8) * GSTR +
                                        kk + (gq >> 1) * 8]));
#pragma unroll
                for (int mi = 0; mi < 2; mi++) {
                    mma_f16(acc[mi][np * 2], a[mi], b0, b2);
                    mma_f16(acc[mi][np * 2 + 1], a[mi], b1, b3);
                }
            }
        }
    }

    // epilogue
    const int r0 = bm + wm * 32 + (lane >> 2);
    const int c0 = bn + wn * 64 + (lane & 3) * 2;
#pragma unroll
    for (int mi = 0; mi < 2; mi++) {
#pragma unroll
        for (int ni = 0; ni < 8; ni++) {
            int r = r0 + mi * 16;
            int c = c0 + ni * 8;
            float2 bb = *(const float2*)&bias[c];
            float v00 = acc[mi][ni][0] + bb.x, v01 = acc[mi][ni][1] + bb.y;
            float v10 = acc[mi][ni][2] + bb.x, v11 = acc[mi][ni][3] + bb.y;
            if (OUT_HALF) {
                __half* C = (__half*)Cv;
                *(__half2*)&C[(size_t)r * N + c] = __floats2half2_rn(v00, v01);
                *(__half2*)&C[(size_t)(r + 8) * N + c] = __floats2half2_rn(v10, v11);
            } else {
                float* C = (float*)Cv;
                *(float2*)&C[(size_t)r * N + c] = make_float2(v00, v01);
                *(float2*)&C[(size_t)(r + 8) * N + c] = make_float2(v10, v11);
            }
        }
    }
}

// ---------------------------------------------------------------------------
// RoPE on fp16 (interleaved pairs), fp32 math, in-place.
// ---------------------------------------------------------------------------
__global__ void rope_h(__half* __restrict__ t, const float* __restrict__ cs,
                       const float* __restrict__ sn, int nheads) {
    int idx = blockIdx.x * blockDim.x + threadIdx.x;
    int ppt = nheads * 64;
    int total = TOK * ppt;
    if (idx >= total) return;
    int tok = idx / ppt;
    int rem = idx - tok * ppt;
    int h = rem >> 6;
    int i = rem & 63;
    int s = tok & (SEQ - 1);
    float c = cs[s * 64 + i];
    float si = sn[s * 64 + i];
    __half2* p = (__half2*)(t + (size_t)tok * (nheads * HD) + h * HD + 2 * i);
    float2 v = __half22float2(*p);
    *p = __floats2half2_rn(v.x * c - v.y * si, v.x * si + v.y * c);
}

// ---------------------------------------------------------------------------
// Causal GQA flash attention, fp16 MMA, fp32 accum + softmax.
// Q tile 128, KV tile 64, 8 warps (16 Q rows each), double-buffered K/V.
// ---------------------------------------------------------------------------
#define FSTR 136
#define FA_SMEM ((128 * FSTR + 2 * 64 * FSTR + 2 * 64 * FSTR) * 2)

__global__ __launch_bounds__(256, 1)
void flash_h(const __half* __restrict__ Q, const __half* __restrict__ K,
             const __half* __restrict__ V, __half* __restrict__ O) {
    extern __shared__ __half sm[];
    __half* Qs = sm;                     // [128][136]
    __half* Ks = Qs + 128 * FSTR;        // [2][64][136]
    __half* Vs = Ks + 2 * 64 * FSTR;     // [2][64][136]

    const int tid = threadIdx.x;
    const int lane = tid & 31;
    const int w = tid >> 5;
    const int q0 = blockIdx.x * 128;
    const int bh = blockIdx.y;
    const int b = bh >> 5;
    const int h = bh & 31;
    const int g = h >> 2;
    const int lr = lane & 7;
    const int gq = lane >> 3;
    const int qr = lane >> 2;
    const int qc = (lane & 3) * 2;

    const __half* Qg = Q + (size_t)(b * SEQ + q0) * DIM + h * HD;
    const __half* Kg = K + (size_t)(b * SEQ) * KVDIM + g * HD;
    const __half* Vg = V + (size_t)(b * SEQ) * KVDIM + g * HD;

    // load Q tile
#pragma unroll
    for (int p = 0; p < 8; p++) {
        int cid = tid + 256 * p;
        int row = cid & 127, ch = cid >> 7;
        cp16(smem_u32(&Qs[row * FSTR + ch * 8]), Qg + (size_t)row * DIM + ch * 8);
    }
    CP_COMMIT;

    auto ldKV = [&](int kv0, int buf) {
#pragma unroll
        for (int p = 0; p < 4; p++) {
            int cid = tid + 256 * p;
            int row = cid & 63, ch = cid >> 6;
            cp16(smem_u32(&Ks[buf * 64 * FSTR + row * FSTR + ch * 8]),
                 Kg + (size_t)(kv0 + row) * KVDIM + ch * 8);
            cp16(smem_u32(&Vs[buf * 64 * FSTR + row * FSTR + ch * 8]),
                 Vg + (size_t)(kv0 + row) * KVDIM + ch * 8);
        }
    };
    ldKV(0, 0);
    CP_COMMIT;

    float o[16][4];
#pragma unroll
    for (int nt = 0; nt < 16; nt++)
#pragma unroll
        for (int j = 0; j < 4; j++) o[nt][j] = 0.f;
    float mA = -1e30f, mB = -1e30f, lA = 0.f, lB = 0.f;
    const float scale = 0.08838834764831845f;
    const int niter = q0 / 64 + 2;
    const int rA = q0 + w * 16 + qr;

    for (int it = 0; it < niter; it++) {
        const int kv0 = it * 64;
        const int buf = it & 1;
        CP_WAIT0;
        __syncthreads();
        if (it + 1 < niter) { ldKV((it + 1) * 64, buf ^ 1); CP_COMMIT; }

        // ---- S = Q @ K^T ----
        float s[8][4];
#pragma unroll
        for (int nt = 0; nt < 8; nt++)
#pragma unroll
            for (int j = 0; j < 4; j++) s[nt][j] = 0.f;

#pragma unroll
        for (int ks = 0; ks < 8; ks++) {
            uint32_t a[4];
            ldsm4(a[0], a[1], a[2], a[3],
                  smem_u32(&Qs[(w * 16 + lr + (gq & 1) * 8) * FSTR +
                               ks * 16 + (gq >> 1) * 8]));
#pragma unroll
            for (int np = 0; np < 4; np++) {
                uint32_t b0, b1, b2, b3;
                ldsm4(b0, b1, b2, b3,
                      smem_u32(&Ks[buf * 64 * FSTR +
                                   (np * 16 + lr + (gq & 1) * 8) * FSTR +
                                   ks * 16 + (gq >> 1) * 8]));
                mma_f16(s[np * 2], a, b0, b2);
                mma_f16(s[np * 2 + 1], a, b1, b3);
            }
        }

        // ---- scale + causal mask ----
        const bool domask = (kv0 + 63) > (q0 + w * 16);
#pragma unroll
        for (int nt = 0; nt < 8; nt++)
#pragma unroll
            for (int j = 0; j < 4; j++) {
                float v = s[nt][j] * scale;
                if (domask) {
                    int col = kv0 + nt * 8 + qc + (j & 1);
                    int row = rA + (j >> 1) * 8;
                    if (col > row) v = -1e30f;
                }
                s[nt][j] = v;
            }

        // ---- online softmax ----
        float rmA = -1e30f, rmB = -1e30f;
#pragma unroll
        for (int nt = 0; nt < 8; nt++) {
            rmA = fmaxf(rmA, fmaxf(s[nt][0], s[nt][1]));
            rmB = fmaxf(rmB, fmaxf(s[nt][2], s[nt][3]));
        }
        rmA = fmaxf(rmA, __shfl_xor_sync(0xffffffffu, rmA, 1));
        rmA = fmaxf(rmA, __shfl_xor_sync(0xffffffffu, rmA, 2));
        rmB = fmaxf(rmB, __shfl_xor_sync(0xffffffffu, rmB, 1));
        rmB = fmaxf(rmB, __shfl_xor_sync(0xffffffffu, rmB, 2));

        float newmA = fmaxf(mA, rmA), newmB = fmaxf(mB, rmB);
        float aAl = __expf(mA - newmA), aBl = __expf(mB - newmB);
        float lsA = 0.f, lsB = 0.f;
#pragma unroll
        for (int nt = 0; nt < 8; nt++) {
            s[nt][0] = __expf(s[nt][0] - newmA);
            s[nt][1] = __expf(s[nt][1] - newmA);
            s[nt][2] = __expf(s[nt][2] - newmB);
            s[nt][3] = __expf(s[nt][3] - newmB);
            lsA += s[nt][0] + s[nt][1];
            lsB += s[nt][2] + s[nt][3];
        }
        lsA += __shfl_xor_sync(0xffffffffu, lsA, 1);
        lsA += __shfl_xor_sync(0xffffffffu, lsA, 2);
        lsB += __shfl_xor_sync(0xffffffffu, lsB, 1);
        lsB += __shfl_xor_sync(0xffffffffu, lsB, 2);
        lA = lA * aAl + lsA;
        lB = lB * aBl + lsB;
        mA = newmA;
        mB = newmB;
#pragma unroll
        for (int nt = 0; nt < 16; nt++) {
            o[nt][0] *= aAl; o[nt][1] *= aAl;
            o[nt][2] *= aBl; o[nt][3] *= aBl;
        }

        // ---- pack P to fp16 a-frags ----
        uint32_t pa[4][4];
#pragma unroll
        for (int t = 0; t < 4; t++) {
            pa[t][0] = pack_h2(s[2 * t][0], s[2 * t][1]);
            pa[t][1] = pack_h2(s[2 * t][2], s[2 * t][3]);
            pa[t][2] = pack_h2(s[2 * t + 1][0], s[2 * t + 1][1]);
            pa[t][3] = pack_h2(s[2 * t + 1][2], s[2 * t + 1][3]);
        }

        // ---- O += P @ V ----
#pragma unroll
        for (int t = 0; t < 4; t++) {
#pragma unroll
            for (int np = 0; np < 8; np++) {
                uint32_t v0, v1, v2, v3;
                ldsm4t(v0, v1, v2, v3,
                       smem_u32(&Vs[buf * 64 * FSTR +
                                    (t * 16 + lr + (gq & 1) * 8) * FSTR +
                                    np * 16 + (gq >> 1) * 8]));
                mma_f16(o[np * 2], pa[t], v0, v1);
                mma_f16(o[np * 2 + 1], pa[t], v2, v3);
            }
        }
    }

    // ---- write O (fp16) ----
    float iA = 1.f / lA, iB = 1.f / lB;
    __half* Og = O + (size_t)(b * SEQ + q0 + w * 16) * DIM + h * HD;
#pragma unroll
    for (int nt = 0; nt < 16; nt++) {
        int c = nt * 8 + qc;
        *(__half2*)&Og[(size_t)qr * DIM + c] =
            __floats2half2_rn(o[nt][0] * iA, o[nt][1] * iA);
        *(__half2*)&Og[(size_t)(qr + 8) * DIM + c] =
            __floats2half2_rn(o[nt][2] * iB, o[nt][3] * iB);
    }
}

// ---------------------------------------------------------------------------
extern "C" void kernel_launch(void* const* d_in, const int* in_sizes, int n_in,
                              void* d_out, int out_size) {
    const float* x   = (const float*)d_in[0];
    const float* fcs = (const float*)d_in[1];
    const float* fsn = (const float*)d_in[2];
    const float* wq = (const float*)d_in[4];
    const float* bq = (const float*)d_in[5];
    const float* wk = (const float*)d_in[6];
    const float* bk = (const float*)d_in[7];
    const float* wv = (const float*)d_in[8];
    const float* bv = (const float*)d_in[9];
    const float* wo = (const float*)d_in[10];
    const float* bo = (const float*)d_in[11];
    float* out = (float*)d_out;

    __half *xh, *wqh, *wkh, *wvh, *woh, *qh, *kh, *vh, *ah;
    cudaGetSymbolAddress((void**)&xh, g_xh);
    cudaGetSymbolAddress((void**)&wqh, g_wqh);
    cudaGetSymbolAddress((void**)&wkh, g_wkh);
    cudaGetSymbolAddress((void**)&wvh, g_wvh);
    cudaGetSymbolAddress((void**)&woh, g_woh);
    cudaGetSymbolAddress((void**)&qh, g_qh);
    cudaGetSymbolAddress((void**)&kh, g_kh);
    cudaGetSymbolAddress((void**)&vh, g_vh);
    cudaGetSymbolAddress((void**)&ah, g_ah);

    cudaFuncSetAttribute(flash_h, cudaFuncAttributeMaxDynamicSharedMemorySize,
                         FA_SMEM);

    // fp32 -> fp16 conversions
    auto cvt = [&](const float* src, __half* dst, size_t n) {
        f2h_kernel<<<(int)(n / 8 + 255) / 256, 256>>>(src, dst, (int)n);
    };
    cvt(x, xh, (size_t)TOK * DIM);
    cvt(wq, wqh, (size_t)DIM * DIM);
    cvt(wk, wkh, (size_t)KVDIM * DIM);
    cvt(wv, wvh, (size_t)KVDIM * DIM);
    cvt(wo, woh, (size_t)DIM * DIM);

    // QKV projections (fp16 MMA, fp16 out)
    h_gemm_nt_bias<1><<<dim3(DIM / 128, TOK / 128), 256>>>(
        xh, wqh, bq, qh, TOK, DIM, DIM);
    h_gemm_nt_bias<1><<<dim3(KVDIM / 128, TOK / 128), 256>>>(
        xh, wkh, bk, kh, TOK, KVDIM, DIM);
    h_gemm_nt_bias<1><<<dim3(KVDIM / 128, TOK / 128), 256>>>(
        xh, wvh, bv, vh, TOK, KVDIM, DIM);

    // RoPE on Q and K (fp16)
    rope_h<<<(TOK * NHEADS * 64 + 255) / 256, 256>>>(qh, fcs, fsn, NHEADS);
    rope_h<<<(TOK * NKV * 64 + 255) / 256, 256>>>(kh, fcs, fsn, NKV);

    // Flash attention (fp16 MMA)
    flash_h<<<dim3(SEQ / 128, BSZ * NHEADS), 256, FA_SMEM>>>(qh, kh, vh, ah);

    // Output projection (fp16 MMA, fp32 out)
    h_gemm_nt_bias<0><<<dim3(DIM / 128, TOK / 128), 256>>>(
        ah, woh, bo, out, TOK, DIM, DIM);
}

// round 5
// speedup vs baseline: 8.0716x; 1.0210x over previous
#include <cuda_runtime.h>
#include <cuda_fp16.h>
#include <math.h>
#include <stdint.h>

#define DIM 4096
#define NHEADS 32
#define NKV 8
#define HD 128
#define SEQ 2048
#define BSZ 2
#define TOK (BSZ*SEQ)
#define KVDIM (NKV*HD)
#define NQKV (DIM + 2*KVDIM)   // 6144

// fp16 scratch (no cudaMalloc allowed)
__device__ __half g_xh[(size_t)TOK * DIM];
__device__ __half g_wqkvh[(size_t)NQKV * DIM];
__device__ __half g_woh[(size_t)DIM * DIM];
__device__ float  g_bqkv[NQKV];
__device__ __half g_qh[(size_t)TOK * DIM];
__device__ __half g_kh[(size_t)TOK * KVDIM];
__device__ __half g_vh[(size_t)TOK * KVDIM];
__device__ __half g_ah[(size_t)TOK * DIM];

// ---------------------------------------------------------------------------
// PTX helpers
// ---------------------------------------------------------------------------
__device__ __forceinline__ uint32_t smem_u32(const void* p) {
    return (uint32_t)__cvta_generic_to_shared(p);
}
__device__ __forceinline__ void cp16(uint32_t dst, const void* src) {
    asm volatile("cp.async.cg.shared.global [%0], [%1], 16;\n" ::"r"(dst), "l"(src));
}
#define CP_COMMIT asm volatile("cp.async.commit_group;\n" ::: "memory")
#define CP_WAIT0  asm volatile("cp.async.wait_group 0;\n" ::: "memory")
#define CP_WAIT1  asm volatile("cp.async.wait_group 1;\n" ::: "memory")

__device__ __forceinline__ void ldsm4(uint32_t& r0, uint32_t& r1, uint32_t& r2,
                                      uint32_t& r3, uint32_t addr) {
    asm volatile("ldmatrix.sync.aligned.m8n8.x4.shared.b16 {%0,%1,%2,%3}, [%4];\n"
                 : "=r"(r0), "=r"(r1), "=r"(r2), "=r"(r3) : "r"(addr));
}
__device__ __forceinline__ void ldsm4t(uint32_t& r0, uint32_t& r1, uint32_t& r2,
                                       uint32_t& r3, uint32_t addr) {
    asm volatile("ldmatrix.sync.aligned.m8n8.x4.trans.shared.b16 {%0,%1,%2,%3}, [%4];\n"
                 : "=r"(r0), "=r"(r1), "=r"(r2), "=r"(r3) : "r"(addr));
}
__device__ __forceinline__ void mma_f16(float* c, const uint32_t* a,
                                        uint32_t b0, uint32_t b1) {
    asm volatile(
        "mma.sync.aligned.m16n8k16.row.col.f32.f16.f16.f32 "
        "{%0,%1,%2,%3}, {%4,%5,%6,%7}, {%8,%9}, {%0,%1,%2,%3};\n"
        : "+f"(c[0]), "+f"(c[1]), "+f"(c[2]), "+f"(c[3])
        : "r"(a[0]), "r"(a[1]), "r"(a[2]), "r"(a[3]), "r"(b0), "r"(b1));
}
__device__ __forceinline__ uint32_t pack_h2(float x, float y) {
    __half2 h = __floats2half2_rn(x, y);
    return *(uint32_t*)&h;
}

// ---------------------------------------------------------------------------
// fp32 -> fp16, 32 elems/thread (8 independent LDG.128 -> MLP=8)
// ---------------------------------------------------------------------------
__global__ void f2h32(const float* __restrict__ in, __half* __restrict__ out,
                      int n) {
    size_t base = (size_t)(blockIdx.x * blockDim.x + threadIdx.x) * 32;
    if (base >= (size_t)n) return;
    float4 v[8];
#pragma unroll
    for (int j = 0; j < 8; j++) v[j] = *(const float4*)(in + base + j * 4);
#pragma unroll
    for (int j = 0; j < 4; j++) {
        __half2 a = __floats2half2_rn(v[2*j].x, v[2*j].y);
        __half2 b = __floats2half2_rn(v[2*j].z, v[2*j].w);
        __half2 c = __floats2half2_rn(v[2*j+1].x, v[2*j+1].y);
        __half2 d = __floats2half2_rn(v[2*j+1].z, v[2*j+1].w);
        uint4 o;
        o.x = *(uint32_t*)&a; o.y = *(uint32_t*)&b;
        o.z = *(uint32_t*)&c; o.w = *(uint32_t*)&d;
        *(uint4*)(out + base + j * 8) = o;
    }
}

__global__ void concat_bias(const float* __restrict__ bq,
                            const float* __restrict__ bk,
                            const float* __restrict__ bv,
                            float* __restrict__ o) {
    int i = blockIdx.x * blockDim.x + threadIdx.x;
    if (i < DIM) o[i] = bq[i];
    else if (i < DIM + KVDIM) o[i] = bk[i - DIM];
    else if (i < NQKV) o[i] = bv[i - DIM - KVDIM];
}

// ---------------------------------------------------------------------------
// fp16 GEMM: C[M,N] = A[M,K] @ B[N,K]^T + bias[N]
// 128x128x32 tile, 8 warps (4x2), warp tile 32x64, m16n8k16,
// 3-stage cp.async pipeline, stride-40 padded smem.
// MODE 0: fp32 out (O-proj). MODE 1: fused QKV -> split fp16 out + RoPE.
// ---------------------------------------------------------------------------
#define GSTR 40
#define STG_H (128 * GSTR)             // halfs per stage per matrix
#define GEMM_SMEM (3 * 2 * STG_H * 2)  // 61440 bytes

template <int MODE>
__global__ __launch_bounds__(256, 2)
void h_gemm3(const __half* __restrict__ A, const __half* __restrict__ B,
             const float* __restrict__ bias, float* __restrict__ Cf,
             __half* __restrict__ Cq, __half* __restrict__ Ck,
             __half* __restrict__ Cv, const float* __restrict__ cs,
             const float* __restrict__ sn, int M, int N, int K) {
    extern __shared__ __half sh[];
    __half* As = sh;                 // [3][128*GSTR]
    __half* Bs = sh + 3 * STG_H;     // [3][128*GSTR]

    const int tid = threadIdx.x;
    const int lane = tid & 31;
    const int wid = tid >> 5;
    const int wm = wid >> 1;
    const int wn = wid & 1;
    const int bm = blockIdx.y * 128;
    const int bn = blockIdx.x * 128;
    const int lr = lane & 7;
    const int gq = lane >> 3;

    float acc[2][8][4];
#pragma unroll
    for (int mi = 0; mi < 2; mi++)
#pragma unroll
        for (int ni = 0; ni < 8; ni++)
#pragma unroll
            for (int j = 0; j < 4; j++) acc[mi][ni][j] = 0.f;

    auto g2s = [&](int k0, int stg) {
#pragma unroll
        for (int p = 0; p < 2; p++) {
            int cid = tid + 256 * p;
            int row = cid & 127;
            int ch = cid >> 7;
            cp16(smem_u32(&As[stg * STG_H + row * GSTR + ch * 8]),
                 A + (size_t)(bm + row) * K + k0 + ch * 8);
            cp16(smem_u32(&Bs[stg * STG_H + row * GSTR + ch * 8]),
                 B + (size_t)(bn + row) * K + k0 + ch * 8);
        }
    };

    const int nit = K / 32;
    g2s(0, 0); CP_COMMIT;
    g2s(32, 1); CP_COMMIT;

    int buf = 0;
    for (int it = 0; it < nit; it++) {
        CP_WAIT1;
        __syncthreads();
        if (it + 2 < nit) g2s((it + 2) * 32, (it + 2) % 3);
        CP_COMMIT;

#pragma unroll
        for (int kk2 = 0; kk2 < 2; kk2++) {
            int kk = kk2 * 16;
            uint32_t a[2][4];
#pragma unroll
            for (int mi = 0; mi < 2; mi++)
                ldsm4(a[mi][0], a[mi][1], a[mi][2], a[mi][3],
                      smem_u32(&As[buf * STG_H +
                                   (wm * 32 + mi * 16 + lr + (gq & 1) * 8) * GSTR +
                                   kk + (gq >> 1) * 8]));
#pragma unroll
            for (int np = 0; np < 4; np++) {
                uint32_t b0, b1, b2, b3;
                ldsm4(b0, b1, b2, b3,
                      smem_u32(&Bs[buf * STG_H +
                                   (wn * 64 + np * 16 + lr + (gq & 1) * 8) * GSTR +
                                   kk + (gq >> 1) * 8]));
#pragma unroll
                for (int mi = 0; mi < 2; mi++) {
                    mma_f16(acc[mi][np * 2], a[mi], b0, b2);
                    mma_f16(acc[mi][np * 2 + 1], a[mi], b1, b3);
                }
            }
        }
        buf = (buf + 1) % 3;
    }

    // ---- epilogue ----
    const int r0 = bm + wm * 32 + (lane >> 2);
    const int c0 = bn + wn * 64 + (lane & 3) * 2;
#pragma unroll
    for (int mi = 0; mi < 2; mi++) {
#pragma unroll
        for (int ni = 0; ni < 8; ni++) {
            int r = r0 + mi * 16;
            int c = c0 + ni * 8;
            float2 bb = *(const float2*)&bias[c];
            float v00 = acc[mi][ni][0] + bb.x, v01 = acc[mi][ni][1] + bb.y;
            float v10 = acc[mi][ni][2] + bb.x, v11 = acc[mi][ni][3] + bb.y;
            if (MODE == 0) {
                *(float2*)&Cf[(size_t)r * N + c] = make_float2(v00, v01);
                *(float2*)&Cf[(size_t)(r + 8) * N + c] = make_float2(v10, v11);
            } else {
                // RoPE on q (c<4096) and k (4096<=c<5120); v unchanged
                if (c < DIM + KVDIM) {
                    int i = (c & 127) >> 1;
                    int s0 = r & (SEQ - 1), s1 = (r + 8) & (SEQ - 1);
                    float c00 = cs[s0 * 64 + i], sn0 = sn[s0 * 64 + i];
                    float c10 = cs[s1 * 64 + i], sn1 = sn[s1 * 64 + i];
                    float a0 = v00, b0v = v01;
                    v00 = a0 * c00 - b0v * sn0;
                    v01 = a0 * sn0 + b0v * c00;
                    float a1 = v10, b1v = v11;
                    v10 = a1 * c10 - b1v * sn1;
                    v11 = a1 * sn1 + b1v * c10;
                }
                __half2 h0 = __floats2half2_rn(v00, v01);
                __half2 h1 = __floats2half2_rn(v10, v11);
                __half* dst;
                size_t str;
                int cc;
                if (c < DIM) { dst = Cq; str = DIM; cc = c; }
                else if (c < DIM + KVDIM) { dst = Ck; str = KVDIM; cc = c - DIM; }
                else { dst = Cv; str = KVDIM; cc = c - DIM - KVDIM; }
                *(__half2*)&dst[(size_t)r * str + cc] = h0;
                *(__half2*)&dst[(size_t)(r + 8) * str + cc] = h1;
            }
        }
    }
}

// ---------------------------------------------------------------------------
// Causal GQA flash attention, fp16 MMA, fp32 accum + softmax.
// Q tile 128, KV tile 64, 8 warps, double-buffered K/V.
// Long (high-q0) blocks scheduled first.
// ---------------------------------------------------------------------------
#define FSTR 136
#define FA_SMEM ((128 * FSTR + 2 * 64 * FSTR + 2 * 64 * FSTR) * 2)

__global__ __launch_bounds__(256, 1)
void flash_h(const __half* __restrict__ Q, const __half* __restrict__ K,
             const __half* __restrict__ V, __half* __restrict__ O) {
    extern __shared__ __half sm[];
    __half* Qs = sm;
    __half* Ks = Qs + 128 * FSTR;
    __half* Vs = Ks + 2 * 64 * FSTR;

    const int tid = threadIdx.x;
    const int lane = tid & 31;
    const int w = tid >> 5;
    const int q0 = (gridDim.x - 1 - blockIdx.x) * 128;  // heavy blocks first
    const int bh = blockIdx.y;
    const int b = bh >> 5;
    const int h = bh & 31;
    const int g = h >> 2;
    const int lr = lane & 7;
    const int gq = lane >> 3;
    const int qr = lane >> 2;
    const int qc = (lane & 3) * 2;

    const __half* Qg = Q + (size_t)(b * SEQ + q0) * DIM + h * HD;
    const __half* Kg = K + (size_t)(b * SEQ) * KVDIM + g * HD;
    const __half* Vg = V + (size_t)(b * SEQ) * KVDIM + g * HD;

#pragma unroll
    for (int p = 0; p < 8; p++) {
        int cid = tid + 256 * p;
        int row = cid & 127, ch = cid >> 7;
        cp16(smem_u32(&Qs[row * FSTR + ch * 8]), Qg + (size_t)row * DIM + ch * 8);
    }
    CP_COMMIT;

    auto ldKV = [&](int kv0, int bufl) {
#pragma unroll
        for (int p = 0; p < 4; p++) {
            int cid = tid + 256 * p;
            int row = cid & 63, ch = cid >> 6;
            cp16(smem_u32(&Ks[bufl * 64 * FSTR + row * FSTR + ch * 8]),
                 Kg + (size_t)(kv0 + row) * KVDIM + ch * 8);
            cp16(smem_u32(&Vs[bufl * 64 * FSTR + row * FSTR + ch * 8]),
                 Vg + (size_t)(kv0 + row) * KVDIM + ch * 8);
        }
    };
    ldKV(0, 0);
    CP_COMMIT;

    float o[16][4];
#pragma unroll
    for (int nt = 0; nt < 16; nt++)
#pragma unroll
        for (int j = 0; j < 4; j++) o[nt][j] = 0.f;
    float mA = -1e30f, mB = -1e30f, lA = 0.f, lB = 0.f;
    const float scale = 0.08838834764831845f;
    const int niter = q0 / 64 + 2;
    const int rA = q0 + w * 16 + qr;

    for (int it = 0; it < niter; it++) {
        const int kv0 = it * 64;
        const int buf = it & 1;
        CP_WAIT0;
        __syncthreads();
        if (it + 1 < niter) { ldKV((it + 1) * 64, buf ^ 1); CP_COMMIT; }

        float s[8][4];
#pragma unroll
        for (int nt = 0; nt < 8; nt++)
#pragma unroll
            for (int j = 0; j < 4; j++) s[nt][j] = 0.f;

#pragma unroll
        for (int ks = 0; ks < 8; ks++) {
            uint32_t a[4];
            ldsm4(a[0], a[1], a[2], a[3],
                  smem_u32(&Qs[(w * 16 + lr + (gq & 1) * 8) * FSTR +
                               ks * 16 + (gq >> 1) * 8]));
#pragma unroll
            for (int np = 0; np < 4; np++) {
                uint32_t b0, b1, b2, b3;
                ldsm4(b0, b1, b2, b3,
                      smem_u32(&Ks[buf * 64 * FSTR +
                                   (np * 16 + lr + (gq & 1) * 8) * FSTR +
                                   ks * 16 + (gq >> 1) * 8]));
                mma_f16(s[np * 2], a, b0, b2);
                mma_f16(s[np * 2 + 1], a, b1, b3);
            }
        }

        const bool domask = (kv0 + 63) > (q0 + w * 16);
#pragma unroll
        for (int nt = 0; nt < 8; nt++)
#pragma unroll
            for (int j = 0; j < 4; j++) {
                float v = s[nt][j] * scale;
                if (domask) {
                    int col = kv0 + nt * 8 + qc + (j & 1);
                    int row = rA + (j >> 1) * 8;
                    if (col > row) v = -1e30f;
                }
                s[nt][j] = v;
            }

        float rmA = -1e30f, rmB = -1e30f;
#pragma unroll
        for (int nt = 0; nt < 8; nt++) {
            rmA = fmaxf(rmA, fmaxf(s[nt][0], s[nt][1]));
            rmB = fmaxf(rmB, fmaxf(s[nt][2], s[nt][3]));
        }
        rmA = fmaxf(rmA, __shfl_xor_sync(0xffffffffu, rmA, 1));
        rmA = fmaxf(rmA, __shfl_xor_sync(0xffffffffu, rmA, 2));
        rmB = fmaxf(rmB, __shfl_xor_sync(0xffffffffu, rmB, 1));
        rmB = fmaxf(rmB, __shfl_xor_sync(0xffffffffu, rmB, 2));

        float newmA = fmaxf(mA, rmA), newmB = fmaxf(mB, rmB);
        float aAl = __expf(mA - newmA), aBl = __expf(mB - newmB);
        float lsA = 0.f, lsB = 0.f;
#pragma unroll
        for (int nt = 0; nt < 8; nt++) {
            s[nt][0] = __expf(s[nt][0] - newmA);
            s[nt][1] = __expf(s[nt][1] - newmA);
            s[nt][2] = __expf(s[nt][2] - newmB);
            s[nt][3] = __expf(s[nt][3] - newmB);
            lsA += s[nt][0] + s[nt][1];
            lsB += s[nt][2] + s[nt][3];
        }
        lsA += __shfl_xor_sync(0xffffffffu, lsA, 1);
        lsA += __shfl_xor_sync(0xffffffffu, lsA, 2);
        lsB += __shfl_xor_sync(0xffffffffu, lsB, 1);
        lsB += __shfl_xor_sync(0xffffffffu, lsB, 2);
        lA = lA * aAl + lsA;
        lB = lB * aBl + lsB;
        mA = newmA;
        mB = newmB;
#pragma unroll
        for (int nt = 0; nt < 16; nt++) {
            o[nt][0] *= aAl; o[nt][1] *= aAl;
            o[nt][2] *= aBl; o[nt][3] *= aBl;
        }

        uint32_t pa[4][4];
#pragma unroll
        for (int t = 0; t < 4; t++) {
            pa[t][0] = pack_h2(s[2 * t][0], s[2 * t][1]);
            pa[t][1] = pack_h2(s[2 * t][2], s[2 * t][3]);
            pa[t][2] = pack_h2(s[2 * t + 1][0], s[2 * t + 1][1]);
            pa[t][3] = pack_h2(s[2 * t + 1][2], s[2 * t + 1][3]);
        }

#pragma unroll
        for (int t = 0; t < 4; t++) {
#pragma unroll
            for (int np = 0; np < 8; np++) {
                uint32_t v0, v1, v2, v3;
                ldsm4t(v0, v1, v2, v3,
                       smem_u32(&Vs[buf * 64 * FSTR +
                                    (t * 16 + lr + (gq & 1) * 8) * FSTR +
                                    np * 16 + (gq >> 1) * 8]));
                mma_f16(o[np * 2], pa[t], v0, v1);
                mma_f16(o[np * 2 + 1], pa[t], v2, v3);
            }
        }
    }

    float iA = 1.f / lA, iB = 1.f / lB;
    __half* Og = O + (size_t)(b * SEQ + q0 + w * 16) * DIM + h * HD;
#pragma unroll
    for (int nt = 0; nt < 16; nt++) {
        int c = nt * 8 + qc;
        *(__half2*)&Og[(size_t)qr * DIM + c] =
            __floats2half2_rn(o[nt][0] * iA, o[nt][1] * iA);
        *(__half2*)&Og[(size_t)(qr + 8) * DIM + c] =
            __floats2half2_rn(o[nt][2] * iB, o[nt][3] * iB);
    }
}

// ---------------------------------------------------------------------------
extern "C" void kernel_launch(void* const* d_in, const int* in_sizes, int n_in,
                              void* d_out, int out_size) {
    const float* x   = (const float*)d_in[0];
    const float* fcs = (const float*)d_in[1];
    const float* fsn = (const float*)d_in[2];
    const float* wq = (const float*)d_in[4];
    const float* bq = (const float*)d_in[5];
    const float* wk = (const float*)d_in[6];
    const float* bk = (const float*)d_in[7];
    const float* wv = (const float*)d_in[8];
    const float* bv = (const float*)d_in[9];
    const float* wo = (const float*)d_in[10];
    const float* bo = (const float*)d_in[11];
    float* out = (float*)d_out;

    __half *xh, *wqkvh, *woh, *qh, *kh, *vh, *ah;
    float* bqkv;
    cudaGetSymbolAddress((void**)&xh, g_xh);
    cudaGetSymbolAddress((void**)&wqkvh, g_wqkvh);
    cudaGetSymbolAddress((void**)&woh, g_woh);
    cudaGetSymbolAddress((void**)&bqkv, g_bqkv);
    cudaGetSymbolAddress((void**)&qh, g_qh);
    cudaGetSymbolAddress((void**)&kh, g_kh);
    cudaGetSymbolAddress((void**)&vh, g_vh);
    cudaGetSymbolAddress((void**)&ah, g_ah);

    cudaFuncSetAttribute(h_gemm3<0>, cudaFuncAttributeMaxDynamicSharedMemorySize,
                         GEMM_SMEM);
    cudaFuncSetAttribute(h_gemm3<1>, cudaFuncAttributeMaxDynamicSharedMemorySize,
                         GEMM_SMEM);
    cudaFuncSetAttribute(flash_h, cudaFuncAttributeMaxDynamicSharedMemorySize,
                         FA_SMEM);

    // fp32 -> fp16 conversions (weights packed into one QKV buffer)
    auto cvt = [&](const float* src, __half* dst, size_t n) {
        f2h32<<<(int)((n / 32 + 255) / 256), 256>>>(src, dst, (int)n);
    };
    cvt(x, xh, (size_t)TOK * DIM);
    cvt(wq, wqkvh, (size_t)DIM * DIM);
    cvt(wk, wqkvh + (size_t)DIM * DIM, (size_t)KVDIM * DIM);
    cvt(wv, wqkvh + (size_t)(DIM + KVDIM) * DIM, (size_t)KVDIM * DIM);
    cvt(wo, woh, (size_t)DIM * DIM);
    concat_bias<<<(NQKV + 255) / 256, 256>>>(bq, bk, bv, bqkv);

    // Fused QKV projection + RoPE epilogue
    h_gemm3<1><<<dim3(NQKV / 128, TOK / 128), 256, GEMM_SMEM>>>(
        xh, wqkvh, bqkv, nullptr, qh, kh, vh, fcs, fsn, TOK, NQKV, DIM);

    // Flash attention
    flash_h<<<dim3(SEQ / 128, BSZ * NHEADS), 256, FA_SMEM>>>(qh, kh, vh, ah);

    // Output projection (fp32 out)
    h_gemm3<0><<<dim3(DIM / 128, TOK / 128), 256, GEMM_SMEM>>>(
        ah, woh, bo, out, nullptr, nullptr, nullptr, nullptr, nullptr,
        TOK, DIM, DIM);
}

// round 7
// speedup vs baseline: 8.1833x; 1.0138x over previous
#include <cuda_runtime.h>
#include <cuda_fp16.h>
#include <math.h>
#include <stdint.h>

#define DIM 4096
#define NHEADS 32
#define NKV 8
#define HD 128
#define SEQ 2048
#define BSZ 2
#define TOK (BSZ*SEQ)
#define KVDIM (NKV*HD)
#define NQKV (DIM + 2*KVDIM)   // 6144

// fp16 scratch (no cudaMalloc allowed)
__device__ __half g_xh[(size_t)TOK * DIM];
__device__ __half g_wqkvh[(size_t)NQKV * DIM];
__device__ __half g_woh[(size_t)DIM * DIM];
__device__ float  g_bqkv[NQKV];
__device__ __half g_qh[(size_t)TOK * DIM];
__device__ __half g_kh[(size_t)TOK * KVDIM];
__device__ __half g_vh[(size_t)TOK * KVDIM];
__device__ __half g_ah[(size_t)TOK * DIM];

// ---------------------------------------------------------------------------
// PTX helpers
// ---------------------------------------------------------------------------
__device__ __forceinline__ uint32_t smem_u32(const void* p) {
    return (uint32_t)__cvta_generic_to_shared(p);
}
__device__ __forceinline__ void cp16(uint32_t dst, const void* src) {
    asm volatile("cp.async.cg.shared.global [%0], [%1], 16;\n" ::"r"(dst), "l"(src));
}
#define CP_COMMIT asm volatile("cp.async.commit_group;\n" ::: "memory")
#define CP_WAIT0  asm volatile("cp.async.wait_group 0;\n" ::: "memory")
#define CP_WAIT1  asm volatile("cp.async.wait_group 1;\n" ::: "memory")

__device__ __forceinline__ void ldsm4(uint32_t& r0, uint32_t& r1, uint32_t& r2,
                                      uint32_t& r3, uint32_t addr) {
    asm volatile("ldmatrix.sync.aligned.m8n8.x4.shared.b16 {%0,%1,%2,%3}, [%4];\n"
                 : "=r"(r0), "=r"(r1), "=r"(r2), "=r"(r3) : "r"(addr));
}
__device__ __forceinline__ void ldsm4t(uint32_t& r0, uint32_t& r1, uint32_t& r2,
                                       uint32_t& r3, uint32_t addr) {
    asm volatile("ldmatrix.sync.aligned.m8n8.x4.trans.shared.b16 {%0,%1,%2,%3}, [%4];\n"
                 : "=r"(r0), "=r"(r1), "=r"(r2), "=r"(r3) : "r"(addr));
}
__device__ __forceinline__ void mma_f16(float* c, const uint32_t* a,
                                        uint32_t b0, uint32_t b1) {
    asm volatile(
        "mma.sync.aligned.m16n8k16.row.col.f32.f16.f16.f32 "
        "{%0,%1,%2,%3}, {%4,%5,%6,%7}, {%8,%9}, {%0,%1,%2,%3};\n"
        : "+f"(c[0]), "+f"(c[1]), "+f"(c[2]), "+f"(c[3])
        : "r"(a[0]), "r"(a[1]), "r"(a[2]), "r"(a[3]), "r"(b0), "r"(b1));
}
__device__ __forceinline__ uint32_t pack_h2(float x, float y) {
    __half2 h = __floats2half2_rn(x, y);
    return *(uint32_t*)&h;
}

// ---------------------------------------------------------------------------
// Single fused fp32 -> fp16 conversion for x, wq, wk, wv, wo (8 elems/thread)
// ---------------------------------------------------------------------------
#define SEG0 ((size_t)TOK * DIM)          // x
#define SEG1 ((size_t)DIM * DIM)          // wq
#define SEG2 ((size_t)KVDIM * DIM)        // wk
#define SEG3 ((size_t)KVDIM * DIM)        // wv
#define SEG4 ((size_t)DIM * DIM)          // wo
#define CVT_TOTAL (SEG0 + SEG1 + SEG2 + SEG3 + SEG4)

__global__ void cvt_all(const float* __restrict__ x, const float* __restrict__ wq,
                        const float* __restrict__ wk, const float* __restrict__ wv,
                        const float* __restrict__ wo, __half* __restrict__ xh,
                        __half* __restrict__ wqkvh, __half* __restrict__ woh) {
    size_t i = (size_t)(blockIdx.x * blockDim.x + threadIdx.x) * 8;
    if (i >= CVT_TOTAL) return;
    const float* src;
    __half* dst;
    size_t off;
    if (i < SEG0) { src = x; dst = xh; off = i; }
    else if (i < SEG0 + SEG1) { src = wq; dst = wqkvh; off = i - SEG0; }
    else if (i < SEG0 + SEG1 + SEG2) {
        src = wk; dst = wqkvh + SEG1; off = i - SEG0 - SEG1;
    } else if (i < SEG0 + SEG1 + SEG2 + SEG3) {
        src = wv; dst = wqkvh + SEG1 + SEG2; off = i - SEG0 - SEG1 - SEG2;
    } else { src = wo; dst = woh; off = i - SEG0 - SEG1 - SEG2 - SEG3; }

    float4 v0 = *(const float4*)(src + off);
    float4 v1 = *(const float4*)(src + off + 4);
    __half2 h0 = __floats2half2_rn(v0.x, v0.y);
    __half2 h1 = __floats2half2_rn(v0.z, v0.w);
    __half2 h2 = __floats2half2_rn(v1.x, v1.y);
    __half2 h3 = __floats2half2_rn(v1.z, v1.w);
    uint4 o;
    o.x = *(uint32_t*)&h0; o.y = *(uint32_t*)&h1;
    o.z = *(uint32_t*)&h2; o.w = *(uint32_t*)&h3;
    *(uint4*)(dst + off) = o;
}

__global__ void concat_bias(const float* __restrict__ bq,
                            const float* __restrict__ bk,
                            const float* __restrict__ bv,
                            float* __restrict__ o) {
    int i = blockIdx.x * blockDim.x + threadIdx.x;
    if (i < DIM) o[i] = bq[i];
    else if (i < DIM + KVDIM) o[i] = bk[i - DIM];
    else if (i < NQKV) o[i] = bv[i - DIM - KVDIM];
}

// ---------------------------------------------------------------------------
// fp16 GEMM: C[M,N] = A[M,K] @ B[N,K]^T + bias[N]
// 128x128x32 tile, 8 warps (4x2), warp tile 32x64, m16n8k16,
// 3-stage cp.async pipeline, stride-40 padded smem.
// MODE 0: fp32 out (O-proj). MODE 1: fused QKV -> split fp16 out + RoPE.
// ---------------------------------------------------------------------------
#define GSTR 40
#define STG_H (128 * GSTR)
#define GEMM_SMEM (3 * 2 * STG_H * 2)  // 61440 bytes

template <int MODE>
__global__ __launch_bounds__(256, 2)
void h_gemm3(const __half* __restrict__ A, const __half* __restrict__ B,
             const float* __restrict__ bias, float* __restrict__ Cf,
             __half* __restrict__ Cq, __half* __restrict__ Ck,
             __half* __restrict__ Cv, const float* __restrict__ cs,
             const float* __restrict__ sn, int M, int N, int K) {
    extern __shared__ __half sh[];
    __half* As = sh;
    __half* Bs = sh + 3 * STG_H;

    const int tid = threadIdx.x;
    const int lane = tid & 31;
    const int wid = tid >> 5;
    const int wm = wid >> 1;
    const int wn = wid & 1;
    const int bm = blockIdx.y * 128;
    const int bn = blockIdx.x * 128;
    const int lr = lane & 7;
    const int gq = lane >> 3;

    float acc[2][8][4];
#pragma unroll
    for (int mi = 0; mi < 2; mi++)
#pragma unroll
        for (int ni = 0; ni < 8; ni++)
#pragma unroll
            for (int j = 0; j < 4; j++) acc[mi][ni][j] = 0.f;

    auto g2s = [&](int k0, int stg) {
#pragma unroll
        for (int p = 0; p < 2; p++) {
            int cid = tid + 256 * p;
            int row = cid & 127;
            int ch = cid >> 7;
            cp16(smem_u32(&As[stg * STG_H + row * GSTR + ch * 8]),
                 A + (size_t)(bm + row) * K + k0 + ch * 8);
            cp16(smem_u32(&Bs[stg * STG_H + row * GSTR + ch * 8]),
                 B + (size_t)(bn + row) * K + k0 + ch * 8);
        }
    };

    const int nit = K / 32;
    g2s(0, 0); CP_COMMIT;
    g2s(32, 1); CP_COMMIT;

    int buf = 0;
    for (int it = 0; it < nit; it++) {
        CP_WAIT1;
        __syncthreads();
        if (it + 2 < nit) g2s((it + 2) * 32, (it + 2) % 3);
        CP_COMMIT;

#pragma unroll
        for (int kk2 = 0; kk2 < 2; kk2++) {
            int kk = kk2 * 16;
            uint32_t a[2][4];
#pragma unroll
            for (int mi = 0; mi < 2; mi++)
                ldsm4(a[mi][0], a[mi][1], a[mi][2], a[mi][3],
                      smem_u32(&As[buf * STG_H +
                                   (wm * 32 + mi * 16 + lr + (gq & 1) * 8) * GSTR +
                                   kk + (gq >> 1) * 8]));
#pragma unroll
            for (int np = 0; np < 4; np++) {
                uint32_t b0, b1, b2, b3;
                ldsm4(b0, b1, b2, b3,
                      smem_u32(&Bs[buf * STG_H +
                                   (wn * 64 + np * 16 + lr + (gq & 1) * 8) * GSTR +
                                   kk + (gq >> 1) * 8]));
#pragma unroll
                for (int mi = 0; mi < 2; mi++) {
                    mma_f16(acc[mi][np * 2], a[mi], b0, b2);
                    mma_f16(acc[mi][np * 2 + 1], a[mi], b1, b3);
                }
            }
        }
        buf = (buf + 1) % 3;
    }

    const int r0 = bm + wm * 32 + (lane >> 2);
    const int c0 = bn + wn * 64 + (lane & 3) * 2;
#pragma unroll
    for (int mi = 0; mi < 2; mi++) {
#pragma unroll
        for (int ni = 0; ni < 8; ni++) {
            int r = r0 + mi * 16;
            int c = c0 + ni * 8;
            float2 bb = *(const float2*)&bias[c];
            float v00 = acc[mi][ni][0] + bb.x, v01 = acc[mi][ni][1] + bb.y;
            float v10 = acc[mi][ni][2] + bb.x, v11 = acc[mi][ni][3] + bb.y;
            if (MODE == 0) {
                *(float2*)&Cf[(size_t)r * N + c] = make_float2(v00, v01);
                *(float2*)&Cf[(size_t)(r + 8) * N + c] = make_float2(v10, v11);
            } else {
                if (c < DIM + KVDIM) {
                    int i = (c & 127) >> 1;
                    int s0 = r & (SEQ - 1), s1 = (r + 8) & (SEQ - 1);
                    float c00 = cs[s0 * 64 + i], sn0 = sn[s0 * 64 + i];
                    float c10 = cs[s1 * 64 + i], sn1 = sn[s1 * 64 + i];
                    float a0 = v00, b0v = v01;
                    v00 = a0 * c00 - b0v * sn0;
                    v01 = a0 * sn0 + b0v * c00;
                    float a1 = v10, b1v = v11;
                    v10 = a1 * c10 - b1v * sn1;
                    v11 = a1 * sn1 + b1v * c10;
                }
                __half2 h0 = __floats2half2_rn(v00, v01);
                __half2 h1 = __floats2half2_rn(v10, v11);
                __half* dst;
                size_t str;
                int cc;
                if (c < DIM) { dst = Cq; str = DIM; cc = c; }
                else if (c < DIM + KVDIM) { dst = Ck; str = KVDIM; cc = c - DIM; }
                else { dst = Cv; str = KVDIM; cc = c - DIM - KVDIM; }
                *(__half2*)&dst[(size_t)r * str + cc] = h0;
                *(__half2*)&dst[(size_t)(r + 8) * str + cc] = h1;
            }
        }
    }
}

// ---------------------------------------------------------------------------
// Causal GQA flash attention, fp16 MMA, fp32 accum + softmax.
// Q tile 128, KV tile 128 (halved per-iter fixed costs vs KT=64),
// 8 warps, double-buffered K/V, heavy blocks first.
// ---------------------------------------------------------------------------
#define FSTR 136
#define KT 128
#define FA_SMEM ((128 * FSTR + 2 * KT * FSTR + 2 * KT * FSTR) * 2)  // 174080

__global__ __launch_bounds__(256, 1)
void flash_h(const __half* __restrict__ Q, const __half* __restrict__ K,
             const __half* __restrict__ V, __half* __restrict__ O) {
    extern __shared__ __half sm[];
    __half* Qs = sm;                       // [128][136]
    __half* Ks = Qs + 128 * FSTR;          // [2][128][136]
    __half* Vs = Ks + 2 * KT * FSTR;       // [2][128][136]

    const int tid = threadIdx.x;
    const int lane = tid & 31;
    const int w = tid >> 5;
    const int q0 = (gridDim.x - 1 - blockIdx.x) * 128;  // heavy blocks first
    const int bh = blockIdx.y;
    const int b = bh >> 5;
    const int h = bh & 31;
    const int g = h >> 2;
    const int lr = lane & 7;
    const int gq = lane >> 3;
    const int qr = lane >> 2;
    const int qc = (lane & 3) * 2;

    const __half* Qg = Q + (size_t)(b * SEQ + q0) * DIM + h * HD;
    const __half* Kg = K + (size_t)(b * SEQ) * KVDIM + g * HD;
    const __half* Vg = V + (size_t)(b * SEQ) * KVDIM + g * HD;

#pragma unroll
    for (int p = 0; p < 8; p++) {
        int cid = tid + 256 * p;
        int row = cid & 127, ch = cid >> 7;
        cp16(smem_u32(&Qs[row * FSTR + ch * 8]), Qg + (size_t)row * DIM + ch * 8);
    }
    CP_COMMIT;

    auto ldKV = [&](int kv0, int bufl) {
#pragma unroll
        for (int p = 0; p < 8; p++) {
            int cid = tid + 256 * p;
            int row = cid & 127, ch = cid >> 7;
            cp16(smem_u32(&Ks[bufl * KT * FSTR + row * FSTR + ch * 8]),
                 Kg + (size_t)(kv0 + row) * KVDIM + ch * 8);
            cp16(smem_u32(&Vs[bufl * KT * FSTR + row * FSTR + ch * 8]),
                 Vg + (size_t)(kv0 + row) * KVDIM + ch * 8);
        }
    };
    ldKV(0, 0);
    CP_COMMIT;

    float o[16][4];
#pragma unroll
    for (int nt = 0; nt < 16; nt++)
#pragma unroll
        for (int j = 0; j < 4; j++) o[nt][j] = 0.f;
    float mA = -1e30f, mB = -1e30f, lA = 0.f, lB = 0.f;
    const float scale = 0.08838834764831845f;
    const int niter = q0 / KT + 1;
    const int rA = q0 + w * 16 + qr;

    for (int it = 0; it < niter; it++) {
        const int kv0 = it * KT;
        const int buf = it & 1;
        CP_WAIT0;
        __syncthreads();
        if (it + 1 < niter) { ldKV((it + 1) * KT, buf ^ 1); CP_COMMIT; }

        // ---- S = Q @ K^T (16 n-tiles of 8 cols) ----
        float s[16][4];
#pragma unroll
        for (int nt = 0; nt < 16; nt++)
#pragma unroll
            for (int j = 0; j < 4; j++) s[nt][j] = 0.f;

#pragma unroll
        for (int ks = 0; ks < 8; ks++) {
            uint32_t a[4];
            ldsm4(a[0], a[1], a[2], a[3],
                  smem_u32(&Qs[(w * 16 + lr + (gq & 1) * 8) * FSTR +
                               ks * 16 + (gq >> 1) * 8]));
#pragma unroll
            for (int np = 0; np < 8; np++) {
                uint32_t b0, b1, b2, b3;
                ldsm4(b0, b1, b2, b3,
                      smem_u32(&Ks[buf * KT * FSTR +
                                   (np * 16 + lr + (gq & 1) * 8) * FSTR +
                                   ks * 16 + (gq >> 1) * 8]));
                mma_f16(s[np * 2], a, b0, b2);
                mma_f16(s[np * 2 + 1], a, b1, b3);
            }
        }

        // ---- scale + causal mask (only diagonal block needs masking) ----
        const bool domask = (kv0 + KT - 1) > (q0 + w * 16);
#pragma unroll
        for (int nt = 0; nt < 16; nt++)
#pragma unroll
            for (int j = 0; j < 4; j++) {
                float v = s[nt][j] * scale;
                if (domask) {
                    int col = kv0 + nt * 8 + qc + (j & 1);
                    int row = rA + (j >> 1) * 8;
                    if (col > row) v = -1e30f;
                }
                s[nt][j] = v;
            }

        // ---- online softmax ----
        float rmA = -1e30f, rmB = -1e30f;
#pragma unroll
        for (int nt = 0; nt < 16; nt++) {
            rmA = fmaxf(rmA, fmaxf(s[nt][0], s[nt][1]));
            rmB = fmaxf(rmB, fmaxf(s[nt][2], s[nt][3]));
        }
        rmA = fmaxf(rmA, __shfl_xor_sync(0xffffffffu, rmA, 1));
        rmA = fmaxf(rmA, __shfl_xor_sync(0xffffffffu, rmA, 2));
        rmB = fmaxf(rmB, __shfl_xor_sync(0xffffffffu, rmB, 1));
        rmB = fmaxf(rmB, __shfl_xor_sync(0xffffffffu, rmB, 2));

        float newmA = fmaxf(mA, rmA), newmB = fmaxf(mB, rmB);
        float aAl = __expf(mA - newmA), aBl = __expf(mB - newmB);
        float lsA = 0.f, lsB = 0.f;
#pragma unroll
        for (int nt = 0; nt < 16; nt++) {
            s[nt][0] = __expf(s[nt][0] - newmA);
            s[nt][1] = __expf(s[nt][1] - newmA);
            s[nt][2] = __expf(s[nt][2] - newmB);
            s[nt][3] = __expf(s[nt][3] - newmB);
            lsA += s[nt][0] + s[nt][1];
            lsB += s[nt][2] + s[nt][3];
        }
        lsA += __shfl_xor_sync(0xffffffffu, lsA, 1);
        lsA += __shfl_xor_sync(0xffffffffu, lsA, 2);
        lsB += __shfl_xor_sync(0xffffffffu, lsB, 1);
        lsB += __shfl_xor_sync(0xffffffffu, lsB, 2);
        lA = lA * aAl + lsA;
        lB = lB * aBl + lsB;
        mA = newmA;
        mB = newmB;
#pragma unroll
        for (int nt = 0; nt < 16; nt++) {
            o[nt][0] *= aAl; o[nt][1] *= aAl;
            o[nt][2] *= aBl; o[nt][3] *= aBl;
        }

        // ---- pack P to fp16 a-frags (8 k-tiles of 16) ----
        uint32_t pa[8][4];
#pragma unroll
        for (int t = 0; t < 8; t++) {
            pa[t][0] = pack_h2(s[2 * t][0], s[2 * t][1]);
            pa[t][1] = pack_h2(s[2 * t][2], s[2 * t][3]);
            pa[t][2] = pack_h2(s[2 * t + 1][0], s[2 * t + 1][1]);
            pa[t][3] = pack_h2(s[2 * t + 1][2], s[2 * t + 1][3]);
        }

        // ---- O += P @ V ----
#pragma unroll
        for (int t = 0; t < 8; t++) {
#pragma unroll
            for (int np = 0; np < 8; np++) {
                uint32_t v0, v1, v2, v3;
                ldsm4t(v0, v1, v2, v3,
                       smem_u32(&Vs[buf * KT * FSTR +
                                    (t * 16 + lr + (gq & 1) * 8) * FSTR +
                                    np * 16 + (gq >> 1) * 8]));
                mma_f16(o[np * 2], pa[t], v0, v1);
                mma_f16(o[np * 2 + 1], pa[t], v2, v3);
            }
        }
    }

    float iA = 1.f / lA, iB = 1.f / lB;
    __half* Og = O + (size_t)(b * SEQ + q0 + w * 16) * DIM + h * HD;
#pragma unroll
    for (int nt = 0; nt < 16; nt++) {
        int c = nt * 8 + qc;
        *(__half2*)&Og[(size_t)qr * DIM + c] =
            __floats2half2_rn(o[nt][0] * iA, o[nt][1] * iA);
        *(__half2*)&Og[(size_t)(qr + 8) * DIM + c] =
            __floats2half2_rn(o[nt][2] * iB, o[nt][3] * iB);
    }
}

// ---------------------------------------------------------------------------
extern "C" void kernel_launch(void* const* d_in, const int* in_sizes, int n_in,
                              void* d_out, int out_size) {
    const float* x   = (const float*)d_in[0];
    const float* fcs = (const float*)d_in[1];
    const float* fsn = (const float*)d_in[2];
    const float* wq = (const float*)d_in[4];
    const float* bq = (const float*)d_in[5];
    const float* wk = (const float*)d_in[6];
    const float* bk = (const float*)d_in[7];
    const float* wv = (const float*)d_in[8];
    const float* bv = (const float*)d_in[9];
    const float* wo = (const float*)d_in[10];
    const float* bo = (const float*)d_in[11];
    float* out = (float*)d_out;

    __half *xh, *wqkvh, *woh, *qh, *kh, *vh, *ah;
    float* bqkv;
    cudaGetSymbolAddress((void**)&xh, g_xh);
    cudaGetSymbolAddress((void**)&wqkvh, g_wqkvh);
    cudaGetSymbolAddress((void**)&woh, g_woh);
    cudaGetSymbolAddress((void**)&bqkv, g_bqkv);
    cudaGetSymbolAddress((void**)&qh, g_qh);
    cudaGetSymbolAddress((void**)&kh, g_kh);
    cudaGetSymbolAddress((void**)&vh, g_vh);
    cudaGetSymbolAddress((void**)&ah, g_ah);

    cudaFuncSetAttribute(h_gemm3<0>, cudaFuncAttributeMaxDynamicSharedMemorySize,
                         GEMM_SMEM);
    cudaFuncSetAttribute(h_gemm3<1>, cudaFuncAttributeMaxDynamicSharedMemorySize,
                         GEMM_SMEM);
    cudaFuncSetAttribute(flash_h, cudaFuncAttributeMaxDynamicSharedMemorySize,
                         FA_SMEM);

    // All fp32->fp16 conversions in one launch
    cvt_all<<<(int)((CVT_TOTAL / 8 + 255) / 256), 256>>>(
        x, wq, wk, wv, wo, xh, wqkvh, woh);
    concat_bias<<<(NQKV + 255) / 256, 256>>>(bq, bk, bv, bqkv);

    // Fused QKV projection + RoPE epilogue
    h_gemm3<1><<<dim3(NQKV / 128, TOK / 128), 256, GEMM_SMEM>>>(
        xh, wqkvh, bqkv, nullptr, qh, kh, vh, fcs, fsn, TOK, NQKV, DIM);

    // Flash attention (KT=128)
    flash_h<<<dim3(SEQ / 128, BSZ * NHEADS), 256, FA_SMEM>>>(qh, kh, vh, ah);

    // Output projection (fp32 out)
    h_gemm3<0><<<dim3(DIM / 128, TOK / 128), 256, GEMM_SMEM>>>(
        ah, woh, bo, out, nullptr, nullptr, nullptr, nullptr, nullptr,
        TOK, DIM, DIM);
}

// round 8
// speedup vs baseline: 9.4591x; 1.1559x over previous
#include <cuda_runtime.h>
#include <cuda_fp16.h>
#include <math.h>
#include <stdint.h>

#define DIM 4096
#define NHEADS 32
#define NKV 8
#define HD 128
#define SEQ 2048
#define BSZ 2
#define TOK (BSZ*SEQ)
#define KVDIM (NKV*HD)
#define NQKV (DIM + 2*KVDIM)   // 6144

// fp16 scratch (no cudaMalloc allowed)
__device__ __half g_xh[(size_t)TOK * DIM];
__device__ __half g_wqkvh[(size_t)NQKV * DIM];
__device__ __half g_woh[(size_t)DIM * DIM];
__device__ float  g_bqkv[NQKV];
__device__ __half g_qh[(size_t)TOK * DIM];
__device__ __half g_kh[(size_t)TOK * KVDIM];
__device__ __half g_vh[(size_t)TOK * KVDIM];
__device__ __half g_ah[(size_t)TOK * DIM];

// ---------------------------------------------------------------------------
// PTX helpers
// ---------------------------------------------------------------------------
__device__ __forceinline__ uint32_t smem_u32(const void* p) {
    return (uint32_t)__cvta_generic_to_shared(p);
}
__device__ __forceinline__ void cp16(uint32_t dst, const void* src) {
    asm volatile("cp.async.cg.shared.global [%0], [%1], 16;\n" ::"r"(dst), "l"(src));
}
#define CP_COMMIT asm volatile("cp.async.commit_group;\n" ::: "memory")
#define CP_WAIT0  asm volatile("cp.async.wait_group 0;\n" ::: "memory")
#define CP_WAIT1  asm volatile("cp.async.wait_group 1;\n" ::: "memory")

__device__ __forceinline__ void ldsm4(uint32_t& r0, uint32_t& r1, uint32_t& r2,
                                      uint32_t& r3, uint32_t addr) {
    asm volatile("ldmatrix.sync.aligned.m8n8.x4.shared.b16 {%0,%1,%2,%3}, [%4];\n"
                 : "=r"(r0), "=r"(r1), "=r"(r2), "=r"(r3) : "r"(addr));
}
__device__ __forceinline__ void ldsm4t(uint32_t& r0, uint32_t& r1, uint32_t& r2,
                                       uint32_t& r3, uint32_t addr) {
    asm volatile("ldmatrix.sync.aligned.m8n8.x4.trans.shared.b16 {%0,%1,%2,%3}, [%4];\n"
                 : "=r"(r0), "=r"(r1), "=r"(r2), "=r"(r3) : "r"(addr));
}
__device__ __forceinline__ void mma_f16(float* c, const uint32_t* a,
                                        uint32_t b0, uint32_t b1) {
    asm volatile(
        "mma.sync.aligned.m16n8k16.row.col.f32.f16.f16.f32 "
        "{%0,%1,%2,%3}, {%4,%5,%6,%7}, {%8,%9}, {%0,%1,%2,%3};\n"
        : "+f"(c[0]), "+f"(c[1]), "+f"(c[2]), "+f"(c[3])
        : "r"(a[0]), "r"(a[1]), "r"(a[2]), "r"(a[3]), "r"(b0), "r"(b1));
}
__device__ __forceinline__ uint32_t pack_h2(float x, float y) {
    __half2 h = __floats2half2_rn(x, y);
    return *(uint32_t*)&h;
}

// ---------------------------------------------------------------------------
// Single fused fp32 -> fp16 conversion for x, wq, wk, wv, wo (8 elems/thread)
// ---------------------------------------------------------------------------
#define SEG0 ((size_t)TOK * DIM)
#define SEG1 ((size_t)DIM * DIM)
#define SEG2 ((size_t)KVDIM * DIM)
#define SEG3 ((size_t)KVDIM * DIM)
#define SEG4 ((size_t)DIM * DIM)
#define CVT_TOTAL (SEG0 + SEG1 + SEG2 + SEG3 + SEG4)

__global__ void cvt_all(const float* __restrict__ x, const float* __restrict__ wq,
                        const float* __restrict__ wk, const float* __restrict__ wv,
                        const float* __restrict__ wo, __half* __restrict__ xh,
                        __half* __restrict__ wqkvh, __half* __restrict__ woh) {
    size_t i = (size_t)(blockIdx.x * blockDim.x + threadIdx.x) * 8;
    if (i >= CVT_TOTAL) return;
    const float* src;
    __half* dst;
    size_t off;
    if (i < SEG0) { src = x; dst = xh; off = i; }
    else if (i < SEG0 + SEG1) { src = wq; dst = wqkvh; off = i - SEG0; }
    else if (i < SEG0 + SEG1 + SEG2) {
        src = wk; dst = wqkvh + SEG1; off = i - SEG0 - SEG1;
    } else if (i < SEG0 + SEG1 + SEG2 + SEG3) {
        src = wv; dst = wqkvh + SEG1 + SEG2; off = i - SEG0 - SEG1 - SEG2;
    } else { src = wo; dst = woh; off = i - SEG0 - SEG1 - SEG2 - SEG3; }

    float4 v0 = *(const float4*)(src + off);
    float4 v1 = *(const float4*)(src + off + 4);
    __half2 h0 = __floats2half2_rn(v0.x, v0.y);
    __half2 h1 = __floats2half2_rn(v0.z, v0.w);
    __half2 h2 = __floats2half2_rn(v1.x, v1.y);
    __half2 h3 = __floats2half2_rn(v1.z, v1.w);
    uint4 o;
    o.x = *(uint32_t*)&h0; o.y = *(uint32_t*)&h1;
    o.z = *(uint32_t*)&h2; o.w = *(uint32_t*)&h3;
    *(uint4*)(dst + off) = o;
}

__global__ void concat_bias(const float* __restrict__ bq,
                            const float* __restrict__ bk,
                            const float* __restrict__ bv,
                            float* __restrict__ o) {
    int i = blockIdx.x * blockDim.x + threadIdx.x;
    if (i < DIM) o[i] = bq[i];
    else if (i < DIM + KVDIM) o[i] = bk[i - DIM];
    else if (i < NQKV) o[i] = bv[i - DIM - KVDIM];
}

// ---------------------------------------------------------------------------
// fp16 GEMM: C[M,N] = A[M,K] @ B[N,K]^T + bias[N]
// CTA tile 128x256x32, 8 warps (2x4), warp tile 64x64 (MMA:LDSM ratio 4.0),
// m16n8k16, 3-stage cp.async pipeline, stride-40 padded smem.
// MODE 0: fp32 out (O-proj). MODE 1: fused QKV -> split fp16 out + RoPE.
// ---------------------------------------------------------------------------
#define GSTR 40
#define A_STG (128 * GSTR)                 // halfs per A stage
#define B_STG (256 * GSTR)                 // halfs per B stage
#define GEMM_SMEM (3 * (A_STG + B_STG) * 2)  // 92160 bytes

template <int MODE>
__global__ __launch_bounds__(256, 1)
void h_gemm3(const __half* __restrict__ A, const __half* __restrict__ B,
             const float* __restrict__ bias, float* __restrict__ Cf,
             __half* __restrict__ Cq, __half* __restrict__ Ck,
             __half* __restrict__ Cv, const float* __restrict__ cs,
             const float* __restrict__ sn, int M, int N, int K) {
    extern __shared__ __half sh[];
    __half* As = sh;                 // [3][A_STG]
    __half* Bs = sh + 3 * A_STG;     // [3][B_STG]

    const int tid = threadIdx.x;
    const int lane = tid & 31;
    const int wid = tid >> 5;
    const int wm = wid >> 2;   // 0..1  (64 rows each)
    const int wn = wid & 3;    // 0..3  (64 cols each)
    const int bm = blockIdx.y * 128;
    const int bn = blockIdx.x * 256;
    const int lr = lane & 7;
    const int gq = lane >> 3;

    float acc[4][8][4];
#pragma unroll
    for (int mi = 0; mi < 4; mi++)
#pragma unroll
        for (int ni = 0; ni < 8; ni++)
#pragma unroll
            for (int j = 0; j < 4; j++) acc[mi][ni][j] = 0.f;

    auto g2s = [&](int k0, int stg) {
        // A: 128 rows x 32 cols = 512 16B-chunks
#pragma unroll
        for (int p = 0; p < 2; p++) {
            int cid = tid + 256 * p;
            int row = cid >> 2;
            int ch = cid & 3;
            cp16(smem_u32(&As[stg * A_STG + row * GSTR + ch * 8]),
                 A + (size_t)(bm + row) * K + k0 + ch * 8);
        }
        // B: 256 rows x 32 cols = 1024 16B-chunks
#pragma unroll
        for (int p = 0; p < 4; p++) {
            int cid = tid + 256 * p;
            int row = cid >> 2;
            int ch = cid & 3;
            cp16(smem_u32(&Bs[stg * B_STG + row * GSTR + ch * 8]),
                 B + (size_t)(bn + row) * K + k0 + ch * 8);
        }
    };

    const int nit = K / 32;
    g2s(0, 0); CP_COMMIT;
    g2s(32, 1); CP_COMMIT;

    int buf = 0;
    for (int it = 0; it < nit; it++) {
        CP_WAIT1;
        __syncthreads();
        if (it + 2 < nit) g2s((it + 2) * 32, (it + 2) % 3);
        CP_COMMIT;

#pragma unroll
        for (int kk2 = 0; kk2 < 2; kk2++) {
            int kk = kk2 * 16;
            uint32_t a[4][4];
#pragma unroll
            for (int mi = 0; mi < 4; mi++)
                ldsm4(a[mi][0], a[mi][1], a[mi][2], a[mi][3],
                      smem_u32(&As[buf * A_STG +
                                   (wm * 64 + mi * 16 + lr + (gq & 1) * 8) * GSTR +
                                   kk + (gq >> 1) * 8]));
#pragma unroll
            for (int nt = 0; nt < 4; nt++) {
                uint32_t b0, b1, b2, b3;
                ldsm4(b0, b1, b2, b3,
                      smem_u32(&Bs[buf * B_STG +
                                   (wn * 64 + nt * 16 + lr + (gq & 1) * 8) * GSTR +
                                   kk + (gq >> 1) * 8]));
#pragma unroll
                for (int mi = 0; mi < 4; mi++) {
                    mma_f16(acc[mi][nt * 2], a[mi], b0, b2);
                    mma_f16(acc[mi][nt * 2 + 1], a[mi], b1, b3);
                }
            }
        }
        buf = (buf + 1) % 3;
    }

    // ---- epilogue ----
    const int r0 = bm + wm * 64 + (lane >> 2);
    const int c0 = bn + wn * 64 + (lane & 3) * 2;
#pragma unroll
    for (int mi = 0; mi < 4; mi++) {
#pragma unroll
        for (int ni = 0; ni < 8; ni++) {
            int r = r0 + mi * 16;
            int c = c0 + ni * 8;
            float2 bb = *(const float2*)&bias[c];
            float v00 = acc[mi][ni][0] + bb.x, v01 = acc[mi][ni][1] + bb.y;
            float v10 = acc[mi][ni][2] + bb.x, v11 = acc[mi][ni][3] + bb.y;
            if (MODE == 0) {
                *(float2*)&Cf[(size_t)r * N + c] = make_float2(v00, v01);
                *(float2*)&Cf[(size_t)(r + 8) * N + c] = make_float2(v10, v11);
            } else {
                if (c < DIM + KVDIM) {
                    int i = (c & 127) >> 1;
                    int s0 = r & (SEQ - 1), s1 = (r + 8) & (SEQ - 1);
                    float c00 = cs[s0 * 64 + i], sn0 = sn[s0 * 64 + i];
                    float c10 = cs[s1 * 64 + i], sn1 = sn[s1 * 64 + i];
                    float a0 = v00, b0v = v01;
                    v00 = a0 * c00 - b0v * sn0;
                    v01 = a0 * sn0 + b0v * c00;
                    float a1 = v10, b1v = v11;
                    v10 = a1 * c10 - b1v * sn1;
                    v11 = a1 * sn1 + b1v * c10;
                }
                __half2 h0 = __floats2half2_rn(v00, v01);
                __half2 h1 = __floats2half2_rn(v10, v11);
                __half* dst;
                size_t str;
                int cc;
                if (c < DIM) { dst = Cq; str = DIM; cc = c; }
                else if (c < DIM + KVDIM) { dst = Ck; str = KVDIM; cc = c - DIM; }
                else { dst = Cv; str = KVDIM; cc = c - DIM - KVDIM; }
                *(__half2*)&dst[(size_t)r * str + cc] = h0;
                *(__half2*)&dst[(size_t)(r + 8) * str + cc] = h1;
            }
        }
    }
}

// ---------------------------------------------------------------------------
// Causal GQA flash attention, fp16 MMA (unchanged from R6, KT=128).
// ---------------------------------------------------------------------------
#define FSTR 136
#define KT 128
#define FA_SMEM ((128 * FSTR + 2 * KT * FSTR + 2 * KT * FSTR) * 2)  // 174080

__global__ __launch_bounds__(256, 1)
void flash_h(const __half* __restrict__ Q, const __half* __restrict__ K,
             const __half* __restrict__ V, __half* __restrict__ O) {
    extern __shared__ __half sm[];
    __half* Qs = sm;
    __half* Ks = Qs + 128 * FSTR;
    __half* Vs = Ks + 2 * KT * FSTR;

    const int tid = threadIdx.x;
    const int lane = tid & 31;
    const int w = tid >> 5;
    const int q0 = (gridDim.x - 1 - blockIdx.x) * 128;
    const int bh = blockIdx.y;
    const int b = bh >> 5;
    const int h = bh & 31;
    const int g = h >> 2;
    const int lr = lane & 7;
    const int gq = lane >> 3;
    const int qr = lane >> 2;
    const int qc = (lane & 3) * 2;

    const __half* Qg = Q + (size_t)(b * SEQ + q0) * DIM + h * HD;
    const __half* Kg = K + (size_t)(b * SEQ) * KVDIM + g * HD;
    const __half* Vg = V + (size_t)(b * SEQ) * KVDIM + g * HD;

#pragma unroll
    for (int p = 0; p < 8; p++) {
        int cid = tid + 256 * p;
        int row = cid & 127, ch = cid >> 7;
        cp16(smem_u32(&Qs[row * FSTR + ch * 8]), Qg + (size_t)row * DIM + ch * 8);
    }
    CP_COMMIT;

    auto ldKV = [&](int kv0, int bufl) {
#pragma unroll
        for (int p = 0; p < 8; p++) {
            int cid = tid + 256 * p;
            int row = cid & 127, ch = cid >> 7;
            cp16(smem_u32(&Ks[bufl * KT * FSTR + row * FSTR + ch * 8]),
                 Kg + (size_t)(kv0 + row) * KVDIM + ch * 8);
            cp16(smem_u32(&Vs[bufl * KT * FSTR + row * FSTR + ch * 8]),
                 Vg + (size_t)(kv0 + row) * KVDIM + ch * 8);
        }
    };
    ldKV(0, 0);
    CP_COMMIT;

    float o[16][4];
#pragma unroll
    for (int nt = 0; nt < 16; nt++)
#pragma unroll
        for (int j = 0; j < 4; j++) o[nt][j] = 0.f;
    float mA = -1e30f, mB = -1e30f, lA = 0.f, lB = 0.f;
    const float scale = 0.08838834764831845f;
    const int niter = q0 / KT + 1;
    const int rA = q0 + w * 16 + qr;

    for (int it = 0; it < niter; it++) {
        const int kv0 = it * KT;
        const int buf = it & 1;
        CP_WAIT0;
        __syncthreads();
        if (it + 1 < niter) { ldKV((it + 1) * KT, buf ^ 1); CP_COMMIT; }

        float s[16][4];
#pragma unroll
        for (int nt = 0; nt < 16; nt++)
#pragma unroll
            for (int j = 0; j < 4; j++) s[nt][j] = 0.f;

#pragma unroll
        for (int ks = 0; ks < 8; ks++) {
            uint32_t a[4];
            ldsm4(a[0], a[1], a[2], a[3],
                  smem_u32(&Qs[(w * 16 + lr + (gq & 1) * 8) * FSTR +
                               ks * 16 + (gq >> 1) * 8]));
#pragma unroll
            for (int np = 0; np < 8; np++) {
                uint32_t b0, b1, b2, b3;
                ldsm4(b0, b1, b2, b3,
                      smem_u32(&Ks[buf * KT * FSTR +
                                   (np * 16 + lr + (gq & 1) * 8) * FSTR +
                                   ks * 16 + (gq >> 1) * 8]));
                mma_f16(s[np * 2], a, b0, b2);
                mma_f16(s[np * 2 + 1], a, b1, b3);
            }
        }

        const bool domask = (kv0 + KT - 1) > (q0 + w * 16);
#pragma unroll
        for (int nt = 0; nt < 16; nt++)
#pragma unroll
            for (int j = 0; j < 4; j++) {
                float v = s[nt][j] * scale;
                if (domask) {
                    int col = kv0 + nt * 8 + qc + (j & 1);
                    int row = rA + (j >> 1) * 8;
                    if (col > row) v = -1e30f;
                }
                s[nt][j] = v;
            }

        float rmA = -1e30f, rmB = -1e30f;
#pragma unroll
        for (int nt = 0; nt < 16; nt++) {
            rmA = fmaxf(rmA, fmaxf(s[nt][0], s[nt][1]));
            rmB = fmaxf(rmB, fmaxf(s[nt][2], s[nt][3]));
        }
        rmA = fmaxf(rmA, __shfl_xor_sync(0xffffffffu, rmA, 1));
        rmA = fmaxf(rmA, __shfl_xor_sync(0xffffffffu, rmA, 2));
        rmB = fmaxf(rmB, __shfl_xor_sync(0xffffffffu, rmB, 1));
        rmB = fmaxf(rmB, __shfl_xor_sync(0xffffffffu, rmB, 2));

        float newmA = fmaxf(mA, rmA), newmB = fmaxf(mB, rmB);
        float aAl = __expf(mA - newmA), aBl = __expf(mB - newmB);
        float lsA = 0.f, lsB = 0.f;
#pragma unroll
        for (int nt = 0; nt < 16; nt++) {
            s[nt][0] = __expf(s[nt][0] - newmA);
            s[nt][1] = __expf(s[nt][1] - newmA);
            s[nt][2] = __expf(s[nt][2] - newmB);
            s[nt][3] = __expf(s[nt][3] - newmB);
            lsA += s[nt][0] + s[nt][1];
            lsB += s[nt][2] + s[nt][3];
        }
        lsA += __shfl_xor_sync(0xffffffffu, lsA, 1);
        lsA += __shfl_xor_sync(0xffffffffu, lsA, 2);
        lsB += __shfl_xor_sync(0xffffffffu, lsB, 1);
        lsB += __shfl_xor_sync(0xffffffffu, lsB, 2);
        lA = lA * aAl + lsA;
        lB = lB * aBl + lsB;
        mA = newmA;
        mB = newmB;
#pragma unroll
        for (int nt = 0; nt < 16; nt++) {
            o[nt][0] *= aAl; o[nt][1] *= aAl;
            o[nt][2] *= aBl; o[nt][3] *= aBl;
        }

        uint32_t pa[8][4];
#pragma unroll
        for (int t = 0; t < 8; t++) {
            pa[t][0] = pack_h2(s[2 * t][0], s[2 * t][1]);
            pa[t][1] = pack_h2(s[2 * t][2], s[2 * t][3]);
            pa[t][2] = pack_h2(s[2 * t + 1][0], s[2 * t + 1][1]);
            pa[t][3] = pack_h2(s[2 * t + 1][2], s[2 * t + 1][3]);
        }

#pragma unroll
        for (int t = 0; t < 8; t++) {
#pragma unroll
            for (int np = 0; np < 8; np++) {
                uint32_t v0, v1, v2, v3;
                ldsm4t(v0, v1, v2, v3,
                       smem_u32(&Vs[buf * KT * FSTR +
                                    (t * 16 + lr + (gq & 1) * 8) * FSTR +
                                    np * 16 + (gq >> 1) * 8]));
                mma_f16(o[np * 2], pa[t], v0, v1);
                mma_f16(o[np * 2 + 1], pa[t], v2, v3);
            }
        }
    }

    float iA = 1.f / lA, iB = 1.f / lB;
    __half* Og = O + (size_t)(b * SEQ + q0 + w * 16) * DIM + h * HD;
#pragma unroll
    for (int nt = 0; nt < 16; nt++) {
        int c = nt * 8 + qc;
        *(__half2*)&Og[(size_t)qr * DIM + c] =
            __floats2half2_rn(o[nt][0] * iA, o[nt][1] * iA);
        *(__half2*)&Og[(size_t)(qr + 8) * DIM + c] =
            __floats2half2_rn(o[nt][2] * iB, o[nt][3] * iB);
    }
}

// ---------------------------------------------------------------------------
extern "C" void kernel_launch(void* const* d_in, const int* in_sizes, int n_in,
                              void* d_out, int out_size) {
    const float* x   = (const float*)d_in[0];
    const float* fcs = (const float*)d_in[1];
    const float* fsn = (const float*)d_in[2];
    const float* wq = (const float*)d_in[4];
    const float* bq = (const float*)d_in[5];
    const float* wk = (const float*)d_in[6];
    const float* bk = (const float*)d_in[7];
    const float* wv = (const float*)d_in[8];
    const float* bv = (const float*)d_in[9];
    const float* wo = (const float*)d_in[10];
    const float* bo = (const float*)d_in[11];
    float* out = (float*)d_out;

    __half *xh, *wqkvh, *woh, *qh, *kh, *vh, *ah;
    float* bqkv;
    cudaGetSymbolAddress((void**)&xh, g_xh);
    cudaGetSymbolAddress((void**)&wqkvh, g_wqkvh);
    cudaGetSymbolAddress((void**)&woh, g_woh);
    cudaGetSymbolAddress((void**)&bqkv, g_bqkv);
    cudaGetSymbolAddress((void**)&qh, g_qh);
    cudaGetSymbolAddress((void**)&kh, g_kh);
    cudaGetSymbolAddress((void**)&vh, g_vh);
    cudaGetSymbolAddress((void**)&ah, g_ah);

    cudaFuncSetAttribute(h_gemm3<0>, cudaFuncAttributeMaxDynamicSharedMemorySize,
                         GEMM_SMEM);
    cudaFuncSetAttribute(h_gemm3<1>, cudaFuncAttributeMaxDynamicSharedMemorySize,
                         GEMM_SMEM);
    cudaFuncSetAttribute(flash_h, cudaFuncAttributeMaxDynamicSharedMemorySize,
                         FA_SMEM);

    // All fp32->fp16 conversions in one launch
    cvt_all<<<(int)((CVT_TOTAL / 8 + 255) / 256), 256>>>(
        x, wq, wk, wv, wo, xh, wqkvh, woh);
    concat_bias<<<(NQKV + 255) / 256, 256>>>(bq, bk, bv, bqkv);

    // Fused QKV projection + RoPE epilogue
    h_gemm3<1><<<dim3(NQKV / 256, TOK / 128), 256, GEMM_SMEM>>>(
        xh, wqkvh, bqkv, nullptr, qh, kh, vh, fcs, fsn, TOK, NQKV, DIM);

    // Flash attention (KT=128)
    flash_h<<<dim3(SEQ / 128, BSZ * NHEADS), 256, FA_SMEM>>>(qh, kh, vh, ah);

    // Output projection (fp32 out)
    h_gemm3<0><<<dim3(DIM / 256, TOK / 128), 256, GEMM_SMEM>>>(
        ah, woh, bo, out, nullptr, nullptr, nullptr, nullptr, nullptr,
        TOK, DIM, DIM);
}

// round 9
// speedup vs baseline: 10.3193x; 1.0909x over previous
#include <cuda_runtime.h>
#include <cuda_fp16.h>
#include <math.h>
#include <stdint.h>

#define DIM 4096
#define NHEADS 32
#define NKV 8
#define HD 128
#define SEQ 2048
#define BSZ 2
#define TOK (BSZ*SEQ)
#define KVDIM (NKV*HD)
#define NQKV (DIM + 2*KVDIM)   // 6144

// fp16 scratch (no cudaMalloc allowed)
__device__ __half g_xh[(size_t)TOK * DIM];
__device__ __half g_wqkvh[(size_t)NQKV * DIM];
__device__ __half g_woh[(size_t)DIM * DIM];
__device__ float  g_bqkv[NQKV];
__device__ __half g_qh[(size_t)TOK * DIM];
__device__ __half g_kh[(size_t)TOK * KVDIM];
__device__ __half g_vh[(size_t)TOK * KVDIM];
__device__ __half g_ah[(size_t)TOK * DIM];

// ---------------------------------------------------------------------------
// PTX helpers
// ---------------------------------------------------------------------------
__device__ __forceinline__ uint32_t smem_u32(const void* p) {
    return (uint32_t)__cvta_generic_to_shared(p);
}
__device__ __forceinline__ void cp16(uint32_t dst, const void* src) {
    asm volatile("cp.async.cg.shared.global [%0], [%1], 16;\n" ::"r"(dst), "l"(src));
}
#define CP_COMMIT asm volatile("cp.async.commit_group;\n" ::: "memory")
#define CP_WAIT0  asm volatile("cp.async.wait_group 0;\n" ::: "memory")

__device__ __forceinline__ void ldsm4(uint32_t& r0, uint32_t& r1, uint32_t& r2,
                                      uint32_t& r3, uint32_t addr) {
    asm volatile("ldmatrix.sync.aligned.m8n8.x4.shared.b16 {%0,%1,%2,%3}, [%4];\n"
                 : "=r"(r0), "=r"(r1), "=r"(r2), "=r"(r3) : "r"(addr));
}
__device__ __forceinline__ void ldsm4t(uint32_t& r0, uint32_t& r1, uint32_t& r2,
                                       uint32_t& r3, uint32_t addr) {
    asm volatile("ldmatrix.sync.aligned.m8n8.x4.trans.shared.b16 {%0,%1,%2,%3}, [%4];\n"
                 : "=r"(r0), "=r"(r1), "=r"(r2), "=r"(r3) : "r"(addr));
}
__device__ __forceinline__ void mma_f16(float* c, const uint32_t* a,
                                        uint32_t b0, uint32_t b1) {
    asm volatile(
        "mma.sync.aligned.m16n8k16.row.col.f32.f16.f16.f32 "
        "{%0,%1,%2,%3}, {%4,%5,%6,%7}, {%8,%9}, {%0,%1,%2,%3};\n"
        : "+f"(c[0]), "+f"(c[1]), "+f"(c[2]), "+f"(c[3])
        : "r"(a[0]), "r"(a[1]), "r"(a[2]), "r"(a[3]), "r"(b0), "r"(b1));
}
__device__ __forceinline__ uint32_t pack_h2(float x, float y) {
    __half2 h = __floats2half2_rn(x, y);
    return *(uint32_t*)&h;
}
__device__ __forceinline__ float fex2(float x) {
    float y;
    asm("ex2.approx.ftz.f32 %0, %1;" : "=f"(y) : "f"(x));
    return y;
}

// ---------------------------------------------------------------------------
// Single fused fp32 -> fp16 conversion for x, wq, wk, wv, wo (8 elems/thread)
// ---------------------------------------------------------------------------
#define SEG0 ((size_t)TOK * DIM)
#define SEG1 ((size_t)DIM * DIM)
#define SEG2 ((size_t)KVDIM * DIM)
#define SEG3 ((size_t)KVDIM * DIM)
#define SEG4 ((size_t)DIM * DIM)
#define CVT_TOTAL (SEG0 + SEG1 + SEG2 + SEG3 + SEG4)

__global__ void cvt_all(const float* __restrict__ x, const float* __restrict__ wq,
                        const float* __restrict__ wk, const float* __restrict__ wv,
                        const float* __restrict__ wo, __half* __restrict__ xh,
                        __half* __restrict__ wqkvh, __half* __restrict__ woh) {
    size_t i = (size_t)(blockIdx.x * blockDim.x + threadIdx.x) * 8;
    if (i >= CVT_TOTAL) return;
    const float* src;
    __half* dst;
    size_t off;
    if (i < SEG0) { src = x; dst = xh; off = i; }
    else if (i < SEG0 + SEG1) { src = wq; dst = wqkvh; off = i - SEG0; }
    else if (i < SEG0 + SEG1 + SEG2) {
        src = wk; dst = wqkvh + SEG1; off = i - SEG0 - SEG1;
    } else if (i < SEG0 + SEG1 + SEG2 + SEG3) {
        src = wv; dst = wqkvh + SEG1 + SEG2; off = i - SEG0 - SEG1 - SEG2;
    } else { src = wo; dst = woh; off = i - SEG0 - SEG1 - SEG2 - SEG3; }

    float4 v0 = *(const float4*)(src + off);
    float4 v1 = *(const float4*)(src + off + 4);
    __half2 h0 = __floats2half2_rn(v0.x, v0.y);
    __half2 h1 = __floats2half2_rn(v0.z, v0.w);
    __half2 h2 = __floats2half2_rn(v1.x, v1.y);
    __half2 h3 = __floats2half2_rn(v1.z, v1.w);
    uint4 o;
    o.x = *(uint32_t*)&h0; o.y = *(uint32_t*)&h1;
    o.z = *(uint32_t*)&h2; o.w = *(uint32_t*)&h3;
    *(uint4*)(dst + off) = o;
}

__global__ void concat_bias(const float* __restrict__ bq,
                            const float* __restrict__ bk,
                            const float* __restrict__ bv,
                            float* __restrict__ o) {
    int i = blockIdx.x * blockDim.x + threadIdx.x;
    if (i < DIM) o[i] = bq[i];
    else if (i < DIM + KVDIM) o[i] = bk[i - DIM];
    else if (i < NQKV) o[i] = bv[i - DIM - KVDIM];
}

// ---------------------------------------------------------------------------
// fp16 GEMM: C[M,N] = A[M,K] @ B[N,K]^T + bias[N]
// CTA tile 128x256x64, 8 warps (2x4), warp tile 64x64,
// m16n8k16, 2-stage cp.async double buffer (64 syncs/CTA vs 128),
// stride-72 padded smem.
// MODE 0: fp32 out (O-proj). MODE 1: fused QKV -> split fp16 out + RoPE.
// ---------------------------------------------------------------------------
#define BK 64
#define GSTR 72
#define A_STG (128 * GSTR)
#define B_STG (256 * GSTR)
#define GEMM_SMEM (2 * (A_STG + B_STG) * 2)   // 110592 bytes

template <int MODE>
__global__ __launch_bounds__(256, 1)
void h_gemm3(const __half* __restrict__ A, const __half* __restrict__ B,
             const float* __restrict__ bias, float* __restrict__ Cf,
             __half* __restrict__ Cq, __half* __restrict__ Ck,
             __half* __restrict__ Cv, const float* __restrict__ cs,
             const float* __restrict__ sn, int M, int N, int K) {
    extern __shared__ __half sh[];
    __half* As = sh;                 // [2][A_STG]
    __half* Bs = sh + 2 * A_STG;     // [2][B_STG]

    const int tid = threadIdx.x;
    const int lane = tid & 31;
    const int wid = tid >> 5;
    const int wm = wid >> 2;   // 0..1  (64 rows each)
    const int wn = wid & 3;    // 0..3  (64 cols each)
    const int bm = blockIdx.y * 128;
    const int bn = blockIdx.x * 256;
    const int lr = lane & 7;
    const int gq = lane >> 3;

    float acc[4][8][4];
#pragma unroll
    for (int mi = 0; mi < 4; mi++)
#pragma unroll
        for (int ni = 0; ni < 8; ni++)
#pragma unroll
            for (int j = 0; j < 4; j++) acc[mi][ni][j] = 0.f;

    auto g2s = [&](int k0, int stg) {
        // A: 128 rows x 8 chunks
#pragma unroll
        for (int p = 0; p < 4; p++) {
            int cid = tid + 256 * p;
            int row = cid >> 3;
            int ch = cid & 7;
            cp16(smem_u32(&As[stg * A_STG + row * GSTR + ch * 8]),
                 A + (size_t)(bm + row) * K + k0 + ch * 8);
        }
        // B: 256 rows x 8 chunks
#pragma unroll
        for (int p = 0; p < 8; p++) {
            int cid = tid + 256 * p;
            int row = cid >> 3;
            int ch = cid & 7;
            cp16(smem_u32(&Bs[stg * B_STG + row * GSTR + ch * 8]),
                 B + (size_t)(bn + row) * K + k0 + ch * 8);
        }
    };

    const int nit = K / BK;
    g2s(0, 0); CP_COMMIT;

    for (int it = 0; it < nit; it++) {
        const int buf = it & 1;
        CP_WAIT0;
        __syncthreads();
        if (it + 1 < nit) { g2s((it + 1) * BK, buf ^ 1); CP_COMMIT; }

#pragma unroll
        for (int kk2 = 0; kk2 < 4; kk2++) {
            int kk = kk2 * 16;
            uint32_t a[4][4];
#pragma unroll
            for (int mi = 0; mi < 4; mi++)
                ldsm4(a[mi][0], a[mi][1], a[mi][2], a[mi][3],
                      smem_u32(&As[buf * A_STG +
                                   (wm * 64 + mi * 16 + lr + (gq & 1) * 8) * GSTR +
                                   kk + (gq >> 1) * 8]));
#pragma unroll
            for (int nt = 0; nt < 4; nt++) {
                uint32_t b0, b1, b2, b3;
                ldsm4(b0, b1, b2, b3,
                      smem_u32(&Bs[buf * B_STG +
                                   (wn * 64 + nt * 16 + lr + (gq & 1) * 8) * GSTR +
                                   kk + (gq >> 1) * 8]));
#pragma unroll
                for (int mi = 0; mi < 4; mi++) {
                    mma_f16(acc[mi][nt * 2], a[mi], b0, b2);
                    mma_f16(acc[mi][nt * 2 + 1], a[mi], b1, b3);
                }
            }
        }
    }

    // ---- epilogue ----
    const int r0 = bm + wm * 64 + (lane >> 2);
    const int c0 = bn + wn * 64 + (lane & 3) * 2;
#pragma unroll
    for (int mi = 0; mi < 4; mi++) {
#pragma unroll
        for (int ni = 0; ni < 8; ni++) {
            int r = r0 + mi * 16;
            int c = c0 + ni * 8;
            float2 bb = *(const float2*)&bias[c];
            float v00 = acc[mi][ni][0] + bb.x, v01 = acc[mi][ni][1] + bb.y;
            float v10 = acc[mi][ni][2] + bb.x, v11 = acc[mi][ni][3] + bb.y;
            if (MODE == 0) {
                *(float2*)&Cf[(size_t)r * N + c] = make_float2(v00, v01);
                *(float2*)&Cf[(size_t)(r + 8) * N + c] = make_float2(v10, v11);
            } else {
                if (c < DIM + KVDIM) {
                    int i = (c & 127) >> 1;
                    int s0 = r & (SEQ - 1), s1 = (r + 8) & (SEQ - 1);
                    float c00 = cs[s0 * 64 + i], sn0 = sn[s0 * 64 + i];
                    float c10 = cs[s1 * 64 + i], sn1 = sn[s1 * 64 + i];
                    float a0 = v00, b0v = v01;
                    v00 = a0 * c00 - b0v * sn0;
                    v01 = a0 * sn0 + b0v * c00;
                    float a1 = v10, b1v = v11;
                    v10 = a1 * c10 - b1v * sn1;
                    v11 = a1 * sn1 + b1v * c10;
                }
                __half2 h0 = __floats2half2_rn(v00, v01);
                __half2 h1 = __floats2half2_rn(v10, v11);
                __half* dst;
                size_t str;
                int cc;
                if (c < DIM) { dst = Cq; str = DIM; cc = c; }
                else if (c < DIM + KVDIM) { dst = Ck; str = KVDIM; cc = c - DIM; }
                else { dst = Cv; str = KVDIM; cc = c - DIM - KVDIM; }
                *(__half2*)&dst[(size_t)r * str + cc] = h0;
                *(__half2*)&dst[(size_t)(r + 8) * str + cc] = h1;
            }
        }
    }
}

// ---------------------------------------------------------------------------
// Causal GQA flash attention, fp16 MMA, log2-domain softmax (ex2.approx),
// warp-uniform rescale skip. Q tile 128, KV tile 128, 8 warps.
// ---------------------------------------------------------------------------
#define FSTR 136
#define KT 128
#define FA_SMEM ((128 * FSTR + 2 * KT * FSTR + 2 * KT * FSTR) * 2)  // 174080

__global__ __launch_bounds__(256, 1)
void flash_h(const __half* __restrict__ Q, const __half* __restrict__ K,
             const __half* __restrict__ V, __half* __restrict__ O) {
    extern __shared__ __half sm[];
    __half* Qs = sm;
    __half* Ks = Qs + 128 * FSTR;
    __half* Vs = Ks + 2 * KT * FSTR;

    const int tid = threadIdx.x;
    const int lane = tid & 31;
    const int w = tid >> 5;
    const int q0 = (gridDim.x - 1 - blockIdx.x) * 128;
    const int bh = blockIdx.y;
    const int b = bh >> 5;
    const int h = bh & 31;
    const int g = h >> 2;
    const int lr = lane & 7;
    const int gq = lane >> 3;
    const int qr = lane >> 2;
    const int qc = (lane & 3) * 2;

    const __half* Qg = Q + (size_t)(b * SEQ + q0) * DIM + h * HD;
    const __half* Kg = K + (size_t)(b * SEQ) * KVDIM + g * HD;
    const __half* Vg = V + (size_t)(b * SEQ) * KVDIM + g * HD;

#pragma unroll
    for (int p = 0; p < 8; p++) {
        int cid = tid + 256 * p;
        int row = cid & 127, ch = cid >> 7;
        cp16(smem_u32(&Qs[row * FSTR + ch * 8]), Qg + (size_t)row * DIM + ch * 8);
    }
    CP_COMMIT;

    auto ldKV = [&](int kv0, int bufl) {
#pragma unroll
        for (int p = 0; p < 8; p++) {
            int cid = tid + 256 * p;
            int row = cid & 127, ch = cid >> 7;
            cp16(smem_u32(&Ks[bufl * KT * FSTR + row * FSTR + ch * 8]),
                 Kg + (size_t)(kv0 + row) * KVDIM + ch * 8);
            cp16(smem_u32(&Vs[bufl * KT * FSTR + row * FSTR + ch * 8]),
                 Vg + (size_t)(kv0 + row) * KVDIM + ch * 8);
        }
    };
    ldKV(0, 0);
    CP_COMMIT;

    float o[16][4];
#pragma unroll
    for (int nt = 0; nt < 16; nt++)
#pragma unroll
        for (int j = 0; j < 4; j++) o[nt][j] = 0.f;
    float mA = -1e30f, mB = -1e30f, lA = 0.f, lB = 0.f;
    // 1/sqrt(128) * log2(e): softmax in log2 domain -> bare EX2
    const float scale2 = 0.08838834764831845f * 1.4426950408889634f;
    const int niter = q0 / KT + 1;
    const int rA = q0 + w * 16 + qr;

    for (int it = 0; it < niter; it++) {
        const int kv0 = it * KT;
        const int buf = it & 1;
        CP_WAIT0;
        __syncthreads();
        if (it + 1 < niter) { ldKV((it + 1) * KT, buf ^ 1); CP_COMMIT; }

        float s[16][4];
#pragma unroll
        for (int nt = 0; nt < 16; nt++)
#pragma unroll
            for (int j = 0; j < 4; j++) s[nt][j] = 0.f;

#pragma unroll
        for (int ks = 0; ks < 8; ks++) {
            uint32_t a[4];
            ldsm4(a[0], a[1], a[2], a[3],
                  smem_u32(&Qs[(w * 16 + lr + (gq & 1) * 8) * FSTR +
                               ks * 16 + (gq >> 1) * 8]));
#pragma unroll
            for (int np = 0; np < 8; np++) {
                uint32_t b0, b1, b2, b3;
                ldsm4(b0, b1, b2, b3,
                      smem_u32(&Ks[buf * KT * FSTR +
                                   (np * 16 + lr + (gq & 1) * 8) * FSTR +
                                   ks * 16 + (gq >> 1) * 8]));
                mma_f16(s[np * 2], a, b0, b2);
                mma_f16(s[np * 2 + 1], a, b1, b3);
            }
        }

        const bool domask = (kv0 + KT - 1) > (q0 + w * 16);
#pragma unroll
        for (int nt = 0; nt < 16; nt++)
#pragma unroll
            for (int j = 0; j < 4; j++) {
                float v = s[nt][j] * scale2;
                if (domask) {
                    int col = kv0 + nt * 8 + qc + (j & 1);
                    int row = rA + (j >> 1) * 8;
                    if (col > row) v = -1e30f;
                }
                s[nt][j] = v;
            }

        float rmA = -1e30f, rmB = -1e30f;
#pragma unroll
        for (int nt = 0; nt < 16; nt++) {
            rmA = fmaxf(rmA, fmaxf(s[nt][0], s[nt][1]));
            rmB = fmaxf(rmB, fmaxf(s[nt][2], s[nt][3]));
        }
        rmA = fmaxf(rmA, __shfl_xor_sync(0xffffffffu, rmA, 1));
        rmA = fmaxf(rmA, __shfl_xor_sync(0xffffffffu, rmA, 2));
        rmB = fmaxf(rmB, __shfl_xor_sync(0xffffffffu, rmB, 1));
        rmB = fmaxf(rmB, __shfl_xor_sync(0xffffffffu, rmB, 2));

        float newmA = fmaxf(mA, rmA), newmB = fmaxf(mB, rmB);
        float aAl = fex2(mA - newmA), aBl = fex2(mB - newmB);
        float lsA = 0.f, lsB = 0.f;
#pragma unroll
        for (int nt = 0; nt < 16; nt++) {
            s[nt][0] = fex2(s[nt][0] - newmA);
            s[nt][1] = fex2(s[nt][1] - newmA);
            s[nt][2] = fex2(s[nt][2] - newmB);
            s[nt][3] = fex2(s[nt][3] - newmB);
            lsA += s[nt][0] + s[nt][1];
            lsB += s[nt][2] + s[nt][3];
        }
        lsA += __shfl_xor_sync(0xffffffffu, lsA, 1);
        lsA += __shfl_xor_sync(0xffffffffu, lsA, 2);
        lsB += __shfl_xor_sync(0xffffffffu, lsB, 1);
        lsB += __shfl_xor_sync(0xffffffffu, lsB, 2);
        lA = lA * aAl + lsA;
        lB = lB * aBl + lsB;
        mA = newmA;
        mB = newmB;
        // warp-uniform rescale skip (common once running max stabilizes)
        if (!__all_sync(0xffffffffu, (aAl == 1.f) & (aBl == 1.f))) {
#pragma unroll
            for (int nt = 0; nt < 16; nt++) {
                o[nt][0] *= aAl; o[nt][1] *= aAl;
                o[nt][2] *= aBl; o[nt][3] *= aBl;
            }
        }

        uint32_t pa[8][4];
#pragma unroll
        for (int t = 0; t < 8; t++) {
            pa[t][0] = pack_h2(s[2 * t][0], s[2 * t][1]);
            pa[t][1] = pack_h2(s[2 * t][2], s[2 * t][3]);
            pa[t][2] = pack_h2(s[2 * t + 1][0], s[2 * t + 1][1]);
            pa[t][3] = pack_h2(s[2 * t + 1][2], s[2 * t + 1][3]);
        }

#pragma unroll
        for (int t = 0; t < 8; t++) {
#pragma unroll
            for (int np = 0; np < 8; np++) {
                uint32_t v0, v1, v2, v3;
                ldsm4t(v0, v1, v2, v3,
                       smem_u32(&Vs[buf * KT * FSTR +
                                    (t * 16 + lr + (gq & 1) * 8) * FSTR +
                                    np * 16 + (gq >> 1) * 8]));
                mma_f16(o[np * 2], pa[t], v0, v1);
                mma_f16(o[np * 2 + 1], pa[t], v2, v3);
            }
        }
    }

    float iA = 1.f / lA, iB = 1.f / lB;
    __half* Og = O + (size_t)(b * SEQ + q0 + w * 16) * DIM + h * HD;
#pragma unroll
    for (int nt = 0; nt < 16; nt++) {
        int c = nt * 8 + qc;
        *(__half2*)&Og[(size_t)qr * DIM + c] =
            __floats2half2_rn(o[nt][0] * iA, o[nt][1] * iA);
        *(__half2*)&Og[(size_t)(qr + 8) * DIM + c] =
            __floats2half2_rn(o[nt][2] * iB, o[nt][3] * iB);
    }
}

// ---------------------------------------------------------------------------
extern "C" void kernel_launch(void* const* d_in, const int* in_sizes, int n_in,
                              void* d_out, int out_size) {
    const float* x   = (const float*)d_in[0];
    const float* fcs = (const float*)d_in[1];
    const float* fsn = (const float*)d_in[2];
    const float* wq = (const float*)d_in[4];
    const float* bq = (const float*)d_in[5];
    const float* wk = (const float*)d_in[6];
    const float* bk = (const float*)d_in[7];
    const float* wv = (const float*)d_in[8];
    const float* bv = (const float*)d_in[9];
    const float* wo = (const float*)d_in[10];
    const float* bo = (const float*)d_in[11];
    float* out = (float*)d_out;

    __half *xh, *wqkvh, *woh, *qh, *kh, *vh, *ah;
    float* bqkv;
    cudaGetSymbolAddress((void**)&xh, g_xh);
    cudaGetSymbolAddress((void**)&wqkvh, g_wqkvh);
    cudaGetSymbolAddress((void**)&woh, g_woh);
    cudaGetSymbolAddress((void**)&bqkv, g_bqkv);
    cudaGetSymbolAddress((void**)&qh, g_qh);
    cudaGetSymbolAddress((void**)&kh, g_kh);
    cudaGetSymbolAddress((void**)&vh, g_vh);
    cudaGetSymbolAddress((void**)&ah, g_ah);

    cudaFuncSetAttribute(h_gemm3<0>, cudaFuncAttributeMaxDynamicSharedMemorySize,
                         GEMM_SMEM);
    cudaFuncSetAttribute(h_gemm3<1>, cudaFuncAttributeMaxDynamicSharedMemorySize,
                         GEMM_SMEM);
    cudaFuncSetAttribute(flash_h, cudaFuncAttributeMaxDynamicSharedMemorySize,
                         FA_SMEM);

    // All fp32->fp16 conversions in one launch
    cvt_all<<<(int)((CVT_TOTAL / 8 + 255) / 256), 256>>>(
        x, wq, wk, wv, wo, xh, wqkvh, woh);
    concat_bias<<<(NQKV + 255) / 256, 256>>>(bq, bk, bv, bqkv);

    // Fused QKV projection + RoPE epilogue
    h_gemm3<1><<<dim3(NQKV / 256, TOK / 128), 256, GEMM_SMEM>>>(
        xh, wqkvh, bqkv, nullptr, qh, kh, vh, fcs, fsn, TOK, NQKV, DIM);

    // Flash attention
    flash_h<<<dim3(SEQ / 128, BSZ * NHEADS), 256, FA_SMEM>>>(qh, kh, vh, ah);

    // Output projection (fp32 out)
    h_gemm3<0><<<dim3(DIM / 256, TOK / 128), 256, GEMM_SMEM>>>(
        ah, woh, bo, out, nullptr, nullptr, nullptr, nullptr, nullptr,
        TOK, DIM, DIM);
}

// round 10
// speedup vs baseline: 10.6046x; 1.0276x over previous
#include <cuda_runtime.h>
#include <cuda_fp16.h>
#include <math.h>
#include <stdint.h>

#define DIM 4096
#define NHEADS 32
#define NKV 8
#define HD 128
#define SEQ 2048
#define BSZ 2
#define TOK (BSZ*SEQ)
#define KVDIM (NKV*HD)
#define NQKV (DIM + 2*KVDIM)   // 6144

// fp16 scratch (no cudaMalloc allowed)
__device__ __half g_xh[(size_t)TOK * DIM];
__device__ __half g_wqkvh[(size_t)NQKV * DIM];
__device__ __half g_woh[(size_t)DIM * DIM];
__device__ float  g_bqkv[NQKV];
__device__ __half g_qh[(size_t)TOK * DIM];
__device__ __half g_kh[(size_t)TOK * KVDIM];
__device__ __half g_vh[(size_t)TOK * KVDIM];
__device__ __half g_ah[(size_t)TOK * DIM];

// ---------------------------------------------------------------------------
// PTX helpers
// ---------------------------------------------------------------------------
__device__ __forceinline__ uint32_t smem_u32(const void* p) {
    return (uint32_t)__cvta_generic_to_shared(p);
}
__device__ __forceinline__ void cp16(uint32_t dst, const void* src) {
    asm volatile("cp.async.cg.shared.global [%0], [%1], 16;\n" ::"r"(dst), "l"(src));
}
#define CP_COMMIT asm volatile("cp.async.commit_group;\n" ::: "memory")
#define CP_WAIT0  asm volatile("cp.async.wait_group 0;\n" ::: "memory")

__device__ __forceinline__ void ldsm4(uint32_t& r0, uint32_t& r1, uint32_t& r2,
                                      uint32_t& r3, uint32_t addr) {
    asm volatile("ldmatrix.sync.aligned.m8n8.x4.shared.b16 {%0,%1,%2,%3}, [%4];\n"
                 : "=r"(r0), "=r"(r1), "=r"(r2), "=r"(r3) : "r"(addr));
}
__device__ __forceinline__ void ldsm4t(uint32_t& r0, uint32_t& r1, uint32_t& r2,
                                       uint32_t& r3, uint32_t addr) {
    asm volatile("ldmatrix.sync.aligned.m8n8.x4.trans.shared.b16 {%0,%1,%2,%3}, [%4];\n"
                 : "=r"(r0), "=r"(r1), "=r"(r2), "=r"(r3) : "r"(addr));
}
__device__ __forceinline__ void mma_f16(float* c, const uint32_t* a,
                                        uint32_t b0, uint32_t b1) {
    asm volatile(
        "mma.sync.aligned.m16n8k16.row.col.f32.f16.f16.f32 "
        "{%0,%1,%2,%3}, {%4,%5,%6,%7}, {%8,%9}, {%0,%1,%2,%3};\n"
        : "+f"(c[0]), "+f"(c[1]), "+f"(c[2]), "+f"(c[3])
        : "r"(a[0]), "r"(a[1]), "r"(a[2]), "r"(a[3]), "r"(b0), "r"(b1));
}
__device__ __forceinline__ uint32_t pack_h2(float x, float y) {
    __half2 h = __floats2half2_rn(x, y);
    return *(uint32_t*)&h;
}
__device__ __forceinline__ float fex2(float x) {
    float y;
    asm("ex2.approx.ftz.f32 %0, %1;" : "=f"(y) : "f"(x));
    return y;
}

// ---------------------------------------------------------------------------
// Single fused fp32 -> fp16 conversion for x, wq, wk, wv, wo (8 elems/thread)
// ---------------------------------------------------------------------------
#define SEG0 ((size_t)TOK * DIM)
#define SEG1 ((size_t)DIM * DIM)
#define SEG2 ((size_t)KVDIM * DIM)
#define SEG3 ((size_t)KVDIM * DIM)
#define SEG4 ((size_t)DIM * DIM)
#define CVT_TOTAL (SEG0 + SEG1 + SEG2 + SEG3 + SEG4)

__global__ void cvt_all(const float* __restrict__ x, const float* __restrict__ wq,
                        const float* __restrict__ wk, const float* __restrict__ wv,
                        const float* __restrict__ wo, __half* __restrict__ xh,
                        __half* __restrict__ wqkvh, __half* __restrict__ woh) {
    size_t i = (size_t)(blockIdx.x * blockDim.x + threadIdx.x) * 8;
    if (i >= CVT_TOTAL) return;
    const float* src;
    __half* dst;
    size_t off;
    if (i < SEG0) { src = x; dst = xh; off = i; }
    else if (i < SEG0 + SEG1) { src = wq; dst = wqkvh; off = i - SEG0; }
    else if (i < SEG0 + SEG1 + SEG2) {
        src = wk; dst = wqkvh + SEG1; off = i - SEG0 - SEG1;
    } else if (i < SEG0 + SEG1 + SEG2 + SEG3) {
        src = wv; dst = wqkvh + SEG1 + SEG2; off = i - SEG0 - SEG1 - SEG2;
    } else { src = wo; dst = woh; off = i - SEG0 - SEG1 - SEG2 - SEG3; }

    float4 v0 = *(const float4*)(src + off);
    float4 v1 = *(const float4*)(src + off + 4);
    __half2 h0 = __floats2half2_rn(v0.x, v0.y);
    __half2 h1 = __floats2half2_rn(v0.z, v0.w);
    __half2 h2 = __floats2half2_rn(v1.x, v1.y);
    __half2 h3 = __floats2half2_rn(v1.z, v1.w);
    uint4 o;
    o.x = *(uint32_t*)&h0; o.y = *(uint32_t*)&h1;
    o.z = *(uint32_t*)&h2; o.w = *(uint32_t*)&h3;
    *(uint4*)(dst + off) = o;
}

__global__ void concat_bias(const float* __restrict__ bq,
                            const float* __restrict__ bk,
                            const float* __restrict__ bv,
                            float* __restrict__ o) {
    int i = blockIdx.x * blockDim.x + threadIdx.x;
    if (i < DIM) o[i] = bq[i];
    else if (i < DIM + KVDIM) o[i] = bk[i - DIM];
    else if (i < NQKV) o[i] = bv[i - DIM - KVDIM];
}

// ---------------------------------------------------------------------------
// fp16 GEMM: C[M,N] = A[M,K] @ B[N,K]^T + bias[N]
// CTA tile 128x256x128, 8 warps (2x4), warp tile 64x64,
// m16n8k16, 2-stage cp.async double buffer (32 syncs/CTA for K=4096),
// stride-136 padded smem.
// MODE 0: fp32 out (O-proj). MODE 1: fused QKV -> split fp16 out + RoPE.
// ---------------------------------------------------------------------------
#define BK 128
#define GSTR 136
#define A_STG (128 * GSTR)
#define B_STG (256 * GSTR)
#define GEMM_SMEM (2 * (A_STG + B_STG) * 2)   // 208896 bytes

template <int MODE>
__global__ __launch_bounds__(256, 1)
void h_gemm3(const __half* __restrict__ A, const __half* __restrict__ B,
             const float* __restrict__ bias, float* __restrict__ Cf,
             __half* __restrict__ Cq, __half* __restrict__ Ck,
             __half* __restrict__ Cv, const float* __restrict__ cs,
             const float* __restrict__ sn, int M, int N, int K) {
    extern __shared__ __half sh[];
    __half* As = sh;                 // [2][A_STG]
    __half* Bs = sh + 2 * A_STG;     // [2][B_STG]

    const int tid = threadIdx.x;
    const int lane = tid & 31;
    const int wid = tid >> 5;
    const int wm = wid >> 2;   // 0..1  (64 rows each)
    const int wn = wid & 3;    // 0..3  (64 cols each)
    const int bm = blockIdx.y * 128;
    const int bn = blockIdx.x * 256;
    const int lr = lane & 7;
    const int gq = lane >> 3;

    float acc[4][8][4];
#pragma unroll
    for (int mi = 0; mi < 4; mi++)
#pragma unroll
        for (int ni = 0; ni < 8; ni++)
#pragma unroll
            for (int j = 0; j < 4; j++) acc[mi][ni][j] = 0.f;

    auto g2s = [&](int k0, int stg) {
        // A: 128 rows x 16 chunks = 2048
#pragma unroll
        for (int p = 0; p < 8; p++) {
            int cid = tid + 256 * p;
            int row = cid >> 4;
            int ch = cid & 15;
            cp16(smem_u32(&As[stg * A_STG + row * GSTR + ch * 8]),
                 A + (size_t)(bm + row) * K + k0 + ch * 8);
        }
        // B: 256 rows x 16 chunks = 4096
#pragma unroll
        for (int p = 0; p < 16; p++) {
            int cid = tid + 256 * p;
            int row = cid >> 4;
            int ch = cid & 15;
            cp16(smem_u32(&Bs[stg * B_STG + row * GSTR + ch * 8]),
                 B + (size_t)(bn + row) * K + k0 + ch * 8);
        }
    };

    const int nit = K / BK;
    g2s(0, 0); CP_COMMIT;

    for (int it = 0; it < nit; it++) {
        const int buf = it & 1;
        CP_WAIT0;
        __syncthreads();
        if (it + 1 < nit) { g2s((it + 1) * BK, buf ^ 1); CP_COMMIT; }

#pragma unroll
        for (int kk2 = 0; kk2 < 8; kk2++) {
            int kk = kk2 * 16;
            uint32_t a[4][4];
#pragma unroll
            for (int mi = 0; mi < 4; mi++)
                ldsm4(a[mi][0], a[mi][1], a[mi][2], a[mi][3],
                      smem_u32(&As[buf * A_STG +
                                   (wm * 64 + mi * 16 + lr + (gq & 1) * 8) * GSTR +
                                   kk + (gq >> 1) * 8]));
#pragma unroll
            for (int nt = 0; nt < 4; nt++) {
                uint32_t b0, b1, b2, b3;
                ldsm4(b0, b1, b2, b3,
                      smem_u32(&Bs[buf * B_STG +
                                   (wn * 64 + nt * 16 + lr + (gq & 1) * 8) * GSTR +
                                   kk + (gq >> 1) * 8]));
#pragma unroll
                for (int mi = 0; mi < 4; mi++) {
                    mma_f16(acc[mi][nt * 2], a[mi], b0, b2);
                    mma_f16(acc[mi][nt * 2 + 1], a[mi], b1, b3);
                }
            }
        }
    }

    // ---- epilogue ----
    const int r0 = bm + wm * 64 + (lane >> 2);
    const int c0 = bn + wn * 64 + (lane & 3) * 2;
#pragma unroll
    for (int mi = 0; mi < 4; mi++) {
#pragma unroll
        for (int ni = 0; ni < 8; ni++) {
            int r = r0 + mi * 16;
            int c = c0 + ni * 8;
            float2 bb = *(const float2*)&bias[c];
            float v00 = acc[mi][ni][0] + bb.x, v01 = acc[mi][ni][1] + bb.y;
            float v10 = acc[mi][ni][2] + bb.x, v11 = acc[mi][ni][3] + bb.y;
            if (MODE == 0) {
                *(float2*)&Cf[(size_t)r * N + c] = make_float2(v00, v01);
                *(float2*)&Cf[(size_t)(r + 8) * N + c] = make_float2(v10, v11);
            } else {
                if (c < DIM + KVDIM) {
                    int i = (c & 127) >> 1;
                    int s0 = r & (SEQ - 1), s1 = (r + 8) & (SEQ - 1);
                    float c00 = cs[s0 * 64 + i], sn0 = sn[s0 * 64 + i];
                    float c10 = cs[s1 * 64 + i], sn1 = sn[s1 * 64 + i];
                    float a0 = v00, b0v = v01;
                    v00 = a0 * c00 - b0v * sn0;
                    v01 = a0 * sn0 + b0v * c00;
                    float a1 = v10, b1v = v11;
                    v10 = a1 * c10 - b1v * sn1;
                    v11 = a1 * sn1 + b1v * c10;
                }
                __half2 h0 = __floats2half2_rn(v00, v01);
                __half2 h1 = __floats2half2_rn(v10, v11);
                __half* dst;
                size_t str;
                int cc;
                if (c < DIM) { dst = Cq; str = DIM; cc = c; }
                else if (c < DIM + KVDIM) { dst = Ck; str = KVDIM; cc = c - DIM; }
                else { dst = Cv; str = KVDIM; cc = c - DIM - KVDIM; }
                *(__half2*)&dst[(size_t)r * str + cc] = h0;
                *(__half2*)&dst[(size_t)(r + 8) * str + cc] = h1;
            }
        }
    }
}

// ---------------------------------------------------------------------------
// Causal GQA flash attention, fp16 MMA, log2-domain softmax, software-
// pipelined: QK(it+1) issued before PV(it) so PV tensor work overlaps the
// softmax ALU/EX2 chain. Q tile 128, KV tile 128, 8 warps.
// ---------------------------------------------------------------------------
#define FSTR 136
#define KT 128
#define FA_SMEM ((128 * FSTR + 2 * KT * FSTR + 2 * KT * FSTR) * 2)  // 174080

__global__ __launch_bounds__(256, 1)
void flash_h(const __half* __restrict__ Q, const __half* __restrict__ K,
             const __half* __restrict__ V, __half* __restrict__ O) {
    extern __shared__ __half sm[];
    __half* Qs = sm;
    __half* Ks = Qs + 128 * FSTR;
    __half* Vs = Ks + 2 * KT * FSTR;

    const int tid = threadIdx.x;
    const int lane = tid & 31;
    const int w = tid >> 5;
    const int q0 = (gridDim.x - 1 - blockIdx.x) * 128;
    const int bh = blockIdx.y;
    const int b = bh >> 5;
    const int h = bh & 31;
    const int g = h >> 2;
    const int lr = lane & 7;
    const int gq = lane >> 3;
    const int qr = lane >> 2;
    const int qc = (lane & 3) * 2;

    const __half* Qg = Q + (size_t)(b * SEQ + q0) * DIM + h * HD;
    const __half* Kg = K + (size_t)(b * SEQ) * KVDIM + g * HD;
    const __half* Vg = V + (size_t)(b * SEQ) * KVDIM + g * HD;

#pragma unroll
    for (int p = 0; p < 8; p++) {
        int cid = tid + 256 * p;
        int row = cid & 127, ch = cid >> 7;
        cp16(smem_u32(&Qs[row * FSTR + ch * 8]), Qg + (size_t)row * DIM + ch * 8);
    }
    CP_COMMIT;

    auto ldKV = [&](int kv0, int bufl) {
#pragma unroll
        for (int p = 0; p < 8; p++) {
            int cid = tid + 256 * p;
            int row = cid & 127, ch = cid >> 7;
            cp16(smem_u32(&Ks[bufl * KT * FSTR + row * FSTR + ch * 8]),
                 Kg + (size_t)(kv0 + row) * KVDIM + ch * 8);
            cp16(smem_u32(&Vs[bufl * KT * FSTR + row * FSTR + ch * 8]),
                 Vg + (size_t)(kv0 + row) * KVDIM + ch * 8);
        }
    };
    ldKV(0, 0);
    CP_COMMIT;

    float o[16][4];
#pragma unroll
    for (int nt = 0; nt < 16; nt++)
#pragma unroll
        for (int j = 0; j < 4; j++) o[nt][j] = 0.f;
    float mA = -1e30f, mB = -1e30f, lA = 0.f, lB = 0.f;
    uint32_t pa[8][4];
    const float scale2 = 0.08838834764831845f * 1.4426950408889634f;
    const int niter = q0 / KT + 1;
    const int rA = q0 + w * 16 + qr;

    // ---- QK into s for one tile ----
    auto qk_tile = [&](float (&s)[16][4], int bufl, int kv0) {
#pragma unroll
        for (int nt = 0; nt < 16; nt++)
#pragma unroll
            for (int j = 0; j < 4; j++) s[nt][j] = 0.f;
#pragma unroll
        for (int ks = 0; ks < 8; ks++) {
            uint32_t a[4];
            ldsm4(a[0], a[1], a[2], a[3],
                  smem_u32(&Qs[(w * 16 + lr + (gq & 1) * 8) * FSTR +
                               ks * 16 + (gq >> 1) * 8]));
#pragma unroll
            for (int np = 0; np < 8; np++) {
                uint32_t b0, b1, b2, b3;
                ldsm4(b0, b1, b2, b3,
                      smem_u32(&Ks[bufl * KT * FSTR +
                                   (np * 16 + lr + (gq & 1) * 8) * FSTR +
                                   ks * 16 + (gq >> 1) * 8]));
                mma_f16(s[np * 2], a, b0, b2);
                mma_f16(s[np * 2 + 1], a, b1, b3);
            }
        }
        const bool domask = (kv0 + KT - 1) > (q0 + w * 16);
#pragma unroll
        for (int nt = 0; nt < 16; nt++)
#pragma unroll
            for (int j = 0; j < 4; j++) {
                float v = s[nt][j] * scale2;
                if (domask) {
                    int col = kv0 + nt * 8 + qc + (j & 1);
                    int row = rA + (j >> 1) * 8;
                    if (col > row) v = -1e30f;
                }
                s[nt][j] = v;
            }
    };

    // ---- softmax of s: updates m/l, rescales o, packs pa ----
    auto softmax_tile = [&](float (&s)[16][4]) {
        float rmA = -1e30f, rmB = -1e30f;
#pragma unroll
        for (int nt = 0; nt < 16; nt++) {
            rmA = fmaxf(rmA, fmaxf(s[nt][0], s[nt][1]));
            rmB = fmaxf(rmB, fmaxf(s[nt][2], s[nt][3]));
        }
        rmA = fmaxf(rmA, __shfl_xor_sync(0xffffffffu, rmA, 1));
        rmA = fmaxf(rmA, __shfl_xor_sync(0xffffffffu, rmA, 2));
        rmB = fmaxf(rmB, __shfl_xor_sync(0xffffffffu, rmB, 1));
        rmB = fmaxf(rmB, __shfl_xor_sync(0xffffffffu, rmB, 2));

        float newmA = fmaxf(mA, rmA), newmB = fmaxf(mB, rmB);
        float aAl = fex2(mA - newmA), aBl = fex2(mB - newmB);
        float lsA = 0.f, lsB = 0.f;
#pragma unroll
        for (int nt = 0; nt < 16; nt++) {
            s[nt][0] = fex2(s[nt][0] - newmA);
            s[nt][1] = fex2(s[nt][1] - newmA);
            s[nt][2] = fex2(s[nt][2] - newmB);
            s[nt][3] = fex2(s[nt][3] - newmB);
            lsA += s[nt][0] + s[nt][1];
            lsB += s[nt][2] + s[nt][3];
        }
        lsA += __shfl_xor_sync(0xffffffffu, lsA, 1);
        lsA += __shfl_xor_sync(0xffffffffu, lsA, 2);
        lsB += __shfl_xor_sync(0xffffffffu, lsB, 1);
        lsB += __shfl_xor_sync(0xffffffffu, lsB, 2);
        lA = lA * aAl + lsA;
        lB = lB * aBl + lsB;
        mA = newmA;
        mB = newmB;
        if (!__all_sync(0xffffffffu, (aAl == 1.f) & (aBl == 1.f))) {
#pragma unroll
            for (int nt = 0; nt < 16; nt++) {
                o[nt][0] *= aAl; o[nt][1] *= aAl;
                o[nt][2] *= aBl; o[nt][3] *= aBl;
            }
        }
#pragma unroll
        for (int t = 0; t < 8; t++) {
            pa[t][0] = pack_h2(s[2 * t][0], s[2 * t][1]);
            pa[t][1] = pack_h2(s[2 * t][2], s[2 * t][3]);
            pa[t][2] = pack_h2(s[2 * t + 1][0], s[2 * t + 1][1]);
            pa[t][3] = pack_h2(s[2 * t + 1][2], s[2 * t + 1][3]);
        }
    };

    // ---- O += pa @ V(bufl) ----
    auto pv_tile = [&](int bufl) {
#pragma unroll
        for (int t = 0; t < 8; t++) {
#pragma unroll
            for (int np = 0; np < 8; np++) {
                uint32_t v0, v1, v2, v3;
                ldsm4t(v0, v1, v2, v3,
                       smem_u32(&Vs[bufl * KT * FSTR +
                                    (t * 16 + lr + (gq & 1) * 8) * FSTR +
                                    np * 16 + (gq >> 1) * 8]));
                mma_f16(o[np * 2], pa[t], v0, v1);
                mma_f16(o[np * 2 + 1], pa[t], v2, v3);
            }
        }
    };

    // ---- prologue: tile 0 QK + softmax ----
    CP_WAIT0;
    __syncthreads();
    if (niter > 1) { ldKV(KT, 1); CP_COMMIT; }
    {
        float s[16][4];
        qk_tile(s, 0, 0);
        softmax_tile(s);
    }

    // ---- pipelined mainloop ----
    for (int it = 0; it < niter; it++) {
        const int bufc = it & 1;
        const bool hn = it + 1 < niter;
        if (hn) { CP_WAIT0; __syncthreads(); }
        float s2[16][4];
        if (hn) qk_tile(s2, bufc ^ 1, (it + 1) * KT);  // tensor: next tile scores
        pv_tile(bufc);                                  // tensor: current tile PV
        if (hn) softmax_tile(s2);                       // ALU/EX2 overlaps PV above
        __syncthreads();
        if (it + 2 < niter) { ldKV((it + 2) * KT, bufc); CP_COMMIT; }
    }

    float iA = 1.f / lA, iB = 1.f / lB;
    __half* Og = O + (size_t)(b * SEQ + q0 + w * 16) * DIM + h * HD;
#pragma unroll
    for (int nt = 0; nt < 16; nt++) {
        int c = nt * 8 + qc;
        *(__half2*)&Og[(size_t)qr * DIM + c] =
            __floats2half2_rn(o[nt][0] * iA, o[nt][1] * iA);
        *(__half2*)&Og[(size_t)(qr + 8) * DIM + c] =
            __floats2half2_rn(o[nt][2] * iB, o[nt][3] * iB);
    }
}

// ---------------------------------------------------------------------------
extern "C" void kernel_launch(void* const* d_in, const int* in_sizes, int n_in,
                              void* d_out, int out_size) {
    const float* x   = (const float*)d_in[0];
    const float* fcs = (const float*)d_in[1];
    const float* fsn = (const float*)d_in[2];
    const float* wq = (const float*)d_in[4];
    const float* bq = (const float*)d_in[5];
    const float* wk = (const float*)d_in[6];
    const float* bk = (const float*)d_in[7];
    const float* wv = (const float*)d_in[8];
    const float* bv = (const float*)d_in[9];
    const float* wo = (const float*)d_in[10];
    const float* bo = (const float*)d_in[11];
    float* out = (float*)d_out;

    __half *xh, *wqkvh, *woh, *qh, *kh, *vh, *ah;
    float* bqkv;
    cudaGetSymbolAddress((void**)&xh, g_xh);
    cudaGetSymbolAddress((void**)&wqkvh, g_wqkvh);
    cudaGetSymbolAddress((void**)&woh, g_woh);
    cudaGetSymbolAddress((void**)&bqkv, g_bqkv);
    cudaGetSymbolAddress((void**)&qh, g_qh);
    cudaGetSymbolAddress((void**)&kh, g_kh);
    cudaGetSymbolAddress((void**)&vh, g_vh);
    cudaGetSymbolAddress((void**)&ah, g_ah);

    cudaFuncSetAttribute(h_gemm3<0>, cudaFuncAttributeMaxDynamicSharedMemorySize,
                         GEMM_SMEM);
    cudaFuncSetAttribute(h_gemm3<1>, cudaFuncAttributeMaxDynamicSharedMemorySize,
                         GEMM_SMEM);
    cudaFuncSetAttribute(flash_h, cudaFuncAttributeMaxDynamicSharedMemorySize,
                         FA_SMEM);

    // All fp32->fp16 conversions in one launch
    cvt_all<<<(int)((CVT_TOTAL / 8 + 255) / 256), 256>>>(
        x, wq, wk, wv, wo, xh, wqkvh, woh);
    concat_bias<<<(NQKV + 255) / 256, 256>>>(bq, bk, bv, bqkv);

    // Fused QKV projection + RoPE epilogue
    h_gemm3<1><<<dim3(NQKV / 256, TOK / 128), 256, GEMM_SMEM>>>(
        xh, wqkvh, bqkv, nullptr, qh, kh, vh, fcs, fsn, TOK, NQKV, DIM);

    // Flash attention (pipelined)
    flash_h<<<dim3(SEQ / 128, BSZ * NHEADS), 256, FA_SMEM>>>(qh, kh, vh, ah);

    // Output projection (fp32 out)
    h_gemm3<0><<<dim3(DIM / 256, TOK / 128), 256, GEMM_SMEM>>>(
        ah, woh, bo, out, nullptr, nullptr, nullptr, nullptr, nullptr,
        TOK, DIM, DIM);
}

// round 11
// speedup vs baseline: 11.4781x; 1.0824x over previous
#include <cuda_runtime.h>
#include <cuda_fp16.h>
#include <math.h>
#include <stdint.h>

#define DIM 4096
#define NHEADS 32
#define NKV 8
#define HD 128
#define SEQ 2048
#define BSZ 2
#define TOK (BSZ*SEQ)
#define KVDIM (NKV*HD)
#define NQKV (DIM + 2*KVDIM)   // 6144

// fp16 scratch (no cudaMalloc allowed)
__device__ __half g_xh[(size_t)TOK * DIM];
__device__ __half g_wqkvh[(size_t)NQKV * DIM];
__device__ __half g_woh[(size_t)DIM * DIM];
__device__ float  g_bqkv[NQKV];
__device__ __half g_qh[(size_t)TOK * DIM];
__device__ __half g_kh[(size_t)TOK * KVDIM];
__device__ __half g_vh[(size_t)TOK * KVDIM];
__device__ __half g_ah[(size_t)TOK * DIM];

// ---------------------------------------------------------------------------
// PTX helpers
// ---------------------------------------------------------------------------
__device__ __forceinline__ uint32_t smem_u32(const void* p) {
    return (uint32_t)__cvta_generic_to_shared(p);
}
__device__ __forceinline__ void cp16(uint32_t dst, const void* src) {
    asm volatile("cp.async.cg.shared.global [%0], [%1], 16;\n" ::"r"(dst), "l"(src));
}
#define CP_COMMIT asm volatile("cp.async.commit_group;\n" ::: "memory")
#define CP_WAIT0  asm volatile("cp.async.wait_group 0;\n" ::: "memory")

__device__ __forceinline__ void ldsm4(uint32_t& r0, uint32_t& r1, uint32_t& r2,
                                      uint32_t& r3, uint32_t addr) {
    asm volatile("ldmatrix.sync.aligned.m8n8.x4.shared.b16 {%0,%1,%2,%3}, [%4];\n"
                 : "=r"(r0), "=r"(r1), "=r"(r2), "=r"(r3) : "r"(addr));
}
__device__ __forceinline__ void ldsm4t(uint32_t& r0, uint32_t& r1, uint32_t& r2,
                                       uint32_t& r3, uint32_t addr) {
    asm volatile("ldmatrix.sync.aligned.m8n8.x4.trans.shared.b16 {%0,%1,%2,%3}, [%4];\n"
                 : "=r"(r0), "=r"(r1), "=r"(r2), "=r"(r3) : "r"(addr));
}
__device__ __forceinline__ void mma_f16(float* c, const uint32_t* a,
                                        uint32_t b0, uint32_t b1) {
    asm volatile(
        "mma.sync.aligned.m16n8k16.row.col.f32.f16.f16.f32 "
        "{%0,%1,%2,%3}, {%4,%5,%6,%7}, {%8,%9}, {%0,%1,%2,%3};\n"
        : "+f"(c[0]), "+f"(c[1]), "+f"(c[2]), "+f"(c[3])
        : "r"(a[0]), "r"(a[1]), "r"(a[2]), "r"(a[3]), "r"(b0), "r"(b1));
}
__device__ __forceinline__ uint32_t pack_h2(float x, float y) {
    __half2 h = __floats2half2_rn(x, y);
    return *(uint32_t*)&h;
}
__device__ __forceinline__ float fex2(float x) {
    float y;
    asm("ex2.approx.ftz.f32 %0, %1;" : "=f"(y) : "f"(x));
    return y;
}

// ---------------------------------------------------------------------------
// Single fused fp32 -> fp16 conversion for x, wq, wk, wv, wo (8 elems/thread)
// ---------------------------------------------------------------------------
#define SEG0 ((size_t)TOK * DIM)
#define SEG1 ((size_t)DIM * DIM)
#define SEG2 ((size_t)KVDIM * DIM)
#define SEG3 ((size_t)KVDIM * DIM)
#define SEG4 ((size_t)DIM * DIM)
#define CVT_TOTAL (SEG0 + SEG1 + SEG2 + SEG3 + SEG4)

__global__ void cvt_all(const float* __restrict__ x, const float* __restrict__ wq,
                        const float* __restrict__ wk, const float* __restrict__ wv,
                        const float* __restrict__ wo, __half* __restrict__ xh,
                        __half* __restrict__ wqkvh, __half* __restrict__ woh) {
    size_t i = (size_t)(blockIdx.x * blockDim.x + threadIdx.x) * 8;
    if (i >= CVT_TOTAL) return;
    const float* src;
    __half* dst;
    size_t off;
    if (i < SEG0) { src = x; dst = xh; off = i; }
    else if (i < SEG0 + SEG1) { src = wq; dst = wqkvh; off = i - SEG0; }
    else if (i < SEG0 + SEG1 + SEG2) {
        src = wk; dst = wqkvh + SEG1; off = i - SEG0 - SEG1;
    } else if (i < SEG0 + SEG1 + SEG2 + SEG3) {
        src = wv; dst = wqkvh + SEG1 + SEG2; off = i - SEG0 - SEG1 - SEG2;
    } else { src = wo; dst = woh; off = i - SEG0 - SEG1 - SEG2 - SEG3; }

    float4 v0 = *(const float4*)(src + off);
    float4 v1 = *(const float4*)(src + off + 4);
    __half2 h0 = __floats2half2_rn(v0.x, v0.y);
    __half2 h1 = __floats2half2_rn(v0.z, v0.w);
    __half2 h2 = __floats2half2_rn(v1.x, v1.y);
    __half2 h3 = __floats2half2_rn(v1.z, v1.w);
    uint4 o;
    o.x = *(uint32_t*)&h0; o.y = *(uint32_t*)&h1;
    o.z = *(uint32_t*)&h2; o.w = *(uint32_t*)&h3;
    *(uint4*)(dst + off) = o;
}

__global__ void concat_bias(const float* __restrict__ bq,
                            const float* __restrict__ bk,
                            const float* __restrict__ bv,
                            float* __restrict__ o) {
    int i = blockIdx.x * blockDim.x + threadIdx.x;
    if (i < DIM) o[i] = bq[i];
    else if (i < DIM + KVDIM) o[i] = bk[i - DIM];
    else if (i < NQKV) o[i] = bv[i - DIM - KVDIM];
}

// ---------------------------------------------------------------------------
// fp16 GEMM: C[M,N] = A[M,K] @ B[N,K]^T + bias[N]
// CTA tile 128x256x128, 8 warps (2x4), warp tile 64x64, m16n8k16,
// 2-stage cp.async double buffer, stride-136 padded smem. (R9 config)
// MODE 0: fp32 out (O-proj). MODE 1: fused QKV -> split fp16 out + RoPE.
// ---------------------------------------------------------------------------
#define BK 128
#define GSTR 136
#define A_STG (128 * GSTR)
#define B_STG (256 * GSTR)
#define GEMM_SMEM (2 * (A_STG + B_STG) * 2)   // 208896 bytes

template <int MODE>
__global__ __launch_bounds__(256, 1)
void h_gemm3(const __half* __restrict__ A, const __half* __restrict__ B,
             const float* __restrict__ bias, float* __restrict__ Cf,
             __half* __restrict__ Cq, __half* __restrict__ Ck,
             __half* __restrict__ Cv, const float* __restrict__ cs,
             const float* __restrict__ sn, int M, int N, int K) {
    extern __shared__ __half sh[];
    __half* As = sh;
    __half* Bs = sh + 2 * A_STG;

    const int tid = threadIdx.x;
    const int lane = tid & 31;
    const int wid = tid >> 5;
    const int wm = wid >> 2;
    const int wn = wid & 3;
    const int bm = blockIdx.y * 128;
    const int bn = blockIdx.x * 256;
    const int lr = lane & 7;
    const int gq = lane >> 3;

    float acc[4][8][4];
#pragma unroll
    for (int mi = 0; mi < 4; mi++)
#pragma unroll
        for (int ni = 0; ni < 8; ni++)
#pragma unroll
            for (int j = 0; j < 4; j++) acc[mi][ni][j] = 0.f;

    auto g2s = [&](int k0, int stg) {
#pragma unroll
        for (int p = 0; p < 8; p++) {
            int cid = tid + 256 * p;
            int row = cid >> 4;
            int ch = cid & 15;
            cp16(smem_u32(&As[stg * A_STG + row * GSTR + ch * 8]),
                 A + (size_t)(bm + row) * K + k0 + ch * 8);
        }
#pragma unroll
        for (int p = 0; p < 16; p++) {
            int cid = tid + 256 * p;
            int row = cid >> 4;
            int ch = cid & 15;
            cp16(smem_u32(&Bs[stg * B_STG + row * GSTR + ch * 8]),
                 B + (size_t)(bn + row) * K + k0 + ch * 8);
        }
    };

    const int nit = K / BK;
    g2s(0, 0); CP_COMMIT;

    for (int it = 0; it < nit; it++) {
        const int buf = it & 1;
        CP_WAIT0;
        __syncthreads();
        if (it + 1 < nit) { g2s((it + 1) * BK, buf ^ 1); CP_COMMIT; }

#pragma unroll
        for (int kk2 = 0; kk2 < 8; kk2++) {
            int kk = kk2 * 16;
            uint32_t a[4][4];
#pragma unroll
            for (int mi = 0; mi < 4; mi++)
                ldsm4(a[mi][0], a[mi][1], a[mi][2], a[mi][3],
                      smem_u32(&As[buf * A_STG +
                                   (wm * 64 + mi * 16 + lr + (gq & 1) * 8) * GSTR +
                                   kk + (gq >> 1) * 8]));
#pragma unroll
            for (int nt = 0; nt < 4; nt++) {
                uint32_t b0, b1, b2, b3;
                ldsm4(b0, b1, b2, b3,
                      smem_u32(&Bs[buf * B_STG +
                                   (wn * 64 + nt * 16 + lr + (gq & 1) * 8) * GSTR +
                                   kk + (gq >> 1) * 8]));
#pragma unroll
                for (int mi = 0; mi < 4; mi++) {
                    mma_f16(acc[mi][nt * 2], a[mi], b0, b2);
                    mma_f16(acc[mi][nt * 2 + 1], a[mi], b1, b3);
                }
            }
        }
    }

    const int r0 = bm + wm * 64 + (lane >> 2);
    const int c0 = bn + wn * 64 + (lane & 3) * 2;
#pragma unroll
    for (int mi = 0; mi < 4; mi++) {
#pragma unroll
        for (int ni = 0; ni < 8; ni++) {
            int r = r0 + mi * 16;
            int c = c0 + ni * 8;
            float2 bb = *(const float2*)&bias[c];
            float v00 = acc[mi][ni][0] + bb.x, v01 = acc[mi][ni][1] + bb.y;
            float v10 = acc[mi][ni][2] + bb.x, v11 = acc[mi][ni][3] + bb.y;
            if (MODE == 0) {
                *(float2*)&Cf[(size_t)r * N + c] = make_float2(v00, v01);
                *(float2*)&Cf[(size_t)(r + 8) * N + c] = make_float2(v10, v11);
            } else {
                if (c < DIM + KVDIM) {
                    int i = (c & 127) >> 1;
                    int s0 = r & (SEQ - 1), s1 = (r + 8) & (SEQ - 1);
                    float c00 = cs[s0 * 64 + i], sn0 = sn[s0 * 64 + i];
                    float c10 = cs[s1 * 64 + i], sn1 = sn[s1 * 64 + i];
                    float a0 = v00, b0v = v01;
                    v00 = a0 * c00 - b0v * sn0;
                    v01 = a0 * sn0 + b0v * c00;
                    float a1 = v10, b1v = v11;
                    v10 = a1 * c10 - b1v * sn1;
                    v11 = a1 * sn1 + b1v * c10;
                }
                __half2 h0 = __floats2half2_rn(v00, v01);
                __half2 h1 = __floats2half2_rn(v10, v11);
                __half* dst;
                size_t str;
                int cc;
                if (c < DIM) { dst = Cq; str = DIM; cc = c; }
                else if (c < DIM + KVDIM) { dst = Ck; str = KVDIM; cc = c - DIM; }
                else { dst = Cv; str = KVDIM; cc = c - DIM - KVDIM; }
                *(__half2*)&dst[(size_t)r * str + cc] = h0;
                *(__half2*)&dst[(size_t)(r + 8) * str + cc] = h1;
            }
        }
    }
}

// ---------------------------------------------------------------------------
// Causal GQA flash attention, fp16 MMA, log2-domain softmax.
// QT=64, KT=64, 128 threads (4 warps), 87KB smem -> 2 CTAs/SM:
// two independent CTAs per SM desynchronize softmax vs MMA phases.
// ---------------------------------------------------------------------------
#define FSTR 136
#define QT 64
#define KT 64
#define FA_SMEM ((QT * FSTR + 2 * KT * FSTR + 2 * KT * FSTR) * 2)  // 87040

__global__ __launch_bounds__(128, 2)
void flash_h(const __half* __restrict__ Q, const __half* __restrict__ K,
             const __half* __restrict__ V, __half* __restrict__ O) {
    extern __shared__ __half sm[];
    __half* Qs = sm;                      // [64][136]
    __half* Ks = Qs + QT * FSTR;          // [2][64][136]
    __half* Vs = Ks + 2 * KT * FSTR;      // [2][64][136]

    const int tid = threadIdx.x;
    const int lane = tid & 31;
    const int w = tid >> 5;               // 0..3
    const int q0 = (gridDim.x - 1 - blockIdx.x) * QT;  // heavy blocks first
    const int bh = blockIdx.y;
    const int b = bh >> 5;
    const int h = bh & 31;
    const int g = h >> 2;
    const int lr = lane & 7;
    const int gq = lane >> 3;
    const int qr = lane >> 2;
    const int qc = (lane & 3) * 2;

    const __half* Qg = Q + (size_t)(b * SEQ + q0) * DIM + h * HD;
    const __half* Kg = K + (size_t)(b * SEQ) * KVDIM + g * HD;
    const __half* Vg = V + (size_t)(b * SEQ) * KVDIM + g * HD;

    // load Q tile: 64 rows x 16 chunks = 1024 chunks / 128 thr
#pragma unroll
    for (int p = 0; p < 8; p++) {
        int cid = tid + 128 * p;
        int row = cid >> 4, ch = cid & 15;
        cp16(smem_u32(&Qs[row * FSTR + ch * 8]), Qg + (size_t)row * DIM + ch * 8);
    }
    CP_COMMIT;

    auto ldKV = [&](int kv0, int bufl) {
#pragma unroll
        for (int p = 0; p < 8; p++) {
            int cid = tid + 128 * p;
            int row = cid >> 4, ch = cid & 15;
            cp16(smem_u32(&Ks[bufl * KT * FSTR + row * FSTR + ch * 8]),
                 Kg + (size_t)(kv0 + row) * KVDIM + ch * 8);
            cp16(smem_u32(&Vs[bufl * KT * FSTR + row * FSTR + ch * 8]),
                 Vg + (size_t)(kv0 + row) * KVDIM + ch * 8);
        }
    };
    ldKV(0, 0);
    CP_COMMIT;

    float o[16][4];
#pragma unroll
    for (int nt = 0; nt < 16; nt++)
#pragma unroll
        for (int j = 0; j < 4; j++) o[nt][j] = 0.f;
    float mA = -1e30f, mB = -1e30f, lA = 0.f, lB = 0.f;
    const float scale2 = 0.08838834764831845f * 1.4426950408889634f;
    const int niter = q0 / KT + 1;
    const int rA = q0 + w * 16 + qr;

    for (int it = 0; it < niter; it++) {
        const int kv0 = it * KT;
        const int buf = it & 1;
        CP_WAIT0;
        __syncthreads();
        if (it + 1 < niter) { ldKV((it + 1) * KT, buf ^ 1); CP_COMMIT; }

        // ---- S = Q @ K^T (8 n-tiles of 8 cols) ----
        float s[8][4];
#pragma unroll
        for (int nt = 0; nt < 8; nt++)
#pragma unroll
            for (int j = 0; j < 4; j++) s[nt][j] = 0.f;

#pragma unroll
        for (int ks = 0; ks < 8; ks++) {
            uint32_t a[4];
            ldsm4(a[0], a[1], a[2], a[3],
                  smem_u32(&Qs[(w * 16 + lr + (gq & 1) * 8) * FSTR +
                               ks * 16 + (gq >> 1) * 8]));
#pragma unroll
            for (int np = 0; np < 4; np++) {
                uint32_t b0, b1, b2, b3;
                ldsm4(b0, b1, b2, b3,
                      smem_u32(&Ks[buf * KT * FSTR +
                                   (np * 16 + lr + (gq & 1) * 8) * FSTR +
                                   ks * 16 + (gq >> 1) * 8]));
                mma_f16(s[np * 2], a, b0, b2);
                mma_f16(s[np * 2 + 1], a, b1, b3);
            }
        }

        const bool domask = (kv0 + KT - 1) > (q0 + w * 16);
#pragma unroll
        for (int nt = 0; nt < 8; nt++)
#pragma unroll
            for (int j = 0; j < 4; j++) {
                float v = s[nt][j] * scale2;
                if (domask) {
                    int col = kv0 + nt * 8 + qc + (j & 1);
                    int row = rA + (j >> 1) * 8;
                    if (col > row) v = -1e30f;
                }
                s[nt][j] = v;
            }

        float rmA = -1e30f, rmB = -1e30f;
#pragma unroll
        for (int nt = 0; nt < 8; nt++) {
            rmA = fmaxf(rmA, fmaxf(s[nt][0], s[nt][1]));
            rmB = fmaxf(rmB, fmaxf(s[nt][2], s[nt][3]));
        }
        rmA = fmaxf(rmA, __shfl_xor_sync(0xffffffffu, rmA, 1));
        rmA = fmaxf(rmA, __shfl_xor_sync(0xffffffffu, rmA, 2));
        rmB = fmaxf(rmB, __shfl_xor_sync(0xffffffffu, rmB, 1));
        rmB = fmaxf(rmB, __shfl_xor_sync(0xffffffffu, rmB, 2));

        float newmA = fmaxf(mA, rmA), newmB = fmaxf(mB, rmB);
        float aAl = fex2(mA - newmA), aBl = fex2(mB - newmB);
        float lsA = 0.f, lsB = 0.f;
#pragma unroll
        for (int nt = 0; nt < 8; nt++) {
            s[nt][0] = fex2(s[nt][0] - newmA);
            s[nt][1] = fex2(s[nt][1] - newmA);
            s[nt][2] = fex2(s[nt][2] - newmB);
            s[nt][3] = fex2(s[nt][3] - newmB);
            lsA += s[nt][0] + s[nt][1];
            lsB += s[nt][2] + s[nt][3];
        }
        lsA += __shfl_xor_sync(0xffffffffu, lsA, 1);
        lsA += __shfl_xor_sync(0xffffffffu, lsA, 2);
        lsB += __shfl_xor_sync(0xffffffffu, lsB, 1);
        lsB += __shfl_xor_sync(0xffffffffu, lsB, 2);
        lA = lA * aAl + lsA;
        lB = lB * aBl + lsB;
        mA = newmA;
        mB = newmB;
        if (!__all_sync(0xffffffffu, (aAl == 1.f) & (aBl == 1.f))) {
#pragma unroll
            for (int nt = 0; nt < 16; nt++) {
                o[nt][0] *= aAl; o[nt][1] *= aAl;
                o[nt][2] *= aBl; o[nt][3] *= aBl;
            }
        }

        uint32_t pa[4][4];
#pragma unroll
        for (int t = 0; t < 4; t++) {
            pa[t][0] = pack_h2(s[2 * t][0], s[2 * t][1]);
            pa[t][1] = pack_h2(s[2 * t][2], s[2 * t][3]);
            pa[t][2] = pack_h2(s[2 * t + 1][0], s[2 * t + 1][1]);
            pa[t][3] = pack_h2(s[2 * t + 1][2], s[2 * t + 1][3]);
        }

#pragma unroll
        for (int t = 0; t < 4; t++) {
#pragma unroll
            for (int np = 0; np < 8; np++) {
                uint32_t v0, v1, v2, v3;
                ldsm4t(v0, v1, v2, v3,
                       smem_u32(&Vs[buf * KT * FSTR +
                                    (t * 16 + lr + (gq & 1) * 8) * FSTR +
                                    np * 16 + (gq >> 1) * 8]));
                mma_f16(o[np * 2], pa[t], v0, v1);
                mma_f16(o[np * 2 + 1], pa[t], v2, v3);
            }
        }
    }

    float iA = 1.f / lA, iB = 1.f / lB;
    __half* Og = O + (size_t)(b * SEQ + q0 + w * 16) * DIM + h * HD;
#pragma unroll
    for (int nt = 0; nt < 16; nt++) {
        int c = nt * 8 + qc;
        *(__half2*)&Og[(size_t)qr * DIM + c] =
            __floats2half2_rn(o[nt][0] * iA, o[nt][1] * iA);
        *(__half2*)&Og[(size_t)(qr + 8) * DIM + c] =
            __floats2half2_rn(o[nt][2] * iB, o[nt][3] * iB);
    }
}

// ---------------------------------------------------------------------------
extern "C" void kernel_launch(void* const* d_in, const int* in_sizes, int n_in,
                              void* d_out, int out_size) {
    const float* x   = (const float*)d_in[0];
    const float* fcs = (const float*)d_in[1];
    const float* fsn = (const float*)d_in[2];
    const float* wq = (const float*)d_in[4];
    const float* bq = (const float*)d_in[5];
    const float* wk = (const float*)d_in[6];
    const float* bk = (const float*)d_in[7];
    const float* wv = (const float*)d_in[8];
    const float* bv = (const float*)d_in[9];
    const float* wo = (const float*)d_in[10];
    const float* bo = (const float*)d_in[11];
    float* out = (float*)d_out;

    __half *xh, *wqkvh, *woh, *qh, *kh, *vh, *ah;
    float* bqkv;
    cudaGetSymbolAddress((void**)&xh, g_xh);
    cudaGetSymbolAddress((void**)&wqkvh, g_wqkvh);
    cudaGetSymbolAddress((void**)&woh, g_woh);
    cudaGetSymbolAddress((void**)&bqkv, g_bqkv);
    cudaGetSymbolAddress((void**)&qh, g_qh);
    cudaGetSymbolAddress((void**)&kh, g_kh);
    cudaGetSymbolAddress((void**)&vh, g_vh);
    cudaGetSymbolAddress((void**)&ah, g_ah);

    cudaFuncSetAttribute(h_gemm3<0>, cudaFuncAttributeMaxDynamicSharedMemorySize,
                         GEMM_SMEM);
    cudaFuncSetAttribute(h_gemm3<1>, cudaFuncAttributeMaxDynamicSharedMemorySize,
                         GEMM_SMEM);
    cudaFuncSetAttribute(flash_h, cudaFuncAttributeMaxDynamicSharedMemorySize,
                         FA_SMEM);

    // All fp32->fp16 conversions in one launch
    cvt_all<<<(int)((CVT_TOTAL / 8 + 255) / 256), 256>>>(
        x, wq, wk, wv, wo, xh, wqkvh, woh);
    concat_bias<<<(NQKV + 255) / 256, 256>>>(bq, bk, bv, bqkv);

    // Fused QKV projection + RoPE epilogue
    h_gemm3<1><<<dim3(NQKV / 256, TOK / 128), 256, GEMM_SMEM>>>(
        xh, wqkvh, bqkv, nullptr, qh, kh, vh, fcs, fsn, TOK, NQKV, DIM);

    // Flash attention (QT=64, 2 CTAs/SM)
    flash_h<<<dim3(SEQ / QT, BSZ * NHEADS), 128, FA_SMEM>>>(qh, kh, vh, ah);

    // Output projection (fp32 out)
    h_gemm3<0><<<dim3(DIM / 256, TOK / 128), 256, GEMM_SMEM>>>(
        ah, woh, bo, out, nullptr, nullptr, nullptr, nullptr, nullptr,
        TOK, DIM, DIM);
}

// round 13
// speedup vs baseline: 11.5344x; 1.0049x over previous
#include <cuda_runtime.h>
#include <cuda_fp16.h>
#include <math.h>
#include <stdint.h>

#define DIM 4096
#define NHEADS 32
#define NKV 8
#define HD 128
#define SEQ 2048
#define BSZ 2
#define TOK (BSZ*SEQ)
#define KVDIM (NKV*HD)
#define NQKV (DIM + 2*KVDIM)   // 6144

// fp16 scratch (no cudaMalloc allowed)
__device__ __half g_xh[(size_t)TOK * DIM];
__device__ __half g_wqkvh[(size_t)NQKV * DIM];
__device__ __half g_woh[(size_t)DIM * DIM];
__device__ float  g_bqkv[NQKV];
__device__ __half g_qh[(size_t)TOK * DIM];
__device__ __half g_kh[(size_t)TOK * KVDIM];
__device__ __half g_vh[(size_t)TOK * KVDIM];
__device__ __half g_ah[(size_t)TOK * DIM];

// ---------------------------------------------------------------------------
// PTX helpers
// ---------------------------------------------------------------------------
__device__ __forceinline__ uint32_t smem_u32(const void* p) {
    return (uint32_t)__cvta_generic_to_shared(p);
}
__device__ __forceinline__ void cp16(uint32_t dst, const void* src) {
    asm volatile("cp.async.cg.shared.global [%0], [%1], 16;\n" ::"r"(dst), "l"(src));
}
#define CP_COMMIT asm volatile("cp.async.commit_group;\n" ::: "memory")
#define CP_WAIT0  asm volatile("cp.async.wait_group 0;\n" ::: "memory")
#define CP_WAIT1  asm volatile("cp.async.wait_group 1;\n" ::: "memory")

__device__ __forceinline__ void ldsm4(uint32_t& r0, uint32_t& r1, uint32_t& r2,
                                      uint32_t& r3, uint32_t addr) {
    asm volatile("ldmatrix.sync.aligned.m8n8.x4.shared.b16 {%0,%1,%2,%3}, [%4];\n"
                 : "=r"(r0), "=r"(r1), "=r"(r2), "=r"(r3) : "r"(addr));
}
__device__ __forceinline__ void ldsm4t(uint32_t& r0, uint32_t& r1, uint32_t& r2,
                                       uint32_t& r3, uint32_t addr) {
    asm volatile("ldmatrix.sync.aligned.m8n8.x4.trans.shared.b16 {%0,%1,%2,%3}, [%4];\n"
                 : "=r"(r0), "=r"(r1), "=r"(r2), "=r"(r3) : "r"(addr));
}
__device__ __forceinline__ void mma_f16(float* c, const uint32_t* a,
                                        uint32_t b0, uint32_t b1) {
    asm volatile(
        "mma.sync.aligned.m16n8k16.row.col.f32.f16.f16.f32 "
        "{%0,%1,%2,%3}, {%4,%5,%6,%7}, {%8,%9}, {%0,%1,%2,%3};\n"
        : "+f"(c[0]), "+f"(c[1]), "+f"(c[2]), "+f"(c[3])
        : "r"(a[0]), "r"(a[1]), "r"(a[2]), "r"(a[3]), "r"(b0), "r"(b1));
}
__device__ __forceinline__ uint32_t pack_h2(float x, float y) {
    __half2 h = __floats2half2_rn(x, y);
    return *(uint32_t*)&h;
}
__device__ __forceinline__ float fex2(float x) {
    float y;
    asm("ex2.approx.ftz.f32 %0, %1;" : "=f"(y) : "f"(x));
    return y;
}

// ---------------------------------------------------------------------------
// fp32 -> fp16 conversion, 16 elems/thread (4 independent LDG.128, MLP=4)
// ---------------------------------------------------------------------------
__global__ void f2h16(const float* __restrict__ in, __half* __restrict__ out,
                      int n) {
    int i = (blockIdx.x * blockDim.x + threadIdx.x) * 16;
    if (i >= n) return;
    float4 v[4];
#pragma unroll
    for (int j = 0; j < 4; j++) v[j] = *(const float4*)(in + i + j * 4);
#pragma unroll
    for (int j = 0; j < 2; j++) {
        __half2 a = __floats2half2_rn(v[2*j].x, v[2*j].y);
        __half2 b = __floats2half2_rn(v[2*j].z, v[2*j].w);
        __half2 c = __floats2half2_rn(v[2*j+1].x, v[2*j+1].y);
        __half2 d = __floats2half2_rn(v[2*j+1].z, v[2*j+1].w);
        uint4 o;
        o.x = *(uint32_t*)&a; o.y = *(uint32_t*)&b;
        o.z = *(uint32_t*)&c; o.w = *(uint32_t*)&d;
        *(uint4*)(out + i + j * 8) = o;
    }
}

__global__ void concat_bias(const float* __restrict__ bq,
                            const float* __restrict__ bk,
                            const float* __restrict__ bv,
                            float* __restrict__ o) {
    int i = blockIdx.x * blockDim.x + threadIdx.x;
    if (i < DIM) o[i] = bq[i];
    else if (i < DIM + KVDIM) o[i] = bk[i - DIM];
    else if (i < NQKV) o[i] = bv[i - DIM - KVDIM];
}

// ---------------------------------------------------------------------------
// fp16 GEMM: C[M,N] = A[M,K] @ B[N,K]^T + bias[N]
// CTA tile 128x256x128, 8 warps (2x4), warp tile 64x64, m16n8k16,
// 2-stage cp.async double buffer, stride-136 padded smem. (At the
// ~512 MAC/cyc/SM HMMA ceiling — unchanged.)
// ---------------------------------------------------------------------------
#define BK 128
#define GSTR 136
#define A_STG (128 * GSTR)
#define B_STG (256 * GSTR)
#define GEMM_SMEM (2 * (A_STG + B_STG) * 2)   // 208896 bytes

template <int MODE>
__global__ __launch_bounds__(256, 1)
void h_gemm3(const __half* __restrict__ A, const __half* __restrict__ B,
             const float* __restrict__ bias, float* __restrict__ Cf,
             __half* __restrict__ Cq, __half* __restrict__ Ck,
             __half* __restrict__ Cv, const float* __restrict__ cs,
             const float* __restrict__ sn, int M, int N, int K) {
    extern __shared__ __half sh[];
    __half* As = sh;
    __half* Bs = sh + 2 * A_STG;

    const int tid = threadIdx.x;
    const int lane = tid & 31;
    const int wid = tid >> 5;
    const int wm = wid >> 2;
    const int wn = wid & 3;
    const int bm = blockIdx.y * 128;
    const int bn = blockIdx.x * 256;
    const int lr = lane & 7;
    const int gq = lane >> 3;

    float acc[4][8][4];
#pragma unroll
    for (int mi = 0; mi < 4; mi++)
#pragma unroll
        for (int ni = 0; ni < 8; ni++)
#pragma unroll
            for (int j = 0; j < 4; j++) acc[mi][ni][j] = 0.f;

    auto g2s = [&](int k0, int stg) {
#pragma unroll
        for (int p = 0; p < 8; p++) {
            int cid = tid + 256 * p;
            int row = cid >> 4;
            int ch = cid & 15;
            cp16(smem_u32(&As[stg * A_STG + row * GSTR + ch * 8]),
                 A + (size_t)(bm + row) * K + k0 + ch * 8);
        }
#pragma unroll
        for (int p = 0; p < 16; p++) {
            int cid = tid + 256 * p;
            int row = cid >> 4;
            int ch = cid & 15;
            cp16(smem_u32(&Bs[stg * B_STG + row * GSTR + ch * 8]),
                 B + (size_t)(bn + row) * K + k0 + ch * 8);
        }
    };

    const int nit = K / BK;
    g2s(0, 0); CP_COMMIT;

    for (int it = 0; it < nit; it++) {
        const int buf = it & 1;
        CP_WAIT0;
        __syncthreads();
        if (it + 1 < nit) { g2s((it + 1) * BK, buf ^ 1); CP_COMMIT; }

#pragma unroll
        for (int kk2 = 0; kk2 < 8; kk2++) {
            int kk = kk2 * 16;
            uint32_t a[4][4];
#pragma unroll
            for (int mi = 0; mi < 4; mi++)
                ldsm4(a[mi][0], a[mi][1], a[mi][2], a[mi][3],
                      smem_u32(&As[buf * A_STG +
                                   (wm * 64 + mi * 16 + lr + (gq & 1) * 8) * GSTR +
                                   kk + (gq >> 1) * 8]));
#pragma unroll
            for (int nt = 0; nt < 4; nt++) {
                uint32_t b0, b1, b2, b3;
                ldsm4(b0, b1, b2, b3,
                      smem_u32(&Bs[buf * B_STG +
                                   (wn * 64 + nt * 16 + lr + (gq & 1) * 8) * GSTR +
                                   kk + (gq >> 1) * 8]));
#pragma unroll
                for (int mi = 0; mi < 4; mi++) {
                    mma_f16(acc[mi][nt * 2], a[mi], b0, b2);
                    mma_f16(acc[mi][nt * 2 + 1], a[mi], b1, b3);
                }
            }
        }
    }

    const int r0 = bm + wm * 64 + (lane >> 2);
    const int c0 = bn + wn * 64 + (lane & 3) * 2;
#pragma unroll
    for (int mi = 0; mi < 4; mi++) {
#pragma unroll
        for (int ni = 0; ni < 8; ni++) {
            int r = r0 + mi * 16;
            int c = c0 + ni * 8;
            float2 bb = *(const float2*)&bias[c];
            float v00 = acc[mi][ni][0] + bb.x, v01 = acc[mi][ni][1] + bb.y;
            float v10 = acc[mi][ni][2] + bb.x, v11 = acc[mi][ni][3] + bb.y;
            if (MODE == 0) {
                *(float2*)&Cf[(size_t)r * N + c] = make_float2(v00, v01);
                *(float2*)&Cf[(size_t)(r + 8) * N + c] = make_float2(v10, v11);
            } else {
                if (c < DIM + KVDIM) {
                    int i = (c & 127) >> 1;
                    int s0 = r & (SEQ - 1), s1 = (r + 8) & (SEQ - 1);
                    float c00 = cs[s0 * 64 + i], sn0 = sn[s0 * 64 + i];
                    float c10 = cs[s1 * 64 + i], sn1 = sn[s1 * 64 + i];
                    float a0 = v00, b0v = v01;
                    v00 = a0 * c00 - b0v * sn0;
                    v01 = a0 * sn0 + b0v * c00;
                    float a1 = v10, b1v = v11;
                    v10 = a1 * c10 - b1v * sn1;
                    v11 = a1 * sn1 + b1v * c10;
                }
                __half2 h0 = __floats2half2_rn(v00, v01);
                __half2 h1 = __floats2half2_rn(v10, v11);
                __half* dst;
                size_t str;
                int cc;
                if (c < DIM) { dst = Cq; str = DIM; cc = c; }
                else if (c < DIM + KVDIM) { dst = Ck; str = KVDIM; cc = c - DIM; }
                else { dst = Cv; str = KVDIM; cc = c - DIM - KVDIM; }
                *(__half2*)&dst[(size_t)r * str + cc] = h0;
                *(__half2*)&dst[(size_t)(r + 8) * str + cc] = h1;
            }
        }
    }
}

// ---------------------------------------------------------------------------
// Causal GQA flash attention, fp16 MMA, log2-domain softmax.
// QT=64, KT=64, 128 threads. K double-buffered, V SINGLE-buffered (issued
// after the post-PV sync, lands during next iter's QK+softmax) ->
// 68KB smem -> 3 CTAs/SM.
// FIX vs R11: ldK/ldV each issue 8x128 = 1024 cp16s (full 64x16-chunk tile).
// ---------------------------------------------------------------------------
#define FSTR 136
#define QT 64
#define KT 64
#define FA_SMEM ((QT * FSTR + 2 * KT * FSTR + KT * FSTR) * 2)  // 69632

__global__ __launch_bounds__(128, 3)
void flash_h(const __half* __restrict__ Q, const __half* __restrict__ K,
             const __half* __restrict__ V, __half* __restrict__ O) {
    extern __shared__ __half sm[];
    __half* Qs = sm;                      // [64][136]
    __half* Ks = Qs + QT * FSTR;          // [2][64][136]
    __half* Vs = Ks + 2 * KT * FSTR;      // [64][136] single buffer

    const int tid = threadIdx.x;
    const int lane = tid & 31;
    const int w = tid >> 5;               // 0..3
    const int q0 = (gridDim.x - 1 - blockIdx.x) * QT;  // heavy blocks first
    const int bh = blockIdx.y;
    const int b = bh >> 5;
    const int h = bh & 31;
    const int g = h >> 2;
    const int lr = lane & 7;
    const int gq = lane >> 3;
    const int qr = lane >> 2;
    const int qc = (lane & 3) * 2;

    const __half* Qg = Q + (size_t)(b * SEQ + q0) * DIM + h * HD;
    const __half* Kg = K + (size_t)(b * SEQ) * KVDIM + g * HD;
    const __half* Vg = V + (size_t)(b * SEQ) * KVDIM + g * HD;

    // load Q tile (grouped with the first K commit)
#pragma unroll
    for (int p = 0; p < 8; p++) {
        int cid = tid + 128 * p;
        int row = cid >> 4, ch = cid & 15;
        cp16(smem_u32(&Qs[row * FSTR + ch * 8]), Qg + (size_t)row * DIM + ch * 8);
    }

    auto ldK = [&](int kv0, int bufl) {
#pragma unroll
        for (int p = 0; p < 8; p++) {
            int cid = tid + 128 * p;
            int row = cid >> 4, ch = cid & 15;
            cp16(smem_u32(&Ks[bufl * KT * FSTR + row * FSTR + ch * 8]),
                 Kg + (size_t)(kv0 + row) * KVDIM + ch * 8);
        }
    };
    auto ldV = [&](int kv0) {
#pragma unroll
        for (int p = 0; p < 8; p++) {
            int cid = tid + 128 * p;
            int row = cid >> 4, ch = cid & 15;
            cp16(smem_u32(&Vs[row * FSTR + ch * 8]),
                 Vg + (size_t)(kv0 + row) * KVDIM + ch * 8);
        }
    };

    // Prologue: group0 = {Q, K(0)}, group1 = {V(0)}
    ldK(0, 0); CP_COMMIT;
    ldV(0);    CP_COMMIT;

    float o[16][4];
#pragma unroll
    for (int nt = 0; nt < 16; nt++)
#pragma unroll
        for (int j = 0; j < 4; j++) o[nt][j] = 0.f;
    float mA = -1e30f, mB = -1e30f, lA = 0.f, lB = 0.f;
    const float scale2 = 0.08838834764831845f * 1.4426950408889634f;
    const int niter = q0 / KT + 1;
    const int rA = q0 + w * 16 + qr;

    for (int it = 0; it < niter; it++) {
        const int kv0 = it * KT;
        const int buf = it & 1;
        const bool hn = it + 1 < niter;

        // K(it) (and Q) ready; V(it) may still be in flight
        CP_WAIT1;
        __syncthreads();

        // ---- S = Q @ K^T ----
        float s[8][4];
#pragma unroll
        for (int nt = 0; nt < 8; nt++)
#pragma unroll
            for (int j = 0; j < 4; j++) s[nt][j] = 0.f;

#pragma unroll
        for (int ks = 0; ks < 8; ks++) {
            uint32_t a[4];
            ldsm4(a[0], a[1], a[2], a[3],
                  smem_u32(&Qs[(w * 16 + lr + (gq & 1) * 8) * FSTR +
                               ks * 16 + (gq >> 1) * 8]));
#pragma unroll
            for (int np = 0; np < 4; np++) {
                uint32_t b0, b1, b2, b3;
                ldsm4(b0, b1, b2, b3,
                      smem_u32(&Ks[buf * KT * FSTR +
                                   (np * 16 + lr + (gq & 1) * 8) * FSTR +
                                   ks * 16 + (gq >> 1) * 8]));
                mma_f16(s[np * 2], a, b0, b2);
                mma_f16(s[np * 2 + 1], a, b1, b3);
            }
        }

        // prefetch K(it+1) into the other K buffer
        if (hn) { ldK((it + 1) * KT, buf ^ 1); CP_COMMIT; }

        // ---- scale + causal mask ----
        const bool domask = (kv0 + KT - 1) > (q0 + w * 16);
#pragma unroll
        for (int nt = 0; nt < 8; nt++)
#pragma unroll
            for (int j = 0; j < 4; j++) {
                float v = s[nt][j] * scale2;
                if (domask) {
                    int col = kv0 + nt * 8 + qc + (j & 1);
                    int row = rA + (j >> 1) * 8;
                    if (col > row) v = -1e30f;
                }
                s[nt][j] = v;
            }

        // ---- online softmax ----
        float rmA = -1e30f, rmB = -1e30f;
#pragma unroll
        for (int nt = 0; nt < 8; nt++) {
            rmA = fmaxf(rmA, fmaxf(s[nt][0], s[nt][1]));
            rmB = fmaxf(rmB, fmaxf(s[nt][2], s[nt][3]));
        }
        rmA = fmaxf(rmA, __shfl_xor_sync(0xffffffffu, rmA, 1));
        rmA = fmaxf(rmA, __shfl_xor_sync(0xffffffffu, rmA, 2));
        rmB = fmaxf(rmB, __shfl_xor_sync(0xffffffffu, rmB, 1));
        rmB = fmaxf(rmB, __shfl_xor_sync(0xffffffffu, rmB, 2));

        float newmA = fmaxf(mA, rmA), newmB = fmaxf(mB, rmB);
        float aAl = fex2(mA - newmA), aBl = fex2(mB - newmB);
        float lsA = 0.f, lsB = 0.f;
#pragma unroll
        for (int nt = 0; nt < 8; nt++) {
            s[nt][0] = fex2(s[nt][0] - newmA);
            s[nt][1] = fex2(s[nt][1] - newmA);
            s[nt][2] = fex2(s[nt][2] - newmB);
            s[nt][3] = fex2(s[nt][3] - newmB);
            lsA += s[nt][0] + s[nt][1];
            lsB += s[nt][2] + s[nt][3];
        }
        lsA += __shfl_xor_sync(0xffffffffu, lsA, 1);
        lsA += __shfl_xor_sync(0xffffffffu, lsA, 2);
        lsB += __shfl_xor_sync(0xffffffffu, lsB, 1);
        lsB += __shfl_xor_sync(0xffffffffu, lsB, 2);
        lA = lA * aAl + lsA;
        lB = lB * aBl + lsB;
        mA = newmA;
        mB = newmB;
        if (!__all_sync(0xffffffffu, (aAl == 1.f) & (aBl == 1.f))) {
#pragma unroll
            for (int nt = 0; nt < 16; nt++) {
                o[nt][0] *= aAl; o[nt][1] *= aAl;
                o[nt][2] *= aBl; o[nt][3] *= aBl;
            }
        }

        uint32_t pa[4][4];
#pragma unroll
        for (int t = 0; t < 4; t++) {
            pa[t][0] = pack_h2(s[2 * t][0], s[2 * t][1]);
            pa[t][1] = pack_h2(s[2 * t][2], s[2 * t][3]);
            pa[t][2] = pack_h2(s[2 * t + 1][0], s[2 * t + 1][1]);
            pa[t][3] = pack_h2(s[2 * t + 1][2], s[2 * t + 1][3]);
        }

        // V(it) ready (pending: K(it+1) if it exists)
        if (hn) { CP_WAIT1; } else { CP_WAIT0; }
        __syncthreads();

        // ---- O += P @ V ----
#pragma unroll
        for (int t = 0; t < 4; t++) {
#pragma unroll
            for (int np = 0; np < 8; np++) {
                uint32_t v0, v1, v2, v3;
                ldsm4t(v0, v1, v2, v3,
                       smem_u32(&Vs[(t * 16 + lr + (gq & 1) * 8) * FSTR +
                                    np * 16 + (gq >> 1) * 8]));
                mma_f16(o[np * 2], pa[t], v0, v1);
                mma_f16(o[np * 2 + 1], pa[t], v2, v3);
            }
        }

        // all warps done reading V buffer -> refill for next tile
        __syncthreads();
        if (hn) { ldV((it + 1) * KT); CP_COMMIT; }
    }

    float iA = 1.f / lA, iB = 1.f / lB;
    __half* Og = O + (size_t)(b * SEQ + q0 + w * 16) * DIM + h * HD;
#pragma unroll
    for (int nt = 0; nt < 16; nt++) {
        int c = nt * 8 + qc;
        *(__half2*)&Og[(size_t)qr * DIM + c] =
            __floats2half2_rn(o[nt][0] * iA, o[nt][1] * iA);
        *(__half2*)&Og[(size_t)(qr + 8) * DIM + c] =
            __floats2half2_rn(o[nt][2] * iB, o[nt][3] * iB);
    }
}

// ---------------------------------------------------------------------------
extern "C" void kernel_launch(void* const* d_in, const int* in_sizes, int n_in,
                              void* d_out, int out_size) {
    const float* x   = (const float*)d_in[0];
    const float* fcs = (const float*)d_in[1];
    const float* fsn = (const float*)d_in[2];
    const float* wq = (const float*)d_in[4];
    const float* bq = (const float*)d_in[5];
    const float* wk = (const float*)d_in[6];
    const float* bk = (const float*)d_in[7];
    const float* wv = (const float*)d_in[8];
    const float* bv = (const float*)d_in[9];
    const float* wo = (const float*)d_in[10];
    const float* bo = (const float*)d_in[11];
    float* out = (float*)d_out;

    __half *xh, *wqkvh, *woh, *qh, *kh, *vh, *ah;
    float* bqkv;
    cudaGetSymbolAddress((void**)&xh, g_xh);
    cudaGetSymbolAddress((void**)&wqkvh, g_wqkvh);
    cudaGetSymbolAddress((void**)&woh, g_woh);
    cudaGetSymbolAddress((void**)&bqkv, g_bqkv);
    cudaGetSymbolAddress((void**)&qh, g_qh);
    cudaGetSymbolAddress((void**)&kh, g_kh);
    cudaGetSymbolAddress((void**)&vh, g_vh);
    cudaGetSymbolAddress((void**)&ah, g_ah);

    cudaFuncSetAttribute(h_gemm3<0>, cudaFuncAttributeMaxDynamicSharedMemorySize,
                         GEMM_SMEM);
    cudaFuncSetAttribute(h_gemm3<1>, cudaFuncAttributeMaxDynamicSharedMemorySize,
                         GEMM_SMEM);
    cudaFuncSetAttribute(flash_h, cudaFuncAttributeMaxDynamicSharedMemorySize,
                         FA_SMEM);

    // fp32 -> fp16 conversions (per-tensor, 16 elems/thread)
    auto cvt = [&](const float* src, __half* dst, size_t n) {
        f2h16<<<(int)((n / 16 + 255) / 256), 256>>>(src, dst, (int)n);
    };
    cvt(x, xh, (size_t)TOK * DIM);
    cvt(wq, wqkvh, (size_t)DIM * DIM);
    cvt(wk, wqkvh + (size_t)DIM * DIM, (size_t)KVDIM * DIM);
    cvt(wv, wqkvh + (size_t)(DIM + KVDIM) * DIM, (size_t)KVDIM * DIM);
    cvt(wo, woh, (size_t)DIM * DIM);
    concat_bias<<<(NQKV + 255) / 256, 256>>>(bq, bk, bv, bqkv);

    // Fused QKV projection + RoPE epilogue
    h_gemm3<1><<<dim3(NQKV / 256, TOK / 128), 256, GEMM_SMEM>>>(
        xh, wqkvh, bqkv, nullptr, qh, kh, vh, fcs, fsn, TOK, NQKV, DIM);

    // Flash attention (QT=64, 3 CTAs/SM, single-buffered V)
    flash_h<<<dim3(SEQ / QT, BSZ * NHEADS), 128, FA_SMEM>>>(qh, kh, vh, ah);

    // Output projection (fp32 out)
    h_gemm3<0><<<dim3(DIM / 256, TOK / 128), 256, GEMM_SMEM>>>(
        ah, woh, bo, out, nullptr, nullptr, nullptr, nullptr, nullptr,
        TOK, DIM, DIM);
}

// round 14
// speedup vs baseline: 11.9758x; 1.0383x over previous
#include <cuda_runtime.h>
#include <cuda_fp16.h>
#include <math.h>
#include <stdint.h>

#define DIM 4096
#define NHEADS 32
#define NKV 8
#define HD 128
#define SEQ 2048
#define BSZ 2
#define TOK (BSZ*SEQ)
#define KVDIM (NKV*HD)
#define NQKV (DIM + 2*KVDIM)   // 6144

// fp16 scratch (no cudaMalloc allowed)
__device__ __half g_xh[(size_t)TOK * DIM];
__device__ __half g_wqkvh[(size_t)NQKV * DIM];
__device__ __half g_woh[(size_t)DIM * DIM];
__device__ float  g_bqkv[NQKV];
__device__ __half g_qh[(size_t)TOK * DIM];
__device__ __half g_kh[(size_t)TOK * KVDIM];
__device__ __half g_vh[(size_t)TOK * KVDIM];
__device__ __half g_ah[(size_t)TOK * DIM];

// ---------------------------------------------------------------------------
// PTX helpers
// ---------------------------------------------------------------------------
__device__ __forceinline__ uint32_t smem_u32(const void* p) {
    return (uint32_t)__cvta_generic_to_shared(p);
}
__device__ __forceinline__ void cp16(uint32_t dst, const void* src) {
    asm volatile("cp.async.cg.shared.global [%0], [%1], 16;\n" ::"r"(dst), "l"(src));
}
#define CP_COMMIT asm volatile("cp.async.commit_group;\n" ::: "memory")
#define CP_WAIT0  asm volatile("cp.async.wait_group 0;\n" ::: "memory")

__device__ __forceinline__ void ldsm4(uint32_t& r0, uint32_t& r1, uint32_t& r2,
                                      uint32_t& r3, uint32_t addr) {
    asm volatile("ldmatrix.sync.aligned.m8n8.x4.shared.b16 {%0,%1,%2,%3}, [%4];\n"
                 : "=r"(r0), "=r"(r1), "=r"(r2), "=r"(r3) : "r"(addr));
}
__device__ __forceinline__ void ldsm4t(uint32_t& r0, uint32_t& r1, uint32_t& r2,
                                       uint32_t& r3, uint32_t addr) {
    asm volatile("ldmatrix.sync.aligned.m8n8.x4.trans.shared.b16 {%0,%1,%2,%3}, [%4];\n"
                 : "=r"(r0), "=r"(r1), "=r"(r2), "=r"(r3) : "r"(addr));
}
__device__ __forceinline__ void mma_f16(float* c, const uint32_t* a,
                                        uint32_t b0, uint32_t b1) {
    asm volatile(
        "mma.sync.aligned.m16n8k16.row.col.f32.f16.f16.f32 "
        "{%0,%1,%2,%3}, {%4,%5,%6,%7}, {%8,%9}, {%0,%1,%2,%3};\n"
        : "+f"(c[0]), "+f"(c[1]), "+f"(c[2]), "+f"(c[3])
        : "r"(a[0]), "r"(a[1]), "r"(a[2]), "r"(a[3]), "r"(b0), "r"(b1));
}
__device__ __forceinline__ uint32_t pack_h2(float x, float y) {
    __half2 h = __floats2half2_rn(x, y);
    return *(uint32_t*)&h;
}
__device__ __forceinline__ float fex2(float x) {
    float y;
    asm("ex2.approx.ftz.f32 %0, %1;" : "=f"(y) : "f"(x));
    return y;
}

// ---------------------------------------------------------------------------
// fp32 -> fp16 conversion, 16 elems/thread (4 independent LDG.128, MLP=4)
// ---------------------------------------------------------------------------
__global__ void f2h16(const float* __restrict__ in, __half* __restrict__ out,
                      int n) {
    int i = (blockIdx.x * blockDim.x + threadIdx.x) * 16;
    if (i >= n) return;
    float4 v[4];
#pragma unroll
    for (int j = 0; j < 4; j++) v[j] = *(const float4*)(in + i + j * 4);
#pragma unroll
    for (int j = 0; j < 2; j++) {
        __half2 a = __floats2half2_rn(v[2*j].x, v[2*j].y);
        __half2 b = __floats2half2_rn(v[2*j].z, v[2*j].w);
        __half2 c = __floats2half2_rn(v[2*j+1].x, v[2*j+1].y);
        __half2 d = __floats2half2_rn(v[2*j+1].z, v[2*j+1].w);
        uint4 o;
        o.x = *(uint32_t*)&a; o.y = *(uint32_t*)&b;
        o.z = *(uint32_t*)&c; o.w = *(uint32_t*)&d;
        *(uint4*)(out + i + j * 8) = o;
    }
}

__global__ void concat_bias(const float* __restrict__ bq,
                            const float* __restrict__ bk,
                            const float* __restrict__ bv,
                            float* __restrict__ o) {
    int i = blockIdx.x * blockDim.x + threadIdx.x;
    if (i < DIM) o[i] = bq[i];
    else if (i < DIM + KVDIM) o[i] = bk[i - DIM];
    else if (i < NQKV) o[i] = bv[i - DIM - KVDIM];
}

// ---------------------------------------------------------------------------
// fp16 GEMM: C[M,N] = A[M,K] @ B[N,K]^T + bias[N]
// CTA tile 128x128x64, 128 threads (4 warps, 2x2), warp tile 64x64
// (same MMA:LDSM ratio 4.0 as the 256-thread config), 2-stage cp.async,
// stride-72 padded smem -> 73.7KB -> 2 CTAs/SM (halves wave-tail waste).
// MODE 0: fp32 out (O-proj). MODE 1: fused QKV -> split fp16 out + RoPE.
// ---------------------------------------------------------------------------
#define BK 64
#define GSTR 72
#define A_STG (128 * GSTR)
#define B_STG (128 * GSTR)
#define GEMM_SMEM (2 * (A_STG + B_STG) * 2)   // 73728 bytes

template <int MODE>
__global__ __launch_bounds__(128, 2)
void h_gemm3(const __half* __restrict__ A, const __half* __restrict__ B,
             const float* __restrict__ bias, float* __restrict__ Cf,
             __half* __restrict__ Cq, __half* __restrict__ Ck,
             __half* __restrict__ Cv, const float* __restrict__ cs,
             const float* __restrict__ sn, int M, int N, int K) {
    extern __shared__ __half sh[];
    __half* As = sh;                 // [2][A_STG]
    __half* Bs = sh + 2 * A_STG;     // [2][B_STG]

    const int tid = threadIdx.x;
    const int lane = tid & 31;
    const int wid = tid >> 5;
    const int wm = wid >> 1;   // 0..1  (64 rows each)
    const int wn = wid & 1;    // 0..1  (64 cols each)
    const int bm = blockIdx.y * 128;
    const int bn = blockIdx.x * 128;
    const int lr = lane & 7;
    const int gq = lane >> 3;

    float acc[4][8][4];
#pragma unroll
    for (int mi = 0; mi < 4; mi++)
#pragma unroll
        for (int ni = 0; ni < 8; ni++)
#pragma unroll
            for (int j = 0; j < 4; j++) acc[mi][ni][j] = 0.f;

    auto g2s = [&](int k0, int stg) {
        // A: 128 rows x 8 chunks = 1024 / 128 thr
#pragma unroll
        for (int p = 0; p < 8; p++) {
            int cid = tid + 128 * p;
            int row = cid >> 3;
            int ch = cid & 7;
            cp16(smem_u32(&As[stg * A_STG + row * GSTR + ch * 8]),
                 A + (size_t)(bm + row) * K + k0 + ch * 8);
        }
        // B: 128 rows x 8 chunks
#pragma unroll
        for (int p = 0; p < 8; p++) {
            int cid = tid + 128 * p;
            int row = cid >> 3;
            int ch = cid & 7;
            cp16(smem_u32(&Bs[stg * B_STG + row * GSTR + ch * 8]),
                 B + (size_t)(bn + row) * K + k0 + ch * 8);
        }
    };

    const int nit = K / BK;
    g2s(0, 0); CP_COMMIT;

    for (int it = 0; it < nit; it++) {
        const int buf = it & 1;
        CP_WAIT0;
        __syncthreads();
        if (it + 1 < nit) { g2s((it + 1) * BK, buf ^ 1); CP_COMMIT; }

#pragma unroll
        for (int kk2 = 0; kk2 < 4; kk2++) {
            int kk = kk2 * 16;
            uint32_t a[4][4];
#pragma unroll
            for (int mi = 0; mi < 4; mi++)
                ldsm4(a[mi][0], a[mi][1], a[mi][2], a[mi][3],
                      smem_u32(&As[buf * A_STG +
                                   (wm * 64 + mi * 16 + lr + (gq & 1) * 8) * GSTR +
                                   kk + (gq >> 1) * 8]));
#pragma unroll
            for (int nt = 0; nt < 4; nt++) {
                uint32_t b0, b1, b2, b3;
                ldsm4(b0, b1, b2, b3,
                      smem_u32(&Bs[buf * B_STG +
                                   (wn * 64 + nt * 16 + lr + (gq & 1) * 8) * GSTR +
                                   kk + (gq >> 1) * 8]));
#pragma unroll
                for (int mi = 0; mi < 4; mi++) {
                    mma_f16(acc[mi][nt * 2], a[mi], b0, b2);
                    mma_f16(acc[mi][nt * 2 + 1], a[mi], b1, b3);
                }
            }
        }
    }

    // ---- epilogue ----
    const int r0 = bm + wm * 64 + (lane >> 2);
    const int c0 = bn + wn * 64 + (lane & 3) * 2;
#pragma unroll
    for (int mi = 0; mi < 4; mi++) {
#pragma unroll
        for (int ni = 0; ni < 8; ni++) {
            int r = r0 + mi * 16;
            int c = c0 + ni * 8;
            float2 bb = *(const float2*)&bias[c];
            float v00 = acc[mi][ni][0] + bb.x, v01 = acc[mi][ni][1] + bb.y;
            float v10 = acc[mi][ni][2] + bb.x, v11 = acc[mi][ni][3] + bb.y;
            if (MODE == 0) {
                *(float2*)&Cf[(size_t)r * N + c] = make_float2(v00, v01);
                *(float2*)&Cf[(size_t)(r + 8) * N + c] = make_float2(v10, v11);
            } else {
                if (c < DIM + KVDIM) {
                    int i = (c & 127) >> 1;
                    int s0 = r & (SEQ - 1), s1 = (r + 8) & (SEQ - 1);
                    float c00 = cs[s0 * 64 + i], sn0 = sn[s0 * 64 + i];
                    float c10 = cs[s1 * 64 + i], sn1 = sn[s1 * 64 + i];
                    float a0 = v00, b0v = v01;
                    v00 = a0 * c00 - b0v * sn0;
                    v01 = a0 * sn0 + b0v * c00;
                    float a1 = v10, b1v = v11;
                    v10 = a1 * c10 - b1v * sn1;
                    v11 = a1 * sn1 + b1v * c10;
                }
                __half2 h0 = __floats2half2_rn(v00, v01);
                __half2 h1 = __floats2half2_rn(v10, v11);
                __half* dst;
                size_t str;
                int cc;
                if (c < DIM) { dst = Cq; str = DIM; cc = c; }
                else if (c < DIM + KVDIM) { dst = Ck; str = KVDIM; cc = c - DIM; }
                else { dst = Cv; str = KVDIM; cc = c - DIM - KVDIM; }
                *(__half2*)&dst[(size_t)r * str + cc] = h0;
                *(__half2*)&dst[(size_t)(r + 8) * str + cc] = h1;
            }
        }
    }
}

// ---------------------------------------------------------------------------
// Causal GQA flash attention (exact R10 config: measured 274us).
// QT=64, KT=64, 128 threads, K/V both double-buffered, 87KB -> 2 CTAs/SM.
// ---------------------------------------------------------------------------
#define FSTR 136
#define QT 64
#define KT 64
#define FA_SMEM ((QT * FSTR + 2 * KT * FSTR + 2 * KT * FSTR) * 2)  // 87040

__global__ __launch_bounds__(128, 2)
void flash_h(const __half* __restrict__ Q, const __half* __restrict__ K,
             const __half* __restrict__ V, __half* __restrict__ O) {
    extern __shared__ __half sm[];
    __half* Qs = sm;                      // [64][136]
    __half* Ks = Qs + QT * FSTR;          // [2][64][136]
    __half* Vs = Ks + 2 * KT * FSTR;      // [2][64][136]

    const int tid = threadIdx.x;
    const int lane = tid & 31;
    const int w = tid >> 5;               // 0..3
    const int q0 = (gridDim.x - 1 - blockIdx.x) * QT;  // heavy blocks first
    const int bh = blockIdx.y;
    const int b = bh >> 5;
    const int h = bh & 31;
    const int g = h >> 2;
    const int lr = lane & 7;
    const int gq = lane >> 3;
    const int qr = lane >> 2;
    const int qc = (lane & 3) * 2;

    const __half* Qg = Q + (size_t)(b * SEQ + q0) * DIM + h * HD;
    const __half* Kg = K + (size_t)(b * SEQ) * KVDIM + g * HD;
    const __half* Vg = V + (size_t)(b * SEQ) * KVDIM + g * HD;

#pragma unroll
    for (int p = 0; p < 8; p++) {
        int cid = tid + 128 * p;
        int row = cid >> 4, ch = cid & 15;
        cp16(smem_u32(&Qs[row * FSTR + ch * 8]), Qg + (size_t)row * DIM + ch * 8);
    }
    CP_COMMIT;

    auto ldKV = [&](int kv0, int bufl) {
#pragma unroll
        for (int p = 0; p < 8; p++) {
            int cid = tid + 128 * p;
            int row = cid >> 4, ch = cid & 15;
            cp16(smem_u32(&Ks[bufl * KT * FSTR + row * FSTR + ch * 8]),
                 Kg + (size_t)(kv0 + row) * KVDIM + ch * 8);
            cp16(smem_u32(&Vs[bufl * KT * FSTR + row * FSTR + ch * 8]),
                 Vg + (size_t)(kv0 + row) * KVDIM + ch * 8);
        }
    };
    ldKV(0, 0);
    CP_COMMIT;

    float o[16][4];
#pragma unroll
    for (int nt = 0; nt < 16; nt++)
#pragma unroll
        for (int j = 0; j < 4; j++) o[nt][j] = 0.f;
    float mA = -1e30f, mB = -1e30f, lA = 0.f, lB = 0.f;
    const float scale2 = 0.08838834764831845f * 1.4426950408889634f;
    const int niter = q0 / KT + 1;
    const int rA = q0 + w * 16 + qr;

    for (int it = 0; it < niter; it++) {
        const int kv0 = it * KT;
        const int buf = it & 1;
        CP_WAIT0;
        __syncthreads();
        if (it + 1 < niter) { ldKV((it + 1) * KT, buf ^ 1); CP_COMMIT; }

        float s[8][4];
#pragma unroll
        for (int nt = 0; nt < 8; nt++)
#pragma unroll
            for (int j = 0; j < 4; j++) s[nt][j] = 0.f;

#pragma unroll
        for (int ks = 0; ks < 8; ks++) {
            uint32_t a[4];
            ldsm4(a[0], a[1], a[2], a[3],
                  smem_u32(&Qs[(w * 16 + lr + (gq & 1) * 8) * FSTR +
                               ks * 16 + (gq >> 1) * 8]));
#pragma unroll
            for (int np = 0; np < 4; np++) {
                uint32_t b0, b1, b2, b3;
                ldsm4(b0, b1, b2, b3,
                      smem_u32(&Ks[buf * KT * FSTR +
                                   (np * 16 + lr + (gq & 1) * 8) * FSTR +
                                   ks * 16 + (gq >> 1) * 8]));
                mma_f16(s[np * 2], a, b0, b2);
                mma_f16(s[np * 2 + 1], a, b1, b3);
            }
        }

        const bool domask = (kv0 + KT - 1) > (q0 + w * 16);
#pragma unroll
        for (int nt = 0; nt < 8; nt++)
#pragma unroll
            for (int j = 0; j < 4; j++) {
                float v = s[nt][j] * scale2;
                if (domask) {
                    int col = kv0 + nt * 8 + qc + (j & 1);
                    int row = rA + (j >> 1) * 8;
                    if (col > row) v = -1e30f;
                }
                s[nt][j] = v;
            }

        float rmA = -1e30f, rmB = -1e30f;
#pragma unroll
        for (int nt = 0; nt < 8; nt++) {
            rmA = fmaxf(rmA, fmaxf(s[nt][0], s[nt][1]));
            rmB = fmaxf(rmB, fmaxf(s[nt][2], s[nt][3]));
        }
        rmA = fmaxf(rmA, __shfl_xor_sync(0xffffffffu, rmA, 1));
        rmA = fmaxf(rmA, __shfl_xor_sync(0xffffffffu, rmA, 2));
        rmB = fmaxf(rmB, __shfl_xor_sync(0xffffffffu, rmB, 1));
        rmB = fmaxf(rmB, __shfl_xor_sync(0xffffffffu, rmB, 2));

        float newmA = fmaxf(mA, rmA), newmB = fmaxf(mB, rmB);
        float aAl = fex2(mA - newmA), aBl = fex2(mB - newmB);
        float lsA = 0.f, lsB = 0.f;
#pragma unroll
        for (int nt = 0; nt < 8; nt++) {
            s[nt][0] = fex2(s[nt][0] - newmA);
            s[nt][1] = fex2(s[nt][1] - newmA);
            s[nt][2] = fex2(s[nt][2] - newmB);
            s[nt][3] = fex2(s[nt][3] - newmB);
            lsA += s[nt][0] + s[nt][1];
            lsB += s[nt][2] + s[nt][3];
        }
        lsA += __shfl_xor_sync(0xffffffffu, lsA, 1);
        lsA += __shfl_xor_sync(0xffffffffu, lsA, 2);
        lsB += __shfl_xor_sync(0xffffffffu, lsB, 1);
        lsB += __shfl_xor_sync(0xffffffffu, lsB, 2);
        lA = lA * aAl + lsA;
        lB = lB * aBl + lsB;
        mA = newmA;
        mB = newmB;
        if (!__all_sync(0xffffffffu, (aAl == 1.f) & (aBl == 1.f))) {
#pragma unroll
            for (int nt = 0; nt < 16; nt++) {
                o[nt][0] *= aAl; o[nt][1] *= aAl;
                o[nt][2] *= aBl; o[nt][3] *= aBl;
            }
        }

        uint32_t pa[4][4];
#pragma unroll
        for (int t = 0; t < 4; t++) {
            pa[t][0] = pack_h2(s[2 * t][0], s[2 * t][1]);
            pa[t][1] = pack_h2(s[2 * t][2], s[2 * t][3]);
            pa[t][2] = pack_h2(s[2 * t + 1][0], s[2 * t + 1][1]);
            pa[t][3] = pack_h2(s[2 * t + 1][2], s[2 * t + 1][3]);
        }

#pragma unroll
        for (int t = 0; t < 4; t++) {
#pragma unroll
            for (int np = 0; np < 8; np++) {
                uint32_t v0, v1, v2, v3;
                ldsm4t(v0, v1, v2, v3,
                       smem_u32(&Vs[buf * KT * FSTR +
                                    (t * 16 + lr + (gq & 1) * 8) * FSTR +
                                    np * 16 + (gq >> 1) * 8]));
                mma_f16(o[np * 2], pa[t], v0, v1);
                mma_f16(o[np * 2 + 1], pa[t], v2, v3);
            }
        }
    }

    float iA = 1.f / lA, iB = 1.f / lB;
    __half* Og = O + (size_t)(b * SEQ + q0 + w * 16) * DIM + h * HD;
#pragma unroll
    for (int nt = 0; nt < 16; nt++) {
        int c = nt * 8 + qc;
        *(__half2*)&Og[(size_t)qr * DIM + c] =
            __floats2half2_rn(o[nt][0] * iA, o[nt][1] * iA);
        *(__half2*)&Og[(size_t)(qr + 8) * DIM + c] =
            __floats2half2_rn(o[nt][2] * iB, o[nt][3] * iB);
    }
}

// ---------------------------------------------------------------------------
extern "C" void kernel_launch(void* const* d_in, const int* in_sizes, int n_in,
                              void* d_out, int out_size) {
    const float* x   = (const float*)d_in[0];
    const float* fcs = (const float*)d_in[1];
    const float* fsn = (const float*)d_in[2];
    const float* wq = (const float*)d_in[4];
    const float* bq = (const float*)d_in[5];
    const float* wk = (const float*)d_in[6];
    const float* bk = (const float*)d_in[7];
    const float* wv = (const float*)d_in[8];
    const float* bv = (const float*)d_in[9];
    const float* wo = (const float*)d_in[10];
    const float* bo = (const float*)d_in[11];
    float* out = (float*)d_out;

    __half *xh, *wqkvh, *woh, *qh, *kh, *vh, *ah;
    float* bqkv;
    cudaGetSymbolAddress((void**)&xh, g_xh);
    cudaGetSymbolAddress((void**)&wqkvh, g_wqkvh);
    cudaGetSymbolAddress((void**)&woh, g_woh);
    cudaGetSymbolAddress((void**)&bqkv, g_bqkv);
    cudaGetSymbolAddress((void**)&qh, g_qh);
    cudaGetSymbolAddress((void**)&kh, g_kh);
    cudaGetSymbolAddress((void**)&vh, g_vh);
    cudaGetSymbolAddress((void**)&ah, g_ah);

    cudaFuncSetAttribute(h_gemm3<0>, cudaFuncAttributeMaxDynamicSharedMemorySize,
                         GEMM_SMEM);
    cudaFuncSetAttribute(h_gemm3<1>, cudaFuncAttributeMaxDynamicSharedMemorySize,
                         GEMM_SMEM);
    cudaFuncSetAttribute(flash_h, cudaFuncAttributeMaxDynamicSharedMemorySize,
                         FA_SMEM);

    // fp32 -> fp16 conversions (per-tensor, 16 elems/thread)
    auto cvt = [&](const float* src, __half* dst, size_t n) {
        f2h16<<<(int)((n / 16 + 255) / 256), 256>>>(src, dst, (int)n);
    };
    cvt(x, xh, (size_t)TOK * DIM);
    cvt(wq, wqkvh, (size_t)DIM * DIM);
    cvt(wk, wqkvh + (size_t)DIM * DIM, (size_t)KVDIM * DIM);
    cvt(wv, wqkvh + (size_t)(DIM + KVDIM) * DIM, (size_t)KVDIM * DIM);
    cvt(wo, woh, (size_t)DIM * DIM);
    concat_bias<<<(NQKV + 255) / 256, 256>>>(bq, bk, bv, bqkv);

    // Fused QKV projection + RoPE epilogue (128x128 tiles, 2 CTAs/SM)
    h_gemm3<1><<<dim3(NQKV / 128, TOK / 128), 128, GEMM_SMEM>>>(
        xh, wqkvh, bqkv, nullptr, qh, kh, vh, fcs, fsn, TOK, NQKV, DIM);

    // Flash attention (R10 config: QT=64, 2 CTAs/SM, KV double-buffered)
    flash_h<<<dim3(SEQ / QT, BSZ * NHEADS), 128, FA_SMEM>>>(qh, kh, vh, ah);

    // Output projection (fp32 out)
    h_gemm3<0><<<dim3(DIM / 128, TOK / 128), 128, GEMM_SMEM>>>(
        ah, woh, bo, out, nullptr, nullptr, nullptr, nullptr, nullptr,
        TOK, DIM, DIM);
}

// round 15
// speedup vs baseline: 12.0818x; 1.0088x over previous
#include <cuda_runtime.h>
#include <cuda_fp16.h>
#include <math.h>
#include <stdint.h>

#define DIM 4096
#define NHEADS 32
#define NKV 8
#define HD 128
#define SEQ 2048
#define BSZ 2
#define TOK (BSZ*SEQ)
#define KVDIM (NKV*HD)
#define NQKV (DIM + 2*KVDIM)   // 6144

// fp16 scratch (no cudaMalloc allowed)
__device__ __half g_xh[(size_t)TOK * DIM];
__device__ __half g_wqkvh[(size_t)NQKV * DIM];
__device__ __half g_woh[(size_t)DIM * DIM];
__device__ __half g_qh[(size_t)TOK * DIM];
__device__ __half g_kh[(size_t)TOK * KVDIM];
__device__ __half g_vh[(size_t)TOK * KVDIM];
__device__ __half g_ah[(size_t)TOK * DIM];

// ---------------------------------------------------------------------------
// PTX helpers
// ---------------------------------------------------------------------------
__device__ __forceinline__ uint32_t smem_u32(const void* p) {
    return (uint32_t)__cvta_generic_to_shared(p);
}
__device__ __forceinline__ void cp16(uint32_t dst, const void* src) {
    asm volatile("cp.async.cg.shared.global [%0], [%1], 16;\n" ::"r"(dst), "l"(src));
}
#define CP_COMMIT asm volatile("cp.async.commit_group;\n" ::: "memory")
#define CP_WAIT0  asm volatile("cp.async.wait_group 0;\n" ::: "memory")

__device__ __forceinline__ void ldsm4(uint32_t& r0, uint32_t& r1, uint32_t& r2,
                                      uint32_t& r3, uint32_t addr) {
    asm volatile("ldmatrix.sync.aligned.m8n8.x4.shared.b16 {%0,%1,%2,%3}, [%4];\n"
                 : "=r"(r0), "=r"(r1), "=r"(r2), "=r"(r3) : "r"(addr));
}
__device__ __forceinline__ void ldsm4t(uint32_t& r0, uint32_t& r1, uint32_t& r2,
                                       uint32_t& r3, uint32_t addr) {
    asm volatile("ldmatrix.sync.aligned.m8n8.x4.trans.shared.b16 {%0,%1,%2,%3}, [%4];\n"
                 : "=r"(r0), "=r"(r1), "=r"(r2), "=r"(r3) : "r"(addr));
}
__device__ __forceinline__ void mma_f16(float* c, const uint32_t* a,
                                        uint32_t b0, uint32_t b1) {
    asm volatile(
        "mma.sync.aligned.m16n8k16.row.col.f32.f16.f16.f32 "
        "{%0,%1,%2,%3}, {%4,%5,%6,%7}, {%8,%9}, {%0,%1,%2,%3};\n"
        : "+f"(c[0]), "+f"(c[1]), "+f"(c[2]), "+f"(c[3])
        : "r"(a[0]), "r"(a[1]), "r"(a[2]), "r"(a[3]), "r"(b0), "r"(b1));
}
__device__ __forceinline__ uint32_t pack_h2(float x, float y) {
    __half2 h = __floats2half2_rn(x, y);
    return *(uint32_t*)&h;
}
__device__ __forceinline__ float fex2(float x) {
    float y;
    asm("ex2.approx.ftz.f32 %0, %1;" : "=f"(y) : "f"(x));
    return y;
}

// ---------------------------------------------------------------------------
// Single merged fp32 -> fp16 conversion for x, wq, wk, wv, wo.
// 8 elems/thread, one launch, ~28.6k blocks (full-chip; no per-tensor
// latency tails, no inter-kernel gaps).
// ---------------------------------------------------------------------------
#define SEG0 ((size_t)TOK * DIM)          // x      16.78M
#define SEG1 ((size_t)DIM * DIM)          // wq     16.78M
#define SEG2 ((size_t)KVDIM * DIM)        // wk      4.19M
#define SEG3 ((size_t)KVDIM * DIM)        // wv      4.19M
#define SEG4 ((size_t)DIM * DIM)          // wo     16.78M
#define CVT_TOTAL (SEG0 + SEG1 + SEG2 + SEG3 + SEG4)

__global__ void cvt_all(const float* __restrict__ x, const float* __restrict__ wq,
                        const float* __restrict__ wk, const float* __restrict__ wv,
                        const float* __restrict__ wo, __half* __restrict__ xh,
                        __half* __restrict__ wqkvh, __half* __restrict__ woh) {
    size_t i = (size_t)(blockIdx.x * blockDim.x + threadIdx.x) * 8;
    if (i >= CVT_TOTAL) return;
    const float* src;
    __half* dst;
    size_t off;
    if (i < SEG0) { src = x; dst = xh; off = i; }
    else if (i < SEG0 + SEG1) { src = wq; dst = wqkvh; off = i - SEG0; }
    else if (i < SEG0 + SEG1 + SEG2) {
        src = wk; dst = wqkvh + SEG1; off = i - SEG0 - SEG1;
    } else if (i < SEG0 + SEG1 + SEG2 + SEG3) {
        src = wv; dst = wqkvh + SEG1 + SEG2; off = i - SEG0 - SEG1 - SEG2;
    } else { src = wo; dst = woh; off = i - SEG0 - SEG1 - SEG2 - SEG3; }

    float4 v0 = *(const float4*)(src + off);
    float4 v1 = *(const float4*)(src + off + 4);
    __half2 h0 = __floats2half2_rn(v0.x, v0.y);
    __half2 h1 = __floats2half2_rn(v0.z, v0.w);
    __half2 h2 = __floats2half2_rn(v1.x, v1.y);
    __half2 h3 = __floats2half2_rn(v1.z, v1.w);
    uint4 o;
    o.x = *(uint32_t*)&h0; o.y = *(uint32_t*)&h1;
    o.z = *(uint32_t*)&h2; o.w = *(uint32_t*)&h3;
    *(uint4*)(dst + off) = o;
}

// ---------------------------------------------------------------------------
// fp16 GEMM: C[M,N] = A[M,K] @ B[N,K]^T + bias
// CTA tile 128x128x64, 128 threads (4 warps, 2x2), warp tile 64x64,
// 2-stage cp.async, stride-72 padded smem -> 73.7KB -> 2 CTAs/SM.
// MODE 0: fp32 out, single bias array.
// MODE 1: fused QKV -> split fp16 out + RoPE; bias selected from bq/bk/bv.
// ---------------------------------------------------------------------------
#define BK 64
#define GSTR 72
#define A_STG (128 * GSTR)
#define B_STG (128 * GSTR)
#define GEMM_SMEM (2 * (A_STG + B_STG) * 2)   // 73728 bytes

template <int MODE>
__global__ __launch_bounds__(128, 2)
void h_gemm3(const __half* __restrict__ A, const __half* __restrict__ B,
             const float* __restrict__ bias_q, const float* __restrict__ bias_k,
             const float* __restrict__ bias_v, float* __restrict__ Cf,
             __half* __restrict__ Cq, __half* __restrict__ Ck,
             __half* __restrict__ Cv, const float* __restrict__ cs,
             const float* __restrict__ sn, int M, int N, int K) {
    extern __shared__ __half sh[];
    __half* As = sh;                 // [2][A_STG]
    __half* Bs = sh + 2 * A_STG;     // [2][B_STG]

    const int tid = threadIdx.x;
    const int lane = tid & 31;
    const int wid = tid >> 5;
    const int wm = wid >> 1;
    const int wn = wid & 1;
    const int bm = blockIdx.y * 128;
    const int bn = blockIdx.x * 128;
    const int lr = lane & 7;
    const int gq = lane >> 3;

    float acc[4][8][4];
#pragma unroll
    for (int mi = 0; mi < 4; mi++)
#pragma unroll
        for (int ni = 0; ni < 8; ni++)
#pragma unroll
            for (int j = 0; j < 4; j++) acc[mi][ni][j] = 0.f;

    auto g2s = [&](int k0, int stg) {
#pragma unroll
        for (int p = 0; p < 8; p++) {
            int cid = tid + 128 * p;
            int row = cid >> 3;
            int ch = cid & 7;
            cp16(smem_u32(&As[stg * A_STG + row * GSTR + ch * 8]),
                 A + (size_t)(bm + row) * K + k0 + ch * 8);
        }
#pragma unroll
        for (int p = 0; p < 8; p++) {
            int cid = tid + 128 * p;
            int row = cid >> 3;
            int ch = cid & 7;
            cp16(smem_u32(&Bs[stg * B_STG + row * GSTR + ch * 8]),
                 B + (size_t)(bn + row) * K + k0 + ch * 8);
        }
    };

    const int nit = K / BK;
    g2s(0, 0); CP_COMMIT;

    for (int it = 0; it < nit; it++) {
        const int buf = it & 1;
        CP_WAIT0;
        __syncthreads();
        if (it + 1 < nit) { g2s((it + 1) * BK, buf ^ 1); CP_COMMIT; }

#pragma unroll
        for (int kk2 = 0; kk2 < 4; kk2++) {
            int kk = kk2 * 16;
            uint32_t a[4][4];
#pragma unroll
            for (int mi = 0; mi < 4; mi++)
                ldsm4(a[mi][0], a[mi][1], a[mi][2], a[mi][3],
                      smem_u32(&As[buf * A_STG +
                                   (wm * 64 + mi * 16 + lr + (gq & 1) * 8) * GSTR +
                                   kk + (gq >> 1) * 8]));
#pragma unroll
            for (int nt = 0; nt < 4; nt++) {
                uint32_t b0, b1, b2, b3;
                ldsm4(b0, b1, b2, b3,
                      smem_u32(&Bs[buf * B_STG +
                                   (wn * 64 + nt * 16 + lr + (gq & 1) * 8) * GSTR +
                                   kk + (gq >> 1) * 8]));
#pragma unroll
                for (int mi = 0; mi < 4; mi++) {
                    mma_f16(acc[mi][nt * 2], a[mi], b0, b2);
                    mma_f16(acc[mi][nt * 2 + 1], a[mi], b1, b3);
                }
            }
        }
    }

    // ---- epilogue ----
    const int r0 = bm + wm * 64 + (lane >> 2);
    const int c0 = bn + wn * 64 + (lane & 3) * 2;
#pragma unroll
    for (int mi = 0; mi < 4; mi++) {
#pragma unroll
        for (int ni = 0; ni < 8; ni++) {
            int r = r0 + mi * 16;
            int c = c0 + ni * 8;
            float2 bb;
            if (MODE == 0) bb = *(const float2*)&bias_q[c];
            else {
                if (c < DIM)                bb = *(const float2*)&bias_q[c];
                else if (c < DIM + KVDIM)   bb = *(const float2*)&bias_k[c - DIM];
                else                        bb = *(const float2*)&bias_v[c - DIM - KVDIM];
            }
            float v00 = acc[mi][ni][0] + bb.x, v01 = acc[mi][ni][1] + bb.y;
            float v10 = acc[mi][ni][2] + bb.x, v11 = acc[mi][ni][3] + bb.y;
            if (MODE == 0) {
                *(float2*)&Cf[(size_t)r * N + c] = make_float2(v00, v01);
                *(float2*)&Cf[(size_t)(r + 8) * N + c] = make_float2(v10, v11);
            } else {
                if (c < DIM + KVDIM) {
                    int i = (c & 127) >> 1;
                    int s0 = r & (SEQ - 1), s1 = (r + 8) & (SEQ - 1);
                    float c00 = cs[s0 * 64 + i], sn0 = sn[s0 * 64 + i];
                    float c10 = cs[s1 * 64 + i], sn1 = sn[s1 * 64 + i];
                    float a0 = v00, b0v = v01;
                    v00 = a0 * c00 - b0v * sn0;
                    v01 = a0 * sn0 + b0v * c00;
                    float a1 = v10, b1v = v11;
                    v10 = a1 * c10 - b1v * sn1;
                    v11 = a1 * sn1 + b1v * c10;
                }
                __half2 h0 = __floats2half2_rn(v00, v01);
                __half2 h1 = __floats2half2_rn(v10, v11);
                __half* dst;
                size_t str;
                int cc;
                if (c < DIM) { dst = Cq; str = DIM; cc = c; }
                else if (c < DIM + KVDIM) { dst = Ck; str = KVDIM; cc = c - DIM; }
                else { dst = Cv; str = KVDIM; cc = c - DIM - KVDIM; }
                *(__half2*)&dst[(size_t)r * str + cc] = h0;
                *(__half2*)&dst[(size_t)(r + 8) * str + cc] = h1;
            }
        }
    }
}

// ---------------------------------------------------------------------------
// Causal GQA flash attention (R10 config, measured 274us).
// QT=64, KT=64, 128 threads, K/V double-buffered, 87KB -> 2 CTAs/SM.
// ---------------------------------------------------------------------------
#define FSTR 136
#define QT 64
#define KT 64
#define FA_SMEM ((QT * FSTR + 2 * KT * FSTR + 2 * KT * FSTR) * 2)  // 87040

__global__ __launch_bounds__(128, 2)
void flash_h(const __half* __restrict__ Q, const __half* __restrict__ K,
             const __half* __restrict__ V, __half* __restrict__ O) {
    extern __shared__ __half sm[];
    __half* Qs = sm;
    __half* Ks = Qs + QT * FSTR;
    __half* Vs = Ks + 2 * KT * FSTR;

    const int tid = threadIdx.x;
    const int lane = tid & 31;
    const int w = tid >> 5;
    const int q0 = (gridDim.x - 1 - blockIdx.x) * QT;
    const int bh = blockIdx.y;
    const int b = bh >> 5;
    const int h = bh & 31;
    const int g = h >> 2;
    const int lr = lane & 7;
    const int gq = lane >> 3;
    const int qr = lane >> 2;
    const int qc = (lane & 3) * 2;

    const __half* Qg = Q + (size_t)(b * SEQ + q0) * DIM + h * HD;
    const __half* Kg = K + (size_t)(b * SEQ) * KVDIM + g * HD;
    const __half* Vg = V + (size_t)(b * SEQ) * KVDIM + g * HD;

#pragma unroll
    for (int p = 0; p < 8; p++) {
        int cid = tid + 128 * p;
        int row = cid >> 4, ch = cid & 15;
        cp16(smem_u32(&Qs[row * FSTR + ch * 8]), Qg + (size_t)row * DIM + ch * 8);
    }
    CP_COMMIT;

    auto ldKV = [&](int kv0, int bufl) {
#pragma unroll
        for (int p = 0; p < 8; p++) {
            int cid = tid + 128 * p;
            int row = cid >> 4, ch = cid & 15;
            cp16(smem_u32(&Ks[bufl * KT * FSTR + row * FSTR + ch * 8]),
                 Kg + (size_t)(kv0 + row) * KVDIM + ch * 8);
            cp16(smem_u32(&Vs[bufl * KT * FSTR + row * FSTR + ch * 8]),
                 Vg + (size_t)(kv0 + row) * KVDIM + ch * 8);
        }
    };
    ldKV(0, 0);
    CP_COMMIT;

    float o[16][4];
#pragma unroll
    for (int nt = 0; nt < 16; nt++)
#pragma unroll
        for (int j = 0; j < 4; j++) o[nt][j] = 0.f;
    float mA = -1e30f, mB = -1e30f, lA = 0.f, lB = 0.f;
    const float scale2 = 0.08838834764831845f * 1.4426950408889634f;
    const int niter = q0 / KT + 1;
    const int rA = q0 + w * 16 + qr;

    for (int it = 0; it < niter; it++) {
        const int kv0 = it * KT;
        const int buf = it & 1;
        CP_WAIT0;
        __syncthreads();
        if (it + 1 < niter) { ldKV((it + 1) * KT, buf ^ 1); CP_COMMIT; }

        float s[8][4];
#pragma unroll
        for (int nt = 0; nt < 8; nt++)
#pragma unroll
            for (int j = 0; j < 4; j++) s[nt][j] = 0.f;

#pragma unroll
        for (int ks = 0; ks < 8; ks++) {
            uint32_t a[4];
            ldsm4(a[0], a[1], a[2], a[3],
                  smem_u32(&Qs[(w * 16 + lr + (gq & 1) * 8) * FSTR +
                               ks * 16 + (gq >> 1) * 8]));
#pragma unroll
            for (int np = 0; np < 4; np++) {
                uint32_t b0, b1, b2, b3;
                ldsm4(b0, b1, b2, b3,
                      smem_u32(&Ks[buf * KT * FSTR +
                                   (np * 16 + lr + (gq & 1) * 8) * FSTR +
                                   ks * 16 + (gq >> 1) * 8]));
                mma_f16(s[np * 2], a, b0, b2);
                mma_f16(s[np * 2 + 1], a, b1, b3);
            }
        }

        const bool domask = (kv0 + KT - 1) > (q0 + w * 16);
#pragma unroll
        for (int nt = 0; nt < 8; nt++)
#pragma unroll
            for (int j = 0; j < 4; j++) {
                float v = s[nt][j] * scale2;
                if (domask) {
                    int col = kv0 + nt * 8 + qc + (j & 1);
                    int row = rA + (j >> 1) * 8;
                    if (col > row) v = -1e30f;
                }
                s[nt][j] = v;
            }

        float rmA = -1e30f, rmB = -1e30f;
#pragma unroll
        for (int nt = 0; nt < 8; nt++) {
            rmA = fmaxf(rmA, fmaxf(s[nt][0], s[nt][1]));
            rmB = fmaxf(rmB, fmaxf(s[nt][2], s[nt][3]));
        }
        rmA = fmaxf(rmA, __shfl_xor_sync(0xffffffffu, rmA, 1));
        rmA = fmaxf(rmA, __shfl_xor_sync(0xffffffffu, rmA, 2));
        rmB = fmaxf(rmB, __shfl_xor_sync(0xffffffffu, rmB, 1));
        rmB = fmaxf(rmB, __shfl_xor_sync(0xffffffffu, rmB, 2));

        float newmA = fmaxf(mA, rmA), newmB = fmaxf(mB, rmB);
        float aAl = fex2(mA - newmA), aBl = fex2(mB - newmB);
        float lsA = 0.f, lsB = 0.f;
#pragma unroll
        for (int nt = 0; nt < 8; nt++) {
            s[nt][0] = fex2(s[nt][0] - newmA);
            s[nt][1] = fex2(s[nt][1] - newmA);
            s[nt][2] = fex2(s[nt][2] - newmB);
            s[nt][3] = fex2(s[nt][3] - newmB);
            lsA += s[nt][0] + s[nt][1];
            lsB += s[nt][2] + s[nt][3];
        }
        lsA += __shfl_xor_sync(0xffffffffu, lsA, 1);
        lsA += __shfl_xor_sync(0xffffffffu, lsA, 2);
        lsB += __shfl_xor_sync(0xffffffffu, lsB, 1);
        lsB += __shfl_xor_sync(0xffffffffu, lsB, 2);
        lA = lA * aAl + lsA;
        lB = lB * aBl + lsB;
        mA = newmA;
        mB = newmB;
        if (!__all_sync(0xffffffffu, (aAl == 1.f) & (aBl == 1.f))) {
#pragma unroll
            for (int nt = 0; nt < 16; nt++) {
                o[nt][0] *= aAl; o[nt][1] *= aAl;
                o[nt][2] *= aBl; o[nt][3] *= aBl;
            }
        }

        uint32_t pa[4][4];
#pragma unroll
        for (int t = 0; t < 4; t++) {
            pa[t][0] = pack_h2(s[2 * t][0], s[2 * t][1]);
            pa[t][1] = pack_h2(s[2 * t][2], s[2 * t][3]);
            pa[t][2] = pack_h2(s[2 * t + 1][0], s[2 * t + 1][1]);
            pa[t][3] = pack_h2(s[2 * t + 1][2], s[2 * t + 1][3]);
        }

#pragma unroll
        for (int t = 0; t < 4; t++) {
#pragma unroll
            for (int np = 0; np < 8; np++) {
                uint32_t v0, v1, v2, v3;
                ldsm4t(v0, v1, v2, v3,
                       smem_u32(&Vs[buf * KT * FSTR +
                                    (t * 16 + lr + (gq & 1) * 8) * FSTR +
                                    np * 16 + (gq >> 1) * 8]));
                mma_f16(o[np * 2], pa[t], v0, v1);
                mma_f16(o[np * 2 + 1], pa[t], v2, v3);
            }
        }
    }

    float iA = 1.f / lA, iB = 1.f / lB;
    __half* Og = O + (size_t)(b * SEQ + q0 + w * 16) * DIM + h * HD;
#pragma unroll
    for (int nt = 0; nt < 16; nt++) {
        int c = nt * 8 + qc;
        *(__half2*)&Og[(size_t)qr * DIM + c] =
            __floats2half2_rn(o[nt][0] * iA, o[nt][1] * iA);
        *(__half2*)&Og[(size_t)(qr + 8) * DIM + c] =
            __floats2half2_rn(o[nt][2] * iB, o[nt][3] * iB);
    }
}

// ---------------------------------------------------------------------------
extern "C" void kernel_launch(void* const* d_in, const int* in_sizes, int n_in,
                              void* d_out, int out_size) {
    const float* x   = (const float*)d_in[0];
    const float* fcs = (const float*)d_in[1];
    const float* fsn = (const float*)d_in[2];
    const float* wq = (const float*)d_in[4];
    const float* bq = (const float*)d_in[5];
    const float* wk = (const float*)d_in[6];
    const float* bk = (const float*)d_in[7];
    const float* wv = (const float*)d_in[8];
    const float* bv = (const float*)d_in[9];
    const float* wo = (const float*)d_in[10];
    const float* bo = (const float*)d_in[11];
    float* out = (float*)d_out;

    __half *xh, *wqkvh, *woh, *qh, *kh, *vh, *ah;
    cudaGetSymbolAddress((void**)&xh, g_xh);
    cudaGetSymbolAddress((void**)&wqkvh, g_wqkvh);
    cudaGetSymbolAddress((void**)&woh, g_woh);
    cudaGetSymbolAddress((void**)&qh, g_qh);
    cudaGetSymbolAddress((void**)&kh, g_kh);
    cudaGetSymbolAddress((void**)&vh, g_vh);
    cudaGetSymbolAddress((void**)&ah, g_ah);

    cudaFuncSetAttribute(h_gemm3<0>, cudaFuncAttributeMaxDynamicSharedMemorySize,
                         GEMM_SMEM);
    cudaFuncSetAttribute(h_gemm3<1>, cudaFuncAttributeMaxDynamicSharedMemorySize,
                         GEMM_SMEM);
    cudaFuncSetAttribute(flash_h, cudaFuncAttributeMaxDynamicSharedMemorySize,
                         FA_SMEM);

    // All fp32->fp16 conversions in ONE launch
    cvt_all<<<(int)((CVT_TOTAL / 8 + 255) / 256), 256>>>(
        x, wq, wk, wv, wo, xh, wqkvh, woh);

    // Fused QKV projection + RoPE epilogue (bias selected in-epilogue)
    h_gemm3<1><<<dim3(NQKV / 128, TOK / 128), 128, GEMM_SMEM>>>(
        xh, wqkvh, bq, bk, bv, nullptr, qh, kh, vh, fcs, fsn, TOK, NQKV, DIM);

    // Flash attention
    flash_h<<<dim3(SEQ / QT, BSZ * NHEADS), 128, FA_SMEM>>>(qh, kh, vh, ah);

    // Output projection (fp32 out)
    h_gemm3<0><<<dim3(DIM / 128, TOK / 128), 128, GEMM_SMEM>>>(
        ah, woh, bo, nullptr, nullptr, out, nullptr, nullptr, nullptr,
        nullptr, nullptr, TOK, DIM, DIM);
}